// round 2
// baseline (speedup 1.0000x reference)
#include <cuda_runtime.h>

constexpr int kB = 8, kSeq = 8192, kCh = 256;
constexpr int kM  = kB * kSeq;          // 65536
constexpr int kN2 = 8192;               // complex FFT size (real 16384)
constexpr int kNF = 8193;               // rfft bins of 16384

__device__ __align__(128) float  g_xe [kM * kCh];
__device__ __align__(128) float  g_xeT[kM * kCh];   // (B,C,L); becomes h1T
__device__ __align__(128) float  g_y1 [kM * kCh];
__device__ __align__(128) float  g_y2 [kM * kCh];
__device__ __align__(128) float2 g_Kf [(size_t)kCh * kNF];
__device__ float2 g_tw8 [4096];
__device__ float2 g_tw16[4097];
__device__ unsigned g_maxxe[kB * kCh];
__device__ unsigned g_maxy [kB * kCh];

__device__ __forceinline__ float2 cmul(float2 a, float2 b) {
    return make_float2(a.x * b.x - a.y * b.y, a.x * b.y + a.y * b.x);
}
__device__ __forceinline__ float gelu_exact(float v) {
    return 0.5f * v * (1.0f + erff(v * 0.7071067811865476f));
}

__global__ void zero_kernel() {
    int i = blockIdx.x * 256 + threadIdx.x;
    if (i < kB * kCh) { g_maxxe[i] = 0u; g_maxy[i] = 0u; }
}

__global__ void twiddle_kernel() {
    int i = blockIdx.x * 256 + threadIdx.x;
    float s, c;
    if (i < 4096) { sincospif(-2.0f * i / 8192.0f,  &s, &c); g_tw8 [i] = make_float2(c, s); }
    if (i < 4097) { sincospif(-2.0f * i / 16384.0f, &s, &c); g_tw16[i] = make_float2(c, s); }
}

// Kf[c][k] = B(w)/A(w)/8192, w = e^{-2*pi*i*k/16384}. (IIR tail beyond n=8192
// underflows fp32, so this equals the reference's FFT-generated kernel.)
__global__ __launch_bounds__(256) void kfgen_kernel(const float* __restrict__ A,
                                                    const float* __restrict__ Bp) {
    __shared__ float sA[64], sB[64];
    int c = blockIdx.y;
    if (threadIdx.x < 64)       sA[threadIdx.x]      = A [c * 64 + threadIdx.x];
    else if (threadIdx.x < 128) sB[threadIdx.x - 64] = Bp[c * 64 + threadIdx.x - 64];
    __syncthreads();
    int k = blockIdx.x * 256 + threadIdx.x;
    if (k >= kNF) return;
    float sv, cv;
    sincospif(-(float)k / 8192.0f, &sv, &cv);
    float2 w = make_float2(cv, sv);
    float2 av = make_float2(sA[63], 0.f);
    for (int j = 62; j >= 0; --j) { av = cmul(av, w); av.x += sA[j]; }
    av = cmul(av, w); av.x += 1.0f;
    float2 bv = make_float2(sB[63], 0.f);
    for (int j = 62; j >= 0; --j) { bv = cmul(bv, w); bv.x += sB[j]; }
    float scl = (1.0f / 8192.0f) / (av.x * av.x + av.y * av.y);
    g_Kf[(size_t)c * kNF + k] = make_float2((bv.x * av.x + bv.y * av.y) * scl,
                                            (bv.y * av.x - bv.x * av.y) * scl);
}

// GEMM: C[M,256] = epi(A[M,256] @ W[256,256]^T + bias)
// EPI 0: encode (x -> g_xe, colmax -> g_maxxe)
// EPI 1: fc     (g_y1 -> g_y2, v = gelu(v) + xe skip)
// EPI 2: decode (g_y2 -> d_out, colmax -> g_maxy)
template <int EPI>
__global__ __launch_bounds__(256) void gemm_kernel(const float* __restrict__ Ain,
                                                   const float* __restrict__ W,
                                                   const float* __restrict__ bias,
                                                   float* __restrict__ Cout) {
    constexpr int BM = 128, BN = 64, BK = 16;
    __shared__ float As[BK][BM + 4];
    __shared__ float Ws[BK][BN + 4];
    __shared__ float red[16][64];
    const float* Ap = (EPI == 1) ? g_y1 : (EPI == 2 ? g_y2 : Ain);
    float*       Cp = (EPI == 0) ? g_xe : (EPI == 1 ? g_y2 : Cout);
    const int m0 = blockIdx.x * BM, n0 = blockIdx.y * BN;
    const int tid = threadIdx.x, trow = tid >> 4, tcol = tid & 15;
    float acc[8][4];
#pragma unroll
    for (int i = 0; i < 8; ++i)
#pragma unroll
        for (int j = 0; j < 4; ++j) acc[i][j] = 0.f;

    for (int kt = 0; kt < kCh; kt += BK) {
#pragma unroll
        for (int u = 0; u < 2; ++u) {
            int f4 = tid * 2 + u, row = f4 >> 2, kq = (f4 & 3) * 4;
            float4 v = *reinterpret_cast<const float4*>(Ap + (size_t)(m0 + row) * kCh + kt + kq);
            As[kq][row] = v.x; As[kq + 1][row] = v.y; As[kq + 2][row] = v.z; As[kq + 3][row] = v.w;
        }
        {
            int row = tid >> 2, kq = (tid & 3) * 4;
            float4 v = *reinterpret_cast<const float4*>(W + (size_t)(n0 + row) * kCh + kt + kq);
            Ws[kq][row] = v.x; Ws[kq + 1][row] = v.y; Ws[kq + 2][row] = v.z; Ws[kq + 3][row] = v.w;
        }
        __syncthreads();
#pragma unroll
        for (int kk = 0; kk < BK; ++kk) {
            float4 a0 = *reinterpret_cast<const float4*>(&As[kk][trow * 8]);
            float4 a1 = *reinterpret_cast<const float4*>(&As[kk][trow * 8 + 4]);
            float4 bb = *reinterpret_cast<const float4*>(&Ws[kk][tcol * 4]);
            float a[8] = {a0.x, a0.y, a0.z, a0.w, a1.x, a1.y, a1.z, a1.w};
            float bj[4] = {bb.x, bb.y, bb.z, bb.w};
#pragma unroll
            for (int i = 0; i < 8; ++i)
#pragma unroll
                for (int j = 0; j < 4; ++j) acc[i][j] = fmaf(a[i], bj[j], acc[i][j]);
        }
        __syncthreads();
    }

    const int nbase = n0 + tcol * 4;
    float4 bv = *reinterpret_cast<const float4*>(bias + nbase);
    float cm[4] = {0.f, 0.f, 0.f, 0.f};
#pragma unroll
    for (int i = 0; i < 8; ++i) {
        int m = m0 + trow * 8 + i;
        float4 v;
        v.x = acc[i][0] + bv.x; v.y = acc[i][1] + bv.y;
        v.z = acc[i][2] + bv.z; v.w = acc[i][3] + bv.w;
        if (EPI == 1) {
            float4 sk = *reinterpret_cast<const float4*>(g_xe + (size_t)m * kCh + nbase);
            v.x = gelu_exact(v.x) + sk.x; v.y = gelu_exact(v.y) + sk.y;
            v.z = gelu_exact(v.z) + sk.z; v.w = gelu_exact(v.w) + sk.w;
        } else {
            cm[0] = fmaxf(cm[0], fabsf(v.x)); cm[1] = fmaxf(cm[1], fabsf(v.y));
            cm[2] = fmaxf(cm[2], fabsf(v.z)); cm[3] = fmaxf(cm[3], fabsf(v.w));
        }
        *reinterpret_cast<float4*>(Cp + (size_t)m * kCh + nbase) = v;
    }
    if (EPI != 1) {
#pragma unroll
        for (int j = 0; j < 4; ++j) red[trow][tcol * 4 + j] = cm[j];
        __syncthreads();
        if (tid < 64) {
            float mx = 0.f;
#pragma unroll
            for (int r = 0; r < 16; ++r) mx = fmaxf(mx, red[r][tid]);
            unsigned* buf = (EPI == 0) ? g_maxxe : g_maxy;
            atomicMax(&buf[(m0 >> 13) * kCh + n0 + tid], __float_as_uint(mx));
        }
    }
}

// g_xe (B,L,C) -> g_xeT (B,C,L)
__global__ __launch_bounds__(256) void transpose_kernel() {
    __shared__ float tile[32][33];
    int b = blockIdx.z, l0 = blockIdx.x * 32, c0 = blockIdx.y * 32;
    int tx = threadIdx.x, ty = threadIdx.y;
    const float* in  = g_xe  + (size_t)b * kSeq * kCh;
    float*       out = g_xeT + (size_t)b * kCh * kSeq;
#pragma unroll
    for (int i = 0; i < 4; ++i)
        tile[ty + i * 8][tx] = in[(size_t)(l0 + ty + i * 8) * kCh + c0 + tx];
    __syncthreads();
#pragma unroll
    for (int i = 0; i < 4; ++i)
        out[(size_t)(c0 + ty + i * 8) * kSeq + l0 + tx] = tile[tx][ty + i * 8];
}

// One CTA per (b,c) row: real-16384 causal conv via packed complex-8192 FFT.
__global__ __launch_bounds__(512, 1) void fftconv_kernel() {
    extern __shared__ float2 sm[];
    float2* tw8  = sm;
    float2* tw16 = sm + 4096;
    float2* b0   = sm + 8193;
    float2* b1   = b0 + kN2;
    for (int i = threadIdx.x; i < 4097; i += 512) {
        if (i < 4096) tw8[i] = g_tw8[i];
        tw16[i] = g_tw16[i];
    }
    const int r = blockIdx.x, c = r & (kCh - 1);
    float* row = g_xeT + (size_t)r * kSeq;
    const float2* row2 = reinterpret_cast<const float2*>(row);
    for (int n = threadIdx.x; n < kN2; n += 512)
        b0[n] = (n < 4096) ? row2[n] : make_float2(0.f, 0.f);
    __syncthreads();

    float2 *src = b0, *dst = b1;
    for (int nn = kN2, s = 1, ls = 0; nn > 1; nn >>= 1, s <<= 1, ++ls) {   // forward
        int nh = nn >> 1;
        for (int t = threadIdx.x; t < 4096; t += 512) {
            int q = t & (s - 1), p = t >> ls;
            float2 a = src[q + s * p], b = src[q + s * (p + nh)], w = tw8[p * s];
            float dx = a.x - b.x, dy = a.y - b.y;
            dst[q + 2 * s * p]     = make_float2(a.x + b.x, a.y + b.y);
            dst[q + 2 * s * p + s] = make_float2(dx * w.x - dy * w.y, dx * w.y + dy * w.x);
        }
        __syncthreads();
        float2* tp = src; src = dst; dst = tp;
    }

    const float2* Kfc = g_Kf + (size_t)c * kNF;
    for (int k = threadIdx.x; k <= 4096; k += 512) {
        int j = (kN2 - k) & (kN2 - 1);
        float2 Zk = src[k], Zj = src[j];
        float2 E = make_float2(0.5f * (Zk.x + Zj.x), 0.5f * (Zk.y - Zj.y));
        float2 O = make_float2(0.5f * (Zk.y + Zj.y), -0.5f * (Zk.x - Zj.x));
        float2 w = tw16[k];
        float2 wO = cmul(w, O);
        float2 Xk = make_float2(E.x + wO.x, E.y + wO.y);
        float2 Xj = make_float2(E.x - wO.x, -(E.y - wO.y));      // X[8192-k]
        float2 Yk = cmul(Xk, Kfc[k]);
        float2 Yj = cmul(Xj, Kfc[kN2 - k]);
        float2 Ey = make_float2(0.5f * (Yk.x + Yj.x), 0.5f * (Yk.y - Yj.y));
        float2 Dy = make_float2(0.5f * (Yk.x - Yj.x), 0.5f * (Yk.y + Yj.y));
        float2 Oy = cmul(make_float2(w.x, -w.y), Dy);
        dst[k] = make_float2(Ey.x - Oy.y, Ey.y + Oy.x);
        if (k >= 1 && k < 4096) {                                // mirror m = 8192-k
            float2 Em = make_float2(0.5f * (Yj.x + Yk.x), 0.5f * (Yj.y - Yk.y));
            float2 Dm = make_float2(0.5f * (Yj.x - Yk.x), 0.5f * (Yj.y + Yk.y));
            float2 Om = cmul(make_float2(-w.x, -w.y), Dm);
            dst[kN2 - k] = make_float2(Em.x - Om.y, Em.y + Om.x);
        }
    }
    __syncthreads();
    { float2* tp = src; src = dst; dst = tp; }

    for (int nn = kN2, s = 1, ls = 0; nn > 1; nn >>= 1, s <<= 1, ++ls) {   // inverse
        int nh = nn >> 1;
        for (int t = threadIdx.x; t < 4096; t += 512) {
            int q = t & (s - 1), p = t >> ls;
            float2 a = src[q + s * p], b = src[q + s * (p + nh)], w = tw8[p * s];
            float dx = a.x - b.x, dy = a.y - b.y;
            dst[q + 2 * s * p]     = make_float2(a.x + b.x, a.y + b.y);
            dst[q + 2 * s * p + s] = make_float2(dx * w.x + dy * w.y, dy * w.x - dx * w.y);
        }
        __syncthreads();
        float2* tp = src; src = dst; dst = tp;
    }
    float2* out2 = reinterpret_cast<float2*>(row);
    for (int n = threadIdx.x; n < 4096; n += 512) out2[n] = src[n];
}

// y1 = gelu(h1 + h0*xe): transpose h1T back to (B,L,C), fuse gelu.
__global__ __launch_bounds__(256) void y1merge_kernel(const float* __restrict__ h0) {
    __shared__ float tile[32][33];
    int b = blockIdx.z, l0 = blockIdx.x * 32, c0 = blockIdx.y * 32;
    int tx = threadIdx.x, ty = threadIdx.y;
    const float* h1T = g_xeT + (size_t)b * kCh * kSeq;
    float h0v = h0[0];
#pragma unroll
    for (int i = 0; i < 4; ++i)
        tile[ty + i * 8][tx] = h1T[(size_t)(c0 + ty + i * 8) * kSeq + l0 + tx];
    __syncthreads();
#pragma unroll
    for (int i = 0; i < 4; ++i) {
        int l = l0 + ty + i * 8;
        size_t idx = ((size_t)b * kSeq + l) * kCh + c0 + tx;
        g_y1[idx] = gelu_exact(tile[tx][ty + i * 8] + h0v * g_xe[idx]);
    }
}

// LayerNorm over channels, in place on g_y2. One warp per row.
__global__ __launch_bounds__(256) void ln_kernel(const float* __restrict__ gamma,
                                                 const float* __restrict__ beta) {
    int warp = threadIdx.x >> 5, lane = threadIdx.x & 31;
    size_t row = (size_t)blockIdx.x * 8 + warp;
    float4* p = reinterpret_cast<float4*>(g_y2 + row * kCh);
    float4 v0 = p[lane], v1 = p[lane + 32];
    float s = v0.x + v0.y + v0.z + v0.w + v1.x + v1.y + v1.z + v1.w;
    float q = v0.x * v0.x + v0.y * v0.y + v0.z * v0.z + v0.w * v0.w
            + v1.x * v1.x + v1.y * v1.y + v1.z * v1.z + v1.w * v1.w;
#pragma unroll
    for (int o = 16; o; o >>= 1) {
        s += __shfl_xor_sync(0xffffffffu, s, o);
        q += __shfl_xor_sync(0xffffffffu, q, o);
    }
    float mu = s * (1.f / 256.f);
    float rstd = rsqrtf(q * (1.f / 256.f) - mu * mu + 1e-5f);
    const float4* g4 = reinterpret_cast<const float4*>(gamma);
    const float4* e4 = reinterpret_cast<const float4*>(beta);
    float4 g0 = g4[lane], g1 = g4[lane + 32], e0 = e4[lane], e1 = e4[lane + 32];
    v0.x = (v0.x - mu) * rstd * g0.x + e0.x; v0.y = (v0.y - mu) * rstd * g0.y + e0.y;
    v0.z = (v0.z - mu) * rstd * g0.z + e0.z; v0.w = (v0.w - mu) * rstd * g0.w + e0.w;
    v1.x = (v1.x - mu) * rstd * g1.x + e1.x; v1.y = (v1.y - mu) * rstd * g1.y + e1.y;
    v1.z = (v1.z - mu) * rstd * g1.z + e1.z; v1.w = (v1.w - mu) * rstd * g1.w + e1.w;
    p[lane] = v0; p[lane + 32] = v1;
}

__global__ void hout_kernel(float* __restrict__ h) {
    int i = blockIdx.x * 256 + threadIdx.x;
    if (i < kB * kCh)
        h[i] = __uint_as_float(g_maxy[i]) / (__uint_as_float(g_maxxe[i]) + 1e-6f);
}

extern "C" void kernel_launch(void* const* d_in, const int* in_sizes, int n_in,
                              void* d_out, int out_size) {
    const float* x     = (const float*)d_in[0];
    const float* A     = (const float*)d_in[1];
    const float* Bp    = (const float*)d_in[2];
    const float* h0    = (const float*)d_in[3];
    const float* W_enc = (const float*)d_in[4];
    const float* b_enc = (const float*)d_in[5];
    const float* W_fc  = (const float*)d_in[6];
    const float* b_fc  = (const float*)d_in[7];
    const float* gamma = (const float*)d_in[8];
    const float* beta  = (const float*)d_in[9];
    const float* W_dec = (const float*)d_in[10];
    const float* b_dec = (const float*)d_in[11];
    float* out = (float*)d_out;

    const int kSmemFFT = 24577 * 8;   // 196616 B dynamic SMEM
    cudaFuncSetAttribute(fftconv_kernel, cudaFuncAttributeMaxDynamicSharedMemorySize, kSmemFFT);

    zero_kernel<<<8, 256>>>();
    twiddle_kernel<<<17, 256>>>();
    kfgen_kernel<<<dim3(33, kCh), 256>>>(A, Bp);
    gemm_kernel<0><<<dim3(kM / 128, kCh / 64), 256>>>(x, W_enc, b_enc, nullptr);
    transpose_kernel<<<dim3(kSeq / 32, kCh / 32, kB), dim3(32, 8)>>>();
    fftconv_kernel<<<kB * kCh, 512, kSmemFFT>>>();
    y1merge_kernel<<<dim3(kSeq / 32, kCh / 32, kB), dim3(32, 8)>>>(h0);
    gemm_kernel<1><<<dim3(kM / 128, kCh / 64), 256>>>(nullptr, W_fc, b_fc, nullptr);
    ln_kernel<<<kM / 8, 256>>>(gamma, beta);
    gemm_kernel<2><<<dim3(kM / 128, kCh / 64), 256>>>(nullptr, W_dec, b_dec, out);
    hout_kernel<<<8, 256>>>(out + (size_t)kM * kCh);
}

// round 3
// speedup vs baseline: 1.1421x; 1.1421x over previous
#include <cuda_runtime.h>

constexpr int kB = 8, kSeq = 8192, kCh = 256;
constexpr int kM  = kB * kSeq;          // 65536
constexpr int kN2 = 8192;               // complex FFT size (real 16384)
constexpr int kNF = 8193;               // rfft bins of 16384

__device__ __align__(128) float  g_xe [kM * kCh];   // (B,L,C)
__device__ __align__(128) float  g_xeT[kM * kCh];   // (B,C,L)
__device__ __align__(128) float  g_h1T[kM * kCh];   // (B,C,L); becomes y1T in place
__device__ __align__(128) float  g_y2 [kM * kCh];   // (B,L,C)
__device__ __align__(128) float2 g_Kf [(size_t)kCh * kNF];
__device__ float2 g_tw8 [4096];
__device__ float2 g_tw16[4097];
__device__ unsigned g_maxxe[kB * kCh];
__device__ unsigned g_maxy [kB * kCh];

__device__ __forceinline__ float2 cmul(float2 a, float2 b) {
    return make_float2(a.x * b.x - a.y * b.y, a.x * b.y + a.y * b.x);
}
__device__ __forceinline__ float2 cadd(float2 a, float2 b) {
    return make_float2(a.x + b.x, a.y + b.y);
}
__device__ __forceinline__ float2 csub(float2 a, float2 b) {
    return make_float2(a.x - b.x, a.y - b.y);
}
__device__ __forceinline__ float gelu_exact(float v) {
    return 0.5f * v * (1.0f + erff(v * 0.7071067811865476f));
}

__global__ void zero_kernel() {
    int i = blockIdx.x * 256 + threadIdx.x;
    if (i < kB * kCh) { g_maxxe[i] = 0u; g_maxy[i] = 0u; }
}

__global__ void twiddle_kernel() {
    int i = blockIdx.x * 256 + threadIdx.x;
    float s, c;
    if (i < 4096) { sincospif(-2.0f * i / 8192.0f,  &s, &c); g_tw8 [i] = make_float2(c, s); }
    if (i < 4097) { sincospif(-2.0f * i / 16384.0f, &s, &c); g_tw16[i] = make_float2(c, s); }
}

// Kf[c][k] = B(w)/A(w)/8192, w = e^{-2*pi*i*k/16384}. (IIR tail beyond n=8192
// underflows fp32, so this equals the reference's FFT-generated kernel.)
__global__ __launch_bounds__(256) void kfgen_kernel(const float* __restrict__ A,
                                                    const float* __restrict__ Bp) {
    __shared__ float sA[64], sB[64];
    int c = blockIdx.y;
    if (threadIdx.x < 64)       sA[threadIdx.x]      = A [c * 64 + threadIdx.x];
    else if (threadIdx.x < 128) sB[threadIdx.x - 64] = Bp[c * 64 + threadIdx.x - 64];
    __syncthreads();
    int k = blockIdx.x * 256 + threadIdx.x;
    if (k >= kNF) return;
    float sv, cv;
    sincospif(-(float)k / 8192.0f, &sv, &cv);
    float2 w = make_float2(cv, sv);
    float2 av = make_float2(sA[63], 0.f);
    for (int j = 62; j >= 0; --j) { av = cmul(av, w); av.x += sA[j]; }
    av = cmul(av, w); av.x += 1.0f;
    float2 bv = make_float2(sB[63], 0.f);
    for (int j = 62; j >= 0; --j) { bv = cmul(bv, w); bv.x += sB[j]; }
    float scl = (1.0f / 8192.0f) / (av.x * av.x + av.y * av.y);
    g_Kf[(size_t)c * kNF + k] = make_float2((bv.x * av.x + bv.y * av.y) * scl,
                                            (bv.y * av.x - bv.x * av.y) * scl);
}

// ---------------------------------------------------------------------------
// GEMM: C[M,256] = epi(A[M,256] @ W[256,256]^T + bias)
// EPI 0: encode (x (B,L,C) -> g_xe, colmax -> g_maxxe)
// EPI 1: fc     (g_h1T (B,C,L, =y1T) -> g_y2, v = gelu(v) + xe skip)
// EPI 2: decode (g_y2 -> d_out, colmax -> g_maxy)
template <int EPI>
__global__ __launch_bounds__(256, 2) void gemm_kernel(const float* __restrict__ Ain,
                                                      const float* __restrict__ W,
                                                      const float* __restrict__ bias,
                                                      float* __restrict__ Cout) {
    constexpr int BM = 128, BN = 128, BK = 16;
    __shared__ float As[BK][BM + 4];
    __shared__ float Ws[BK][BN + 4];
    __shared__ float red[16][BN];
    const float* Ap = (EPI == 1) ? g_h1T : (EPI == 2 ? g_y2 : Ain);
    float*       Cp = (EPI == 0) ? g_xe : (EPI == 1 ? g_y2 : Cout);
    const int m0 = blockIdx.x * BM, n0 = blockIdx.y * BN;
    const int tid = threadIdx.x, trow = tid >> 4, tcol = tid & 15;
    float acc[8][8];
#pragma unroll
    for (int i = 0; i < 8; ++i)
#pragma unroll
        for (int j = 0; j < 8; ++j) acc[i][j] = 0.f;

    float4 pa[2], pw[2];
    auto loadA = [&](int kt, int u) -> float4 {
        int f4 = tid * 2 + u;
        if (EPI == 1) {
            int b = m0 >> 13, l0 = m0 & (kSeq - 1);
            int ch = f4 >> 5, lq = (f4 & 31) * 4;
            return *reinterpret_cast<const float4*>(
                Ap + ((size_t)b * kCh + kt + ch) * kSeq + l0 + lq);
        } else {
            int row = f4 >> 2, kq = (f4 & 3) * 4;
            return *reinterpret_cast<const float4*>(
                Ap + (size_t)(m0 + row) * kCh + kt + kq);
        }
    };
    auto loadW = [&](int kt, int u) -> float4 {
        int f4 = tid * 2 + u, row = f4 >> 2, kq = (f4 & 3) * 4;
        return *reinterpret_cast<const float4*>(
            W + (size_t)(n0 + row) * kCh + kt + kq);
    };
#pragma unroll
    for (int u = 0; u < 2; ++u) { pa[u] = loadA(0, u); pw[u] = loadW(0, u); }

    for (int kt = 0; kt < kCh; kt += BK) {
#pragma unroll
        for (int u = 0; u < 2; ++u) {
            int f4 = tid * 2 + u;
            if (EPI == 1) {
                int ch = f4 >> 5, lq = (f4 & 31) * 4;
                *reinterpret_cast<float4*>(&As[ch][lq]) = pa[u];
            } else {
                int row = f4 >> 2, kq = (f4 & 3) * 4;
                As[kq][row] = pa[u].x; As[kq + 1][row] = pa[u].y;
                As[kq + 2][row] = pa[u].z; As[kq + 3][row] = pa[u].w;
            }
            int row = f4 >> 2, kq = (f4 & 3) * 4;
            Ws[kq][row] = pw[u].x; Ws[kq + 1][row] = pw[u].y;
            Ws[kq + 2][row] = pw[u].z; Ws[kq + 3][row] = pw[u].w;
        }
        __syncthreads();
        if (kt + BK < kCh) {
#pragma unroll
            for (int u = 0; u < 2; ++u) { pa[u] = loadA(kt + BK, u); pw[u] = loadW(kt + BK, u); }
        }
#pragma unroll
        for (int kk = 0; kk < BK; ++kk) {
            float4 a0 = *reinterpret_cast<const float4*>(&As[kk][trow * 8]);
            float4 a1 = *reinterpret_cast<const float4*>(&As[kk][trow * 8 + 4]);
            float4 b0 = *reinterpret_cast<const float4*>(&Ws[kk][tcol * 8]);
            float4 b1 = *reinterpret_cast<const float4*>(&Ws[kk][tcol * 8 + 4]);
            float a[8] = {a0.x, a0.y, a0.z, a0.w, a1.x, a1.y, a1.z, a1.w};
            float bb[8] = {b0.x, b0.y, b0.z, b0.w, b1.x, b1.y, b1.z, b1.w};
#pragma unroll
            for (int i = 0; i < 8; ++i)
#pragma unroll
                for (int j = 0; j < 8; ++j) acc[i][j] = fmaf(a[i], bb[j], acc[i][j]);
        }
        __syncthreads();
    }

    const int nbase = n0 + tcol * 8;
    float4 bv0 = *reinterpret_cast<const float4*>(bias + nbase);
    float4 bv1 = *reinterpret_cast<const float4*>(bias + nbase + 4);
    float cm[8] = {0.f, 0.f, 0.f, 0.f, 0.f, 0.f, 0.f, 0.f};
#pragma unroll
    for (int i = 0; i < 8; ++i) {
        int m = m0 + trow * 8 + i;
        float4 v0, v1;
        v0.x = acc[i][0] + bv0.x; v0.y = acc[i][1] + bv0.y;
        v0.z = acc[i][2] + bv0.z; v0.w = acc[i][3] + bv0.w;
        v1.x = acc[i][4] + bv1.x; v1.y = acc[i][5] + bv1.y;
        v1.z = acc[i][6] + bv1.z; v1.w = acc[i][7] + bv1.w;
        if (EPI == 1) {
            float4 s0 = *reinterpret_cast<const float4*>(g_xe + (size_t)m * kCh + nbase);
            float4 s1 = *reinterpret_cast<const float4*>(g_xe + (size_t)m * kCh + nbase + 4);
            v0.x = gelu_exact(v0.x) + s0.x; v0.y = gelu_exact(v0.y) + s0.y;
            v0.z = gelu_exact(v0.z) + s0.z; v0.w = gelu_exact(v0.w) + s0.w;
            v1.x = gelu_exact(v1.x) + s1.x; v1.y = gelu_exact(v1.y) + s1.y;
            v1.z = gelu_exact(v1.z) + s1.z; v1.w = gelu_exact(v1.w) + s1.w;
        } else {
            cm[0] = fmaxf(cm[0], fabsf(v0.x)); cm[1] = fmaxf(cm[1], fabsf(v0.y));
            cm[2] = fmaxf(cm[2], fabsf(v0.z)); cm[3] = fmaxf(cm[3], fabsf(v0.w));
            cm[4] = fmaxf(cm[4], fabsf(v1.x)); cm[5] = fmaxf(cm[5], fabsf(v1.y));
            cm[6] = fmaxf(cm[6], fabsf(v1.z)); cm[7] = fmaxf(cm[7], fabsf(v1.w));
        }
        *reinterpret_cast<float4*>(Cp + (size_t)m * kCh + nbase)     = v0;
        *reinterpret_cast<float4*>(Cp + (size_t)m * kCh + nbase + 4) = v1;
    }
    if (EPI != 1) {
#pragma unroll
        for (int j = 0; j < 8; ++j) red[trow][tcol * 8 + j] = cm[j];
        __syncthreads();
        if (tid < BN) {
            float mx = 0.f;
#pragma unroll
            for (int r = 0; r < 16; ++r) mx = fmaxf(mx, red[r][tid]);
            unsigned* buf = (EPI == 0) ? g_maxxe : g_maxy;
            atomicMax(&buf[(m0 >> 13) * kCh + n0 + tid], __float_as_uint(mx));
        }
    }
}

// g_xe (B,L,C) -> g_xeT (B,C,L)
__global__ __launch_bounds__(256) void transpose_kernel() {
    __shared__ float tile[32][33];
    int b = blockIdx.z, l0 = blockIdx.x * 32, c0 = blockIdx.y * 32;
    int tx = threadIdx.x, ty = threadIdx.y;
    const float* in  = g_xe  + (size_t)b * kSeq * kCh;
    float*       out = g_xeT + (size_t)b * kCh * kSeq;
#pragma unroll
    for (int i = 0; i < 4; ++i)
        tile[ty + i * 8][tx] = in[(size_t)(l0 + ty + i * 8) * kCh + c0 + tx];
    __syncthreads();
#pragma unroll
    for (int i = 0; i < 4; ++i)
        out[(size_t)(c0 + ty + i * 8) * kSeq + l0 + tx] = tile[tx][ty + i * 8];
}

// Mixed-radix Stockham: 6 radix-4 stages + 1 radix-2, autosorting ping-pong.
template <bool INV>
__device__ __forceinline__ void fft_stages(float2*& src, float2*& dst, const float2* tw) {
    int nn = kN2, s = 1, ls = 0;
    while (nn > 2) {
        int nq = nn >> 2;
        for (int t = threadIdx.x; t < 2048; t += 512) {
            int q = t & (s - 1), p = t >> ls;
            float2 a0 = src[q + (p << ls)];
            float2 a1 = src[q + ((p + nq) << ls)];
            float2 a2 = src[q + ((p + 2 * nq) << ls)];
            float2 a3 = src[q + ((p + 3 * nq) << ls)];
            float2 t0 = cadd(a0, a2), t1 = csub(a0, a2);
            float2 t2 = cadd(a1, a3), t3 = csub(a1, a3);
            float2 b0 = cadd(t0, t2), b2 = csub(t0, t2);
            float2 b1, b3;
            if (!INV) {   // b1 = t1 - i t3, b3 = t1 + i t3
                b1 = make_float2(t1.x + t3.y, t1.y - t3.x);
                b3 = make_float2(t1.x - t3.y, t1.y + t3.x);
            } else {
                b1 = make_float2(t1.x - t3.y, t1.y + t3.x);
                b3 = make_float2(t1.x + t3.y, t1.y - t3.x);
            }
            float2 w1 = tw[p << ls];
            if (INV) w1.y = -w1.y;
            float2 w2 = cmul(w1, w1), w3 = cmul(w2, w1);
            int o = q + (p << (ls + 2));
            dst[o]         = b0;
            dst[o + s]     = cmul(w1, b1);
            dst[o + 2 * s] = cmul(w2, b2);
            dst[o + 3 * s] = cmul(w3, b3);
        }
        __syncthreads();
        float2* tp = src; src = dst; dst = tp;
        nn >>= 2; s <<= 2; ls += 2;
    }
    // nn == 2, s == 4096, twiddle = 1
    for (int t = threadIdx.x; t < 4096; t += 512) {
        float2 a = src[t], b = src[t + 4096];
        dst[t]        = cadd(a, b);
        dst[t + 4096] = csub(a, b);
    }
    __syncthreads();
    float2* tp = src; src = dst; dst = tp;
}

// One CTA per (b,c) row: real-16384 causal conv via packed complex-8192 FFT.
// Reads g_xeT row, writes g_h1T row.
__global__ __launch_bounds__(512, 1) void fftconv_kernel() {
    extern __shared__ float2 sm[];
    float2* tw8  = sm;
    float2* tw16 = sm + 4096;
    float2* b0   = sm + 8193;
    float2* b1   = b0 + kN2;
    for (int i = threadIdx.x; i < 4097; i += 512) {
        if (i < 4096) tw8[i] = g_tw8[i];
        tw16[i] = g_tw16[i];
    }
    const int r = blockIdx.x, c = r & (kCh - 1);
    const float2* row2 = reinterpret_cast<const float2*>(g_xeT + (size_t)r * kSeq);
    for (int n = threadIdx.x; n < kN2; n += 512)
        b0[n] = (n < 4096) ? row2[n] : make_float2(0.f, 0.f);
    __syncthreads();

    float2 *src = b0, *dst = b1;
    fft_stages<false>(src, dst, tw8);

    const float2* Kfc = g_Kf + (size_t)c * kNF;
    for (int k = threadIdx.x; k <= 4096; k += 512) {
        int j = (kN2 - k) & (kN2 - 1);
        float2 Zk = src[k], Zj = src[j];
        float2 E = make_float2(0.5f * (Zk.x + Zj.x), 0.5f * (Zk.y - Zj.y));
        float2 O = make_float2(0.5f * (Zk.y + Zj.y), -0.5f * (Zk.x - Zj.x));
        float2 w = tw16[k];
        float2 wO = cmul(w, O);
        float2 Xk = make_float2(E.x + wO.x, E.y + wO.y);
        float2 Xj = make_float2(E.x - wO.x, -(E.y - wO.y));      // X[8192-k]
        float2 Yk = cmul(Xk, Kfc[k]);
        float2 Yj = cmul(Xj, Kfc[kN2 - k]);
        float2 Ey = make_float2(0.5f * (Yk.x + Yj.x), 0.5f * (Yk.y - Yj.y));
        float2 Dy = make_float2(0.5f * (Yk.x - Yj.x), 0.5f * (Yk.y + Yj.y));
        float2 Oy = cmul(make_float2(w.x, -w.y), Dy);
        dst[k] = make_float2(Ey.x - Oy.y, Ey.y + Oy.x);
        if (k >= 1 && k < 4096) {                                // mirror m = 8192-k
            float2 Em = make_float2(0.5f * (Yj.x + Yk.x), 0.5f * (Yj.y - Yk.y));
            float2 Dm = make_float2(0.5f * (Yj.x - Yk.x), 0.5f * (Yj.y + Yk.y));
            float2 Om = cmul(make_float2(-w.x, -w.y), Dm);
            dst[kN2 - k] = make_float2(Em.x - Om.y, Em.y + Om.x);
        }
    }
    __syncthreads();
    { float2* tp = src; src = dst; dst = tp; }

    fft_stages<true>(src, dst, tw8);

    float2* out2 = reinterpret_cast<float2*>(g_h1T + (size_t)r * kSeq);
    for (int n = threadIdx.x; n < 4096; n += 512) out2[n] = src[n];
}

// y1T = gelu(h1T + h0*xeT), elementwise, in place on g_h1T.
__global__ __launch_bounds__(256) void y1_kernel(const float* __restrict__ h0) {
    size_t i = ((size_t)blockIdx.x * 256 + threadIdx.x) * 4;
    float h0v = h0[0];
    float4 h = *reinterpret_cast<const float4*>(g_h1T + i);
    float4 e = *reinterpret_cast<const float4*>(g_xeT + i);
    h.x = gelu_exact(h.x + h0v * e.x); h.y = gelu_exact(h.y + h0v * e.y);
    h.z = gelu_exact(h.z + h0v * e.z); h.w = gelu_exact(h.w + h0v * e.w);
    *reinterpret_cast<float4*>(g_h1T + i) = h;
}

// LayerNorm over channels, in place on g_y2. One warp per row.
__global__ __launch_bounds__(256) void ln_kernel(const float* __restrict__ gamma,
                                                 const float* __restrict__ beta) {
    int warp = threadIdx.x >> 5, lane = threadIdx.x & 31;
    size_t row = (size_t)blockIdx.x * 8 + warp;
    float4* p = reinterpret_cast<float4*>(g_y2 + row * kCh);
    float4 v0 = p[lane], v1 = p[lane + 32];
    float s = v0.x + v0.y + v0.z + v0.w + v1.x + v1.y + v1.z + v1.w;
    float q = v0.x * v0.x + v0.y * v0.y + v0.z * v0.z + v0.w * v0.w
            + v1.x * v1.x + v1.y * v1.y + v1.z * v1.z + v1.w * v1.w;
#pragma unroll
    for (int o = 16; o; o >>= 1) {
        s += __shfl_xor_sync(0xffffffffu, s, o);
        q += __shfl_xor_sync(0xffffffffu, q, o);
    }
    float mu = s * (1.f / 256.f);
    float rstd = rsqrtf(q * (1.f / 256.f) - mu * mu + 1e-5f);
    const float4* g4 = reinterpret_cast<const float4*>(gamma);
    const float4* e4 = reinterpret_cast<const float4*>(beta);
    float4 g0 = g4[lane], g1 = g4[lane + 32], e0 = e4[lane], e1 = e4[lane + 32];
    v0.x = (v0.x - mu) * rstd * g0.x + e0.x; v0.y = (v0.y - mu) * rstd * g0.y + e0.y;
    v0.z = (v0.z - mu) * rstd * g0.z + e0.z; v0.w = (v0.w - mu) * rstd * g0.w + e0.w;
    v1.x = (v1.x - mu) * rstd * g1.x + e1.x; v1.y = (v1.y - mu) * rstd * g1.y + e1.y;
    v1.z = (v1.z - mu) * rstd * g1.z + e1.z; v1.w = (v1.w - mu) * rstd * g1.w + e1.w;
    p[lane] = v0; p[lane + 32] = v1;
}

__global__ void hout_kernel(float* __restrict__ h) {
    int i = blockIdx.x * 256 + threadIdx.x;
    if (i < kB * kCh)
        h[i] = __uint_as_float(g_maxy[i]) / (__uint_as_float(g_maxxe[i]) + 1e-6f);
}

extern "C" void kernel_launch(void* const* d_in, const int* in_sizes, int n_in,
                              void* d_out, int out_size) {
    const float* x     = (const float*)d_in[0];
    const float* A     = (const float*)d_in[1];
    const float* Bp    = (const float*)d_in[2];
    const float* h0    = (const float*)d_in[3];
    const float* W_enc = (const float*)d_in[4];
    const float* b_enc = (const float*)d_in[5];
    const float* W_fc  = (const float*)d_in[6];
    const float* b_fc  = (const float*)d_in[7];
    const float* gamma = (const float*)d_in[8];
    const float* beta  = (const float*)d_in[9];
    const float* W_dec = (const float*)d_in[10];
    const float* b_dec = (const float*)d_in[11];
    float* out = (float*)d_out;

    const int kSmemFFT = 24577 * 8;   // 196616 B dynamic SMEM
    cudaFuncSetAttribute(fftconv_kernel, cudaFuncAttributeMaxDynamicSharedMemorySize, kSmemFFT);

    zero_kernel<<<8, 256>>>();
    twiddle_kernel<<<17, 256>>>();
    kfgen_kernel<<<dim3(33, kCh), 256>>>(A, Bp);
    gemm_kernel<0><<<dim3(kM / 128, kCh / 128), 256>>>(x, W_enc, b_enc, nullptr);
    transpose_kernel<<<dim3(kSeq / 32, kCh / 32, kB), dim3(32, 8)>>>();
    fftconv_kernel<<<kB * kCh, 512, kSmemFFT>>>();
    y1_kernel<<<kM * kCh / 1024, 256>>>(h0);
    gemm_kernel<1><<<dim3(kM / 128, kCh / 128), 256>>>(nullptr, W_fc, b_fc, nullptr);
    ln_kernel<<<kM / 8, 256>>>(gamma, beta);
    gemm_kernel<2><<<dim3(kM / 128, kCh / 128), 256>>>(nullptr, W_dec, b_dec, out);
    hout_kernel<<<8, 256>>>(out + (size_t)kM * kCh);
}

// round 5
// speedup vs baseline: 1.5298x; 1.3394x over previous
#include <cuda_runtime.h>
#include <cuda_bf16.h>

constexpr int kB = 8, kSeq = 8192, kCh = 256;
constexpr int kM  = kB * kSeq;          // 65536
constexpr int kN2 = 8192;               // complex FFT size (real 16384)
constexpr int kNF = 8193;               // rfft bins of 16384

__device__ __align__(128) float  g_xe [kM * kCh];   // (B,L,C)
__device__ __align__(128) float  g_xeT[kM * kCh];   // (B,C,L); FFT in place -> h1T
__device__ __align__(128) float  g_y1 [kM * kCh];   // (B,L,C)
__device__ __align__(128) float  g_y2 [kM * kCh];   // (B,L,C)
__device__ __align__(128) float2 g_Kf [(size_t)kCh * kNF];
__device__ __align__(128) __nv_bfloat16 g_Wh[3 * kCh * kCh];
__device__ __align__(128) __nv_bfloat16 g_Wl[3 * kCh * kCh];
__device__ float2 g_tw8 [4096];
__device__ float2 g_tw16[4097];
__device__ unsigned g_maxxe[kB * kCh];
__device__ unsigned g_maxy [kB * kCh];

__device__ __forceinline__ float2 cmul(float2 a, float2 b) {
    return make_float2(a.x * b.x - a.y * b.y, a.x * b.y + a.y * b.x);
}
__device__ __forceinline__ float2 cadd(float2 a, float2 b) {
    return make_float2(a.x + b.x, a.y + b.y);
}
__device__ __forceinline__ float2 csub(float2 a, float2 b) {
    return make_float2(a.x - b.x, a.y - b.y);
}
__device__ __forceinline__ float gelu_exact(float v) {
    return 0.5f * v * (1.0f + erff(v * 0.7071067811865476f));
}
__device__ __forceinline__ void ldsm4(unsigned* r, const void* p) {
    unsigned addr = (unsigned)__cvta_generic_to_shared(p);
    asm volatile("ldmatrix.sync.aligned.m8n8.x4.shared.b16 {%0,%1,%2,%3}, [%4];"
                 : "=r"(r[0]), "=r"(r[1]), "=r"(r[2]), "=r"(r[3]) : "r"(addr));
}
__device__ __forceinline__ void mma16816(float* d, const unsigned* a, const unsigned* b) {
    asm volatile("mma.sync.aligned.m16n8k16.row.col.f32.bf16.bf16.f32 "
                 "{%0,%1,%2,%3}, {%4,%5,%6,%7}, {%8,%9}, {%0,%1,%2,%3};"
                 : "+f"(d[0]), "+f"(d[1]), "+f"(d[2]), "+f"(d[3])
                 : "r"(a[0]), "r"(a[1]), "r"(a[2]), "r"(a[3]), "r"(b[0]), "r"(b[1]));
}

__global__ void zero_kernel() {
    int i = blockIdx.x * 256 + threadIdx.x;
    if (i < kB * kCh) { g_maxxe[i] = 0u; g_maxy[i] = 0u; }
}

__global__ void twiddle_kernel() {
    int i = blockIdx.x * 256 + threadIdx.x;
    float s, c;
    if (i < 4096) { sincospif(-2.0f * i / 8192.0f,  &s, &c); g_tw8 [i] = make_float2(c, s); }
    if (i < 4097) { sincospif(-2.0f * i / 16384.0f, &s, &c); g_tw16[i] = make_float2(c, s); }
}

// Split the 3 weight matrices into hi/lo bf16 pairs (x = hi + lo exactly to 2^-18).
__global__ void wsplit_kernel(const float* __restrict__ We, const float* __restrict__ Wf,
                              const float* __restrict__ Wd) {
    int i = blockIdx.x * 256 + threadIdx.x;
    const float* src = (blockIdx.y == 0) ? We : (blockIdx.y == 1 ? Wf : Wd);
    float v = src[i];
    __nv_bfloat16 h = __float2bfloat16(v);
    g_Wh[blockIdx.y * kCh * kCh + i] = h;
    g_Wl[blockIdx.y * kCh * kCh + i] = __float2bfloat16(v - __bfloat162float(h));
}

// Kf[c][k] = B(w)/A(w)/8192, w = e^{-2*pi*i*k/16384}. (IIR tail beyond n=8192
// underflows fp32, so this equals the reference's FFT-generated kernel.)
__global__ __launch_bounds__(256) void kfgen_kernel(const float* __restrict__ A,
                                                    const float* __restrict__ Bp) {
    __shared__ float sA[64], sB[64];
    int c = blockIdx.y;
    if (threadIdx.x < 64)       sA[threadIdx.x]      = A [c * 64 + threadIdx.x];
    else if (threadIdx.x < 128) sB[threadIdx.x - 64] = Bp[c * 64 + threadIdx.x - 64];
    __syncthreads();
    int k = blockIdx.x * 256 + threadIdx.x;
    if (k >= kNF) return;
    float sv, cv;
    sincospif(-(float)k / 8192.0f, &sv, &cv);
    float2 w = make_float2(cv, sv);
    float2 av = make_float2(sA[63], 0.f);
    for (int j = 62; j >= 0; --j) { av = cmul(av, w); av.x += sA[j]; }
    av = cmul(av, w); av.x += 1.0f;
    float2 bv = make_float2(sB[63], 0.f);
    for (int j = 62; j >= 0; --j) { bv = cmul(bv, w); bv.x += sB[j]; }
    float scl = (1.0f / 8192.0f) / (av.x * av.x + av.y * av.y);
    g_Kf[(size_t)c * kNF + k] = make_float2((bv.x * av.x + bv.y * av.y) * scl,
                                            (bv.y * av.x - bv.x * av.y) * scl);
}

// ---------------------------------------------------------------------------
// Tensor-core GEMM: C[M,256] = epi(A[M,256] @ W[256,256]^T + bias)
// 3-pass bf16 split: D = Ah*Wh + Ah*Wl + Al*Wh  (error ~2^-17).
// EPI 0: encode (x -> g_xe, colmax -> g_maxxe)
// EPI 1: fc     (g_y1 -> g_y2, v = gelu(v) + xe skip)
// EPI 2: decode (g_y2 -> d_out, colmax -> g_maxy)
template <int EPI>
__global__ __launch_bounds__(256, 2) void gemm_kernel(const float* __restrict__ Ain,
                                                      const float* __restrict__ bias,
                                                      float* __restrict__ Cout) {
    constexpr int BM = 128, BN = 128, BK = 32, LDS = 40;   // 80B row stride: conflict-free
    __shared__ __nv_bfloat16 Ah[BM][LDS], Al[BM][LDS];
    __shared__ __nv_bfloat16 Bh[BN][LDS], Bl[BN][LDS];
    __shared__ unsigned red[BN];
    const float* Ap = (EPI == 1) ? g_y1 : (EPI == 2 ? g_y2 : Ain);
    float*       Cp = (EPI == 0) ? g_xe : (EPI == 1 ? g_y2 : Cout);
    const __nv_bfloat16* Whp = g_Wh + EPI * kCh * kCh;
    const __nv_bfloat16* Wlp = g_Wl + EPI * kCh * kCh;
    const int m0 = blockIdx.x * BM, n0 = blockIdx.y * BN;
    const int tid = threadIdx.x, lane = tid & 31, warp = tid >> 5;
    const int wr = warp >> 1, wc = warp & 1;      // 4x2 warp grid, warp tile 32x64

    if (EPI != 1 && tid < BN) red[tid] = 0u;

    float acc[2][8][4];
#pragma unroll
    for (int mt = 0; mt < 2; ++mt)
#pragma unroll
        for (int nt = 0; nt < 8; ++nt)
#pragma unroll
            for (int r = 0; r < 4; ++r) acc[mt][nt][r] = 0.f;

    for (int kt = 0; kt < kCh; kt += BK) {
        // A: load fp32 128x32, split to hi/lo bf16
#pragma unroll
        for (int u = 0; u < 4; ++u) {
            int idx = u * 256 + tid;               // 0..1023 float4s
            int row = idx >> 3, c4 = (idx & 7) * 4;
            float4 v = *reinterpret_cast<const float4*>(
                Ap + (size_t)(m0 + row) * kCh + kt + c4);
            __nv_bfloat162 h01 = __floats2bfloat162_rn(v.x, v.y);
            __nv_bfloat162 h23 = __floats2bfloat162_rn(v.z, v.w);
            __nv_bfloat162 l01 = __floats2bfloat162_rn(v.x - __low2float(h01),
                                                       v.y - __high2float(h01));
            __nv_bfloat162 l23 = __floats2bfloat162_rn(v.z - __low2float(h23),
                                                       v.w - __high2float(h23));
            *reinterpret_cast<uint2*>(&Ah[row][c4]) =
                make_uint2(*reinterpret_cast<unsigned*>(&h01), *reinterpret_cast<unsigned*>(&h23));
            *reinterpret_cast<uint2*>(&Al[row][c4]) =
                make_uint2(*reinterpret_cast<unsigned*>(&l01), *reinterpret_cast<unsigned*>(&l23));
        }
        // W: copy pre-split bf16 128x32 (hi and lo)
#pragma unroll
        for (int u = 0; u < 2; ++u) {
            int idx = u * 256 + tid;               // 0..511 uint4s
            int row = idx >> 2, c8 = (idx & 3) * 8;
            *reinterpret_cast<uint4*>(&Bh[row][c8]) =
                *reinterpret_cast<const uint4*>(Whp + (size_t)(n0 + row) * kCh + kt + c8);
            *reinterpret_cast<uint4*>(&Bl[row][c8]) =
                *reinterpret_cast<const uint4*>(Wlp + (size_t)(n0 + row) * kCh + kt + c8);
        }
        __syncthreads();
#pragma unroll
        for (int ks = 0; ks < 2; ++ks) {
            const int kb = ks * 16;
            unsigned ah[2][4], al[2][4];
#pragma unroll
            for (int mt = 0; mt < 2; ++mt) {
                int arow = wr * 32 + mt * 16 + (lane & 15);
                int koff = kb + ((lane >> 4) << 3);
                ldsm4(ah[mt], &Ah[arow][koff]);
                ldsm4(al[mt], &Al[arow][koff]);
            }
#pragma unroll
            for (int g = 0; g < 4; ++g) {
                int nrow = wc * 64 + g * 16 + (lane & 7) + ((lane >> 4) << 3);
                int koff = kb + (((lane >> 3) & 1) << 3);
                unsigned bh[4], bl[4];
                ldsm4(bh, &Bh[nrow][koff]);
                ldsm4(bl, &Bl[nrow][koff]);
#pragma unroll
                for (int mt = 0; mt < 2; ++mt) {
                    mma16816(acc[mt][2 * g],     ah[mt], bh);
                    mma16816(acc[mt][2 * g],     ah[mt], bl);
                    mma16816(acc[mt][2 * g],     al[mt], bh);
                    mma16816(acc[mt][2 * g + 1], ah[mt], bh + 2);
                    mma16816(acc[mt][2 * g + 1], ah[mt], bl + 2);
                    mma16816(acc[mt][2 * g + 1], al[mt], bh + 2);
                }
            }
        }
        __syncthreads();
    }

    // Epilogue: d0,d1 -> (row, col..col+1); d2,d3 -> (row+8, ...)
#pragma unroll
    for (int mt = 0; mt < 2; ++mt) {
        int r0 = m0 + wr * 32 + mt * 16 + (lane >> 2);
#pragma unroll
        for (int nt = 0; nt < 8; ++nt) {
            int col = n0 + wc * 64 + nt * 8 + (lane & 3) * 2;
            float* c = acc[mt][nt];
            float2 bv = *reinterpret_cast<const float2*>(bias + col);
            float v0 = c[0] + bv.x, v1 = c[1] + bv.y;
            float v2 = c[2] + bv.x, v3 = c[3] + bv.y;
            if (EPI == 1) {
                float2 s0 = *reinterpret_cast<const float2*>(g_xe + (size_t)r0 * kCh + col);
                float2 s1 = *reinterpret_cast<const float2*>(g_xe + (size_t)(r0 + 8) * kCh + col);
                v0 = gelu_exact(v0) + s0.x; v1 = gelu_exact(v1) + s0.y;
                v2 = gelu_exact(v2) + s1.x; v3 = gelu_exact(v3) + s1.y;
            } else {
                float me = fmaxf(fabsf(v0), fabsf(v2));
                float mo = fmaxf(fabsf(v1), fabsf(v3));
#pragma unroll
                for (int o = 4; o < 32; o <<= 1) {
                    me = fmaxf(me, __shfl_xor_sync(0xffffffffu, me, o));
                    mo = fmaxf(mo, __shfl_xor_sync(0xffffffffu, mo, o));
                }
                if (lane < 4) {
                    atomicMax(&red[col - n0],     __float_as_uint(me));
                    atomicMax(&red[col - n0 + 1], __float_as_uint(mo));
                }
            }
            *reinterpret_cast<float2*>(Cp + (size_t)r0 * kCh + col)       = make_float2(v0, v1);
            *reinterpret_cast<float2*>(Cp + (size_t)(r0 + 8) * kCh + col) = make_float2(v2, v3);
        }
    }
    if (EPI != 1) {
        __syncthreads();
        if (tid < BN) {
            unsigned* buf = (EPI == 0) ? g_maxxe : g_maxy;
            atomicMax(&buf[(m0 >> 13) * kCh + n0 + tid], red[tid]);
        }
    }
}

// g_xe (B,L,C) -> g_xeT (B,C,L)
__global__ __launch_bounds__(256) void transpose_kernel() {
    __shared__ float tile[32][33];
    int b = blockIdx.z, l0 = blockIdx.x * 32, c0 = blockIdx.y * 32;
    int tx = threadIdx.x, ty = threadIdx.y;
    const float* in  = g_xe  + (size_t)b * kSeq * kCh;
    float*       out = g_xeT + (size_t)b * kCh * kSeq;
#pragma unroll
    for (int i = 0; i < 4; ++i)
        tile[ty + i * 8][tx] = in[(size_t)(l0 + ty + i * 8) * kCh + c0 + tx];
    __syncthreads();
#pragma unroll
    for (int i = 0; i < 4; ++i)
        out[(size_t)(c0 + ty + i * 8) * kSeq + l0 + tx] = tile[tx][ty + i * 8];
}

// Mixed-radix Stockham: 6 radix-4 stages + 1 radix-2, autosorting ping-pong.
template <bool INV>
__device__ __forceinline__ void fft_stages(float2*& src, float2*& dst, const float2* tw) {
    int nn = kN2, s = 1, ls = 0;
    while (nn > 2) {
        int nq = nn >> 2;
        for (int t = threadIdx.x; t < 2048; t += 512) {
            int q = t & (s - 1), p = t >> ls;
            float2 a0 = src[q + (p << ls)];
            float2 a1 = src[q + ((p + nq) << ls)];
            float2 a2 = src[q + ((p + 2 * nq) << ls)];
            float2 a3 = src[q + ((p + 3 * nq) << ls)];
            float2 t0 = cadd(a0, a2), t1 = csub(a0, a2);
            float2 t2 = cadd(a1, a3), t3 = csub(a1, a3);
            float2 b0 = cadd(t0, t2), b2 = csub(t0, t2);
            float2 b1, b3;
            if (!INV) {
                b1 = make_float2(t1.x + t3.y, t1.y - t3.x);
                b3 = make_float2(t1.x - t3.y, t1.y + t3.x);
            } else {
                b1 = make_float2(t1.x - t3.y, t1.y + t3.x);
                b3 = make_float2(t1.x + t3.y, t1.y - t3.x);
            }
            float2 w1 = tw[p << ls];
            if (INV) w1.y = -w1.y;
            float2 w2 = cmul(w1, w1), w3 = cmul(w2, w1);
            int o = q + (p << (ls + 2));
            dst[o]         = b0;
            dst[o + s]     = cmul(w1, b1);
            dst[o + 2 * s] = cmul(w2, b2);
            dst[o + 3 * s] = cmul(w3, b3);
        }
        __syncthreads();
        float2* tp = src; src = dst; dst = tp;
        nn >>= 2; s <<= 2; ls += 2;
    }
    for (int t = threadIdx.x; t < 4096; t += 512) {
        float2 a = src[t], b = src[t + 4096];
        dst[t]        = cadd(a, b);
        dst[t + 4096] = csub(a, b);
    }
    __syncthreads();
    float2* tp = src; src = dst; dst = tp;
}

// One CTA per (b,c) row: real-16384 causal conv via packed complex-8192 FFT.
// In place on g_xeT.
__global__ __launch_bounds__(512, 1) void fftconv_kernel() {
    extern __shared__ float2 sm[];
    float2* tw8  = sm;
    float2* tw16 = sm + 4096;
    float2* b0   = sm + 8193;
    float2* b1   = b0 + kN2;
    for (int i = threadIdx.x; i < 4097; i += 512) {
        if (i < 4096) tw8[i] = g_tw8[i];
        tw16[i] = g_tw16[i];
    }
    const int r = blockIdx.x, c = r & (kCh - 1);
    float2* row2 = reinterpret_cast<float2*>(g_xeT + (size_t)r * kSeq);
    for (int n = threadIdx.x; n < kN2; n += 512)
        b0[n] = (n < 4096) ? row2[n] : make_float2(0.f, 0.f);
    __syncthreads();

    float2 *src = b0, *dst = b1;
    fft_stages<false>(src, dst, tw8);

    const float2* Kfc = g_Kf + (size_t)c * kNF;
    for (int k = threadIdx.x; k <= 4096; k += 512) {
        int j = (kN2 - k) & (kN2 - 1);
        float2 Zk = src[k], Zj = src[j];
        float2 E = make_float2(0.5f * (Zk.x + Zj.x), 0.5f * (Zk.y - Zj.y));
        float2 O = make_float2(0.5f * (Zk.y + Zj.y), -0.5f * (Zk.x - Zj.x));
        float2 w = tw16[k];
        float2 wO = cmul(w, O);
        float2 Xk = make_float2(E.x + wO.x, E.y + wO.y);
        float2 Xj = make_float2(E.x - wO.x, -(E.y - wO.y));
        float2 Yk = cmul(Xk, Kfc[k]);
        float2 Yj = cmul(Xj, Kfc[kN2 - k]);
        float2 Ey = make_float2(0.5f * (Yk.x + Yj.x), 0.5f * (Yk.y - Yj.y));
        float2 Dy = make_float2(0.5f * (Yk.x - Yj.x), 0.5f * (Yk.y + Yj.y));
        float2 Oy = cmul(make_float2(w.x, -w.y), Dy);
        dst[k] = make_float2(Ey.x - Oy.y, Ey.y + Oy.x);
        if (k >= 1 && k < 4096) {
            float2 Em = make_float2(0.5f * (Yj.x + Yk.x), 0.5f * (Yj.y - Yk.y));
            float2 Dm = make_float2(0.5f * (Yj.x - Yk.x), 0.5f * (Yj.y + Yk.y));
            float2 Om = cmul(make_float2(-w.x, -w.y), Dm);
            dst[kN2 - k] = make_float2(Em.x - Om.y, Em.y + Om.x);
        }
    }
    __syncthreads();
    { float2* tp = src; src = dst; dst = tp; }

    fft_stages<true>(src, dst, tw8);

    for (int n = threadIdx.x; n < 4096; n += 512) row2[n] = src[n];
}

// y1 = gelu(h1 + h0*xe): transpose h1T (in g_xeT) back to (B,L,C), fuse gelu.
__global__ __launch_bounds__(256) void y1merge_kernel(const float* __restrict__ h0) {
    __shared__ float tile[32][33];
    int b = blockIdx.z, l0 = blockIdx.x * 32, c0 = blockIdx.y * 32;
    int tx = threadIdx.x, ty = threadIdx.y;
    const float* h1T = g_xeT + (size_t)b * kCh * kSeq;
    float h0v = h0[0];
#pragma unroll
    for (int i = 0; i < 4; ++i)
        tile[ty + i * 8][tx] = h1T[(size_t)(c0 + ty + i * 8) * kSeq + l0 + tx];
    __syncthreads();
#pragma unroll
    for (int i = 0; i < 4; ++i) {
        int l = l0 + ty + i * 8;
        size_t idx = ((size_t)b * kSeq + l) * kCh + c0 + tx;
        g_y1[idx] = gelu_exact(tile[tx][ty + i * 8] + h0v * g_xe[idx]);
    }
}

// LayerNorm over channels, in place on g_y2. One warp per row.
__global__ __launch_bounds__(256) void ln_kernel(const float* __restrict__ gamma,
                                                 const float* __restrict__ beta) {
    int warp = threadIdx.x >> 5, lane = threadIdx.x & 31;
    size_t row = (size_t)blockIdx.x * 8 + warp;
    float4* p = reinterpret_cast<float4*>(g_y2 + row * kCh);
    float4 v0 = p[lane], v1 = p[lane + 32];
    float s = v0.x + v0.y + v0.z + v0.w + v1.x + v1.y + v1.z + v1.w;
    float q = v0.x * v0.x + v0.y * v0.y + v0.z * v0.z + v0.w * v0.w
            + v1.x * v1.x + v1.y * v1.y + v1.z * v1.z + v1.w * v1.w;
#pragma unroll
    for (int o = 16; o; o >>= 1) {
        s += __shfl_xor_sync(0xffffffffu, s, o);
        q += __shfl_xor_sync(0xffffffffu, q, o);
    }
    float mu = s * (1.f / 256.f);
    float rstd = rsqrtf(q * (1.f / 256.f) - mu * mu + 1e-5f);
    const float4* g4 = reinterpret_cast<const float4*>(gamma);
    const float4* e4 = reinterpret_cast<const float4*>(beta);
    float4 g0 = g4[lane], g1 = g4[lane + 32], e0 = e4[lane], e1 = e4[lane + 32];
    v0.x = (v0.x - mu) * rstd * g0.x + e0.x; v0.y = (v0.y - mu) * rstd * g0.y + e0.y;
    v0.z = (v0.z - mu) * rstd * g0.z + e0.z; v0.w = (v0.w - mu) * rstd * g0.w + e0.w;
    v1.x = (v1.x - mu) * rstd * g1.x + e1.x; v1.y = (v1.y - mu) * rstd * g1.y + e1.y;
    v1.z = (v1.z - mu) * rstd * g1.z + e1.z; v1.w = (v1.w - mu) * rstd * g1.w + e1.w;
    p[lane] = v0; p[lane + 32] = v1;
}

__global__ void hout_kernel(float* __restrict__ h) {
    int i = blockIdx.x * 256 + threadIdx.x;
    if (i < kB * kCh)
        h[i] = __uint_as_float(g_maxy[i]) / (__uint_as_float(g_maxxe[i]) + 1e-6f);
}

extern "C" void kernel_launch(void* const* d_in, const int* in_sizes, int n_in,
                              void* d_out, int out_size) {
    const float* x     = (const float*)d_in[0];
    const float* A     = (const float*)d_in[1];
    const float* Bp    = (const float*)d_in[2];
    const float* h0    = (const float*)d_in[3];
    const float* W_enc = (const float*)d_in[4];
    const float* b_enc = (const float*)d_in[5];
    const float* W_fc  = (const float*)d_in[6];
    const float* b_fc  = (const float*)d_in[7];
    const float* gamma = (const float*)d_in[8];
    const float* beta  = (const float*)d_in[9];
    const float* W_dec = (const float*)d_in[10];
    const float* b_dec = (const float*)d_in[11];
    float* out = (float*)d_out;

    const int kSmemFFT = 24577 * 8;   // 196616 B dynamic SMEM
    cudaFuncSetAttribute(fftconv_kernel, cudaFuncAttributeMaxDynamicSharedMemorySize, kSmemFFT);

    zero_kernel<<<8, 256>>>();
    twiddle_kernel<<<17, 256>>>();
    wsplit_kernel<<<dim3(kCh * kCh / 256, 3), 256>>>(W_enc, W_fc, W_dec);
    kfgen_kernel<<<dim3(33, kCh), 256>>>(A, Bp);
    gemm_kernel<0><<<dim3(kM / 128, 2), 256>>>(x, b_enc, nullptr);
    transpose_kernel<<<dim3(kSeq / 32, kCh / 32, kB), dim3(32, 8)>>>();
    fftconv_kernel<<<kB * kCh, 512, kSmemFFT>>>();
    y1merge_kernel<<<dim3(kSeq / 32, kCh / 32, kB), dim3(32, 8)>>>(h0);
    gemm_kernel<1><<<dim3(kM / 128, 2), 256>>>(nullptr, b_fc, nullptr);
    ln_kernel<<<kM / 8, 256>>>(gamma, beta);
    gemm_kernel<2><<<dim3(kM / 128, 2), 256>>>(nullptr, b_dec, out);
    hout_kernel<<<8, 256>>>(out + (size_t)kM * kCh);
}

// round 7
// speedup vs baseline: 1.6562x; 1.0827x over previous
#include <cuda_runtime.h>
#include <cuda_bf16.h>

constexpr int kB = 8, kSeq = 8192, kCh = 256;
constexpr int kM  = kB * kSeq;          // 65536
constexpr int kN2 = 8192;               // complex FFT size (real 16384)
constexpr int kNF = 8193;               // rfft bins of 16384

__device__ __align__(128) float  g_xe [kM * kCh];   // (B,L,C)
__device__ __align__(128) float  g_xeT[kM * kCh];   // (B,C,L); FFT in place -> h1T
__device__ __align__(128) float  g_y1 [kM * kCh];   // (B,L,C)
__device__ __align__(128) float  g_y2 [kM * kCh];   // (B,L,C)
__device__ __align__(128) float2 g_Kf [(size_t)kCh * kNF];
__device__ __align__(128) __nv_bfloat16 g_Wh[3 * kCh * kCh];
__device__ __align__(128) __nv_bfloat16 g_Wl[3 * kCh * kCh];
__device__ float2 g_tw8 [4096];
__device__ float2 g_tw16[4097];
__device__ unsigned g_maxxe[kB * kCh];
__device__ unsigned g_maxy [kB * kCh];

__device__ __forceinline__ float2 cmul(float2 a, float2 b) {
    return make_float2(a.x * b.x - a.y * b.y, a.x * b.y + a.y * b.x);
}
__device__ __forceinline__ float2 cadd(float2 a, float2 b) {
    return make_float2(a.x + b.x, a.y + b.y);
}
__device__ __forceinline__ float2 csub(float2 a, float2 b) {
    return make_float2(a.x - b.x, a.y - b.y);
}
__device__ __forceinline__ float gelu_exact(float v) {
    return 0.5f * v * (1.0f + erff(v * 0.7071067811865476f));
}
__device__ __forceinline__ void ldsm4(unsigned* r, const void* p) {
    unsigned addr = (unsigned)__cvta_generic_to_shared(p);
    asm volatile("ldmatrix.sync.aligned.m8n8.x4.shared.b16 {%0,%1,%2,%3}, [%4];"
                 : "=r"(r[0]), "=r"(r[1]), "=r"(r[2]), "=r"(r[3]) : "r"(addr));
}
__device__ __forceinline__ void mma16816(float* d, const unsigned* a, const unsigned* b) {
    asm volatile("mma.sync.aligned.m16n8k16.row.col.f32.bf16.bf16.f32 "
                 "{%0,%1,%2,%3}, {%4,%5,%6,%7}, {%8,%9}, {%0,%1,%2,%3};"
                 : "+f"(d[0]), "+f"(d[1]), "+f"(d[2]), "+f"(d[3])
                 : "r"(a[0]), "r"(a[1]), "r"(a[2]), "r"(a[3]), "r"(b[0]), "r"(b[1]));
}

__global__ void zero_kernel() {
    int i = blockIdx.x * 256 + threadIdx.x;
    if (i < kB * kCh) { g_maxxe[i] = 0u; g_maxy[i] = 0u; }
}

__global__ void twiddle_kernel() {
    int i = blockIdx.x * 256 + threadIdx.x;
    float s, c;
    if (i < 4096) { sincospif(-2.0f * i / 8192.0f,  &s, &c); g_tw8 [i] = make_float2(c, s); }
    if (i < 4097) { sincospif(-2.0f * i / 16384.0f, &s, &c); g_tw16[i] = make_float2(c, s); }
}

// Split the 3 weight matrices into hi/lo bf16 pairs (x = hi + lo exactly to 2^-18).
__global__ void wsplit_kernel(const float* __restrict__ We, const float* __restrict__ Wf,
                              const float* __restrict__ Wd) {
    int i = blockIdx.x * 256 + threadIdx.x;
    const float* src = (blockIdx.y == 0) ? We : (blockIdx.y == 1 ? Wf : Wd);
    float v = src[i];
    __nv_bfloat16 h = __float2bfloat16(v);
    g_Wh[blockIdx.y * kCh * kCh + i] = h;
    g_Wl[blockIdx.y * kCh * kCh + i] = __float2bfloat16(v - __bfloat162float(h));
}

// Kf[c][k] = B(w)/A(w)/8192, w = e^{-2*pi*i*k/16384}. (IIR tail beyond n=8192
// underflows fp32, so this equals the reference's FFT-generated kernel.)
// Even/odd Horner: P(w) = Pe(w^2) + w*Po(w^2), 4 independent chains for ILP.
// a coefficients: a_0 = 1, a_j = sA[j-1] (j=1..64).
//   even e_i = a_{2i}:  e_0 = 1, e_i = sA[2i-1], i=1..32
//   odd  o_i = a_{2i+1} = sA[2i], i=0..31
// b coefficients: b_j = sB[j] (j=0..63).
//   even be_i = sB[2i], odd bo_i = sB[2i+1], i=0..31
__global__ __launch_bounds__(256) void kfgen_kernel(const float* __restrict__ A,
                                                    const float* __restrict__ Bp) {
    __shared__ float sA[64], sB[64];
    int c = blockIdx.y;
    if (threadIdx.x < 64)       sA[threadIdx.x]      = A [c * 64 + threadIdx.x];
    else if (threadIdx.x < 128) sB[threadIdx.x - 64] = Bp[c * 64 + threadIdx.x - 64];
    __syncthreads();
    int k = blockIdx.x * 256 + threadIdx.x;
    if (k >= kNF) return;
    float sv, cv;
    sincospif(-(float)k / 8192.0f, &sv, &cv);
    float2 w  = make_float2(cv, sv);
    float2 w2 = cmul(w, w);
    float2 ae = make_float2(sA[63], 0.f);            // e_32
    float2 ao = make_float2(sA[62], 0.f);            // o_31
    float2 be = make_float2(sB[62], 0.f);            // be_31
    float2 bo = make_float2(sB[63], 0.f);            // bo_31
#pragma unroll 4
    for (int i = 31; i >= 1; --i) {
        ae = cmul(ae, w2); ae.x += sA[2 * i - 1];    // e_i
        ao = cmul(ao, w2); ao.x += sA[2 * i - 2];    // o_{i-1}
        be = cmul(be, w2); be.x += sB[2 * i - 2];    // be_{i-1}
        bo = cmul(bo, w2); bo.x += sB[2 * i - 1];    // bo_{i-1}
    }
    ae = cmul(ae, w2); ae.x += 1.0f;                 // e_0 = 1
    float2 av = cadd(ae, cmul(w, ao));
    float2 bv = cadd(be, cmul(w, bo));
    float scl = (1.0f / 8192.0f) / (av.x * av.x + av.y * av.y);
    g_Kf[(size_t)c * kNF + k] = make_float2((bv.x * av.x + bv.y * av.y) * scl,
                                            (bv.y * av.x - bv.x * av.y) * scl);
}

// ---------------------------------------------------------------------------
// Tensor-core GEMM: C[M,256] = epi(A[M,256] @ W[256,256]^T + bias)
// 3-pass bf16 split: D = Ah*Wh + Ah*Wl + Al*Wh  (error ~2^-17).
// EPI 0: encode (x -> g_xe, colmax -> g_maxxe)
// EPI 1: fc     (g_y1 -> g_y2, v = gelu(v) + xe skip)
// EPI 2: decode (g_y2 -> d_out, colmax -> g_maxy)
template <int EPI>
__global__ __launch_bounds__(256, 2) void gemm_kernel(const float* __restrict__ Ain,
                                                      const float* __restrict__ bias,
                                                      float* __restrict__ Cout) {
    constexpr int BM = 128, BN = 128, BK = 32, LDS = 40;   // 80B row stride: conflict-free
    __shared__ __nv_bfloat16 Ah[BM][LDS], Al[BM][LDS];
    __shared__ __nv_bfloat16 Bh[BN][LDS], Bl[BN][LDS];
    __shared__ unsigned red[BN];
    const float* Ap = (EPI == 1) ? g_y1 : (EPI == 2 ? g_y2 : Ain);
    float*       Cp = (EPI == 0) ? g_xe : (EPI == 1 ? g_y2 : Cout);
    const __nv_bfloat16* Whp = g_Wh + EPI * kCh * kCh;
    const __nv_bfloat16* Wlp = g_Wl + EPI * kCh * kCh;
    const int m0 = blockIdx.x * BM, n0 = blockIdx.y * BN;
    const int tid = threadIdx.x, lane = tid & 31, warp = tid >> 5;
    const int wr = warp >> 1, wc = warp & 1;      // 4x2 warp grid, warp tile 32x64

    if (EPI != 1 && tid < BN) red[tid] = 0u;

    float acc[2][8][4];
#pragma unroll
    for (int mt = 0; mt < 2; ++mt)
#pragma unroll
        for (int nt = 0; nt < 8; ++nt)
#pragma unroll
            for (int r = 0; r < 4; ++r) acc[mt][nt][r] = 0.f;

    for (int kt = 0; kt < kCh; kt += BK) {
        // A: load fp32 128x32, split to hi/lo bf16
#pragma unroll
        for (int u = 0; u < 4; ++u) {
            int idx = u * 256 + tid;               // 0..1023 float4s
            int row = idx >> 3, c4 = (idx & 7) * 4;
            float4 v = *reinterpret_cast<const float4*>(
                Ap + (size_t)(m0 + row) * kCh + kt + c4);
            __nv_bfloat162 h01 = __floats2bfloat162_rn(v.x, v.y);
            __nv_bfloat162 h23 = __floats2bfloat162_rn(v.z, v.w);
            __nv_bfloat162 l01 = __floats2bfloat162_rn(v.x - __low2float(h01),
                                                       v.y - __high2float(h01));
            __nv_bfloat162 l23 = __floats2bfloat162_rn(v.z - __low2float(h23),
                                                       v.w - __high2float(h23));
            *reinterpret_cast<uint2*>(&Ah[row][c4]) =
                make_uint2(*reinterpret_cast<unsigned*>(&h01), *reinterpret_cast<unsigned*>(&h23));
            *reinterpret_cast<uint2*>(&Al[row][c4]) =
                make_uint2(*reinterpret_cast<unsigned*>(&l01), *reinterpret_cast<unsigned*>(&l23));
        }
        // W: copy pre-split bf16 128x32 (hi and lo)
#pragma unroll
        for (int u = 0; u < 2; ++u) {
            int idx = u * 256 + tid;               // 0..511 uint4s
            int row = idx >> 2, c8 = (idx & 3) * 8;
            *reinterpret_cast<uint4*>(&Bh[row][c8]) =
                *reinterpret_cast<const uint4*>(Whp + (size_t)(n0 + row) * kCh + kt + c8);
            *reinterpret_cast<uint4*>(&Bl[row][c8]) =
                *reinterpret_cast<const uint4*>(Wlp + (size_t)(n0 + row) * kCh + kt + c8);
        }
        __syncthreads();
#pragma unroll
        for (int ks = 0; ks < 2; ++ks) {
            const int kb = ks * 16;
            unsigned ah[2][4], al[2][4];
#pragma unroll
            for (int mt = 0; mt < 2; ++mt) {
                int arow = wr * 32 + mt * 16 + (lane & 15);
                int koff = kb + ((lane >> 4) << 3);
                ldsm4(ah[mt], &Ah[arow][koff]);
                ldsm4(al[mt], &Al[arow][koff]);
            }
#pragma unroll
            for (int g = 0; g < 4; ++g) {
                int nrow = wc * 64 + g * 16 + (lane & 7) + ((lane >> 4) << 3);
                int koff = kb + (((lane >> 3) & 1) << 3);
                unsigned bh[4], bl[4];
                ldsm4(bh, &Bh[nrow][koff]);
                ldsm4(bl, &Bl[nrow][koff]);
#pragma unroll
                for (int mt = 0; mt < 2; ++mt) {
                    mma16816(acc[mt][2 * g],     ah[mt], bh);
                    mma16816(acc[mt][2 * g],     ah[mt], bl);
                    mma16816(acc[mt][2 * g],     al[mt], bh);
                    mma16816(acc[mt][2 * g + 1], ah[mt], bh + 2);
                    mma16816(acc[mt][2 * g + 1], ah[mt], bl + 2);
                    mma16816(acc[mt][2 * g + 1], al[mt], bh + 2);
                }
            }
        }
        __syncthreads();
    }

    // Epilogue: d0,d1 -> (row, col..col+1); d2,d3 -> (row+8, ...)
#pragma unroll
    for (int mt = 0; mt < 2; ++mt) {
        int r0 = m0 + wr * 32 + mt * 16 + (lane >> 2);
#pragma unroll
        for (int nt = 0; nt < 8; ++nt) {
            int col = n0 + wc * 64 + nt * 8 + (lane & 3) * 2;
            float* c = acc[mt][nt];
            float2 bv = *reinterpret_cast<const float2*>(bias + col);
            float v0 = c[0] + bv.x, v1 = c[1] + bv.y;
            float v2 = c[2] + bv.x, v3 = c[3] + bv.y;
            if (EPI == 1) {
                float2 s0 = *reinterpret_cast<const float2*>(g_xe + (size_t)r0 * kCh + col);
                float2 s1 = *reinterpret_cast<const float2*>(g_xe + (size_t)(r0 + 8) * kCh + col);
                v0 = gelu_exact(v0) + s0.x; v1 = gelu_exact(v1) + s0.y;
                v2 = gelu_exact(v2) + s1.x; v3 = gelu_exact(v3) + s1.y;
            } else {
                float me = fmaxf(fabsf(v0), fabsf(v2));
                float mo = fmaxf(fabsf(v1), fabsf(v3));
#pragma unroll
                for (int o = 4; o < 32; o <<= 1) {
                    me = fmaxf(me, __shfl_xor_sync(0xffffffffu, me, o));
                    mo = fmaxf(mo, __shfl_xor_sync(0xffffffffu, mo, o));
                }
                if (lane < 4) {
                    atomicMax(&red[col - n0],     __float_as_uint(me));
                    atomicMax(&red[col - n0 + 1], __float_as_uint(mo));
                }
            }
            *reinterpret_cast<float2*>(Cp + (size_t)r0 * kCh + col)       = make_float2(v0, v1);
            *reinterpret_cast<float2*>(Cp + (size_t)(r0 + 8) * kCh + col) = make_float2(v2, v3);
        }
    }
    if (EPI != 1) {
        __syncthreads();
        if (tid < BN) {
            unsigned* buf = (EPI == 0) ? g_maxxe : g_maxy;
            atomicMax(&buf[(m0 >> 13) * kCh + n0 + tid], red[tid]);
        }
    }
}

// g_xe (B,L,C) -> g_xeT (B,C,L)
__global__ __launch_bounds__(256) void transpose_kernel() {
    __shared__ float tile[32][33];
    int b = blockIdx.z, l0 = blockIdx.x * 32, c0 = blockIdx.y * 32;
    int tx = threadIdx.x, ty = threadIdx.y;
    const float* in  = g_xe  + (size_t)b * kSeq * kCh;
    float*       out = g_xeT + (size_t)b * kCh * kSeq;
#pragma unroll
    for (int i = 0; i < 4; ++i)
        tile[ty + i * 8][tx] = in[(size_t)(l0 + ty + i * 8) * kCh + c0 + tx];
    __syncthreads();
#pragma unroll
    for (int i = 0; i < 4; ++i)
        out[(size_t)(c0 + ty + i * 8) * kSeq + l0 + tx] = tile[tx][ty + i * 8];
}

// Mixed-radix Stockham: 6 radix-4 stages + 1 radix-2, autosorting ping-pong.
template <bool INV>
__device__ __forceinline__ void fft_stages(float2*& src, float2*& dst, const float2* tw) {
    int nn = kN2, s = 1, ls = 0;
    while (nn > 2) {
        int nq = nn >> 2;
        for (int t = threadIdx.x; t < 2048; t += 1024) {
            int q = t & (s - 1), p = t >> ls;
            float2 a0 = src[q + (p << ls)];
            float2 a1 = src[q + ((p + nq) << ls)];
            float2 a2 = src[q + ((p + 2 * nq) << ls)];
            float2 a3 = src[q + ((p + 3 * nq) << ls)];
            float2 t0 = cadd(a0, a2), t1 = csub(a0, a2);
            float2 t2 = cadd(a1, a3), t3 = csub(a1, a3);
            float2 b0 = cadd(t0, t2), b2 = csub(t0, t2);
            float2 b1, b3;
            if (!INV) {
                b1 = make_float2(t1.x + t3.y, t1.y - t3.x);
                b3 = make_float2(t1.x - t3.y, t1.y + t3.x);
            } else {
                b1 = make_float2(t1.x - t3.y, t1.y + t3.x);
                b3 = make_float2(t1.x + t3.y, t1.y - t3.x);
            }
            float2 w1 = tw[p << ls];
            if (INV) w1.y = -w1.y;
            float2 w2 = cmul(w1, w1), w3 = cmul(w2, w1);
            int o = q + (p << (ls + 2));
            dst[o]         = b0;
            dst[o + s]     = cmul(w1, b1);
            dst[o + 2 * s] = cmul(w2, b2);
            dst[o + 3 * s] = cmul(w3, b3);
        }
        __syncthreads();
        float2* tp = src; src = dst; dst = tp;
        nn >>= 2; s <<= 2; ls += 2;
    }
    for (int t = threadIdx.x; t < 4096; t += 1024) {
        float2 a = src[t], b = src[t + 4096];
        dst[t]        = cadd(a, b);
        dst[t + 4096] = csub(a, b);
    }
    __syncthreads();
    float2* tp = src; src = dst; dst = tp;
}

// One CTA per (b,c) row: real-16384 causal conv via packed complex-8192 FFT.
// In place on g_xeT.
__global__ __launch_bounds__(1024, 1) void fftconv_kernel() {
    extern __shared__ float2 sm[];
    float2* tw8  = sm;
    float2* tw16 = sm + 4096;
    float2* b0   = sm + 8193;
    float2* b1   = b0 + kN2;
    for (int i = threadIdx.x; i < 4097; i += 1024) {
        if (i < 4096) tw8[i] = g_tw8[i];
        tw16[i] = g_tw16[i];
    }
    const int r = blockIdx.x, c = r & (kCh - 1);
    float2* row2 = reinterpret_cast<float2*>(g_xeT + (size_t)r * kSeq);
    for (int n = threadIdx.x; n < kN2; n += 1024)
        b0[n] = (n < 4096) ? row2[n] : make_float2(0.f, 0.f);
    __syncthreads();

    float2 *src = b0, *dst = b1;
    fft_stages<false>(src, dst, tw8);

    const float2* Kfc = g_Kf + (size_t)c * kNF;
    for (int k = threadIdx.x; k <= 4096; k += 1024) {
        int j = (kN2 - k) & (kN2 - 1);
        float2 Zk = src[k], Zj = src[j];
        float2 E = make_float2(0.5f * (Zk.x + Zj.x), 0.5f * (Zk.y - Zj.y));
        float2 O = make_float2(0.5f * (Zk.y + Zj.y), -0.5f * (Zk.x - Zj.x));
        float2 w = tw16[k];
        float2 wO = cmul(w, O);
        float2 Xk = make_float2(E.x + wO.x, E.y + wO.y);
        float2 Xj = make_float2(E.x - wO.x, -(E.y - wO.y));
        float2 Yk = cmul(Xk, Kfc[k]);
        float2 Yj = cmul(Xj, Kfc[kN2 - k]);
        float2 Ey = make_float2(0.5f * (Yk.x + Yj.x), 0.5f * (Yk.y - Yj.y));
        float2 Dy = make_float2(0.5f * (Yk.x - Yj.x), 0.5f * (Yk.y + Yj.y));
        float2 Oy = cmul(make_float2(w.x, -w.y), Dy);
        dst[k] = make_float2(Ey.x - Oy.y, Ey.y + Oy.x);
        if (k >= 1 && k < 4096) {
            float2 Em = make_float2(0.5f * (Yj.x + Yk.x), 0.5f * (Yj.y - Yk.y));
            float2 Dm = make_float2(0.5f * (Yj.x - Yk.x), 0.5f * (Yj.y + Yk.y));
            float2 Om = cmul(make_float2(-w.x, -w.y), Dm);
            dst[kN2 - k] = make_float2(Em.x - Om.y, Em.y + Om.x);
        }
    }
    __syncthreads();
    { float2* tp = src; src = dst; dst = tp; }

    fft_stages<true>(src, dst, tw8);

    for (int n = threadIdx.x; n < 4096; n += 1024) row2[n] = src[n];
}

// y1 = gelu(h1 + h0*xe): transpose h1T (in g_xeT) back to (B,L,C), fuse gelu.
__global__ __launch_bounds__(256) void y1merge_kernel(const float* __restrict__ h0) {
    __shared__ float tile[32][33];
    int b = blockIdx.z, l0 = blockIdx.x * 32, c0 = blockIdx.y * 32;
    int tx = threadIdx.x, ty = threadIdx.y;
    const float* h1T = g_xeT + (size_t)b * kCh * kSeq;
    float h0v = h0[0];
#pragma unroll
    for (int i = 0; i < 4; ++i)
        tile[ty + i * 8][tx] = h1T[(size_t)(c0 + ty + i * 8) * kSeq + l0 + tx];
    __syncthreads();
#pragma unroll
    for (int i = 0; i < 4; ++i) {
        int l = l0 + ty + i * 8;
        size_t idx = ((size_t)b * kSeq + l) * kCh + c0 + tx;
        g_y1[idx] = gelu_exact(tile[tx][ty + i * 8] + h0v * g_xe[idx]);
    }
}

// LayerNorm over channels, in place on g_y2. One warp per row.
__global__ __launch_bounds__(256) void ln_kernel(const float* __restrict__ gamma,
                                                 const float* __restrict__ beta) {
    int warp = threadIdx.x >> 5, lane = threadIdx.x & 31;
    size_t row = (size_t)blockIdx.x * 8 + warp;
    float4* p = reinterpret_cast<float4*>(g_y2 + row * kCh);
    float4 v0 = p[lane], v1 = p[lane + 32];
    float s = v0.x + v0.y + v0.z + v0.w + v1.x + v1.y + v1.z + v1.w;
    float q = v0.x * v0.x + v0.y * v0.y + v0.z * v0.z + v0.w * v0.w
            + v1.x * v1.x + v1.y * v1.y + v1.z * v1.z + v1.w * v1.w;
#pragma unroll
    for (int o = 16; o; o >>= 1) {
        s += __shfl_xor_sync(0xffffffffu, s, o);
        q += __shfl_xor_sync(0xffffffffu, q, o);
    }
    float mu = s * (1.f / 256.f);
    float rstd = rsqrtf(q * (1.f / 256.f) - mu * mu + 1e-5f);
    const float4* g4 = reinterpret_cast<const float4*>(gamma);
    const float4* e4 = reinterpret_cast<const float4*>(beta);
    float4 g0 = g4[lane], g1 = g4[lane + 32], e0 = e4[lane], e1 = e4[lane + 32];
    v0.x = (v0.x - mu) * rstd * g0.x + e0.x; v0.y = (v0.y - mu) * rstd * g0.y + e0.y;
    v0.z = (v0.z - mu) * rstd * g0.z + e0.z; v0.w = (v0.w - mu) * rstd * g0.w + e0.w;
    v1.x = (v1.x - mu) * rstd * g1.x + e1.x; v1.y = (v1.y - mu) * rstd * g1.y + e1.y;
    v1.z = (v1.z - mu) * rstd * g1.z + e1.z; v1.w = (v1.w - mu) * rstd * g1.w + e1.w;
    p[lane] = v0; p[lane + 32] = v1;
}

__global__ void hout_kernel(float* __restrict__ h) {
    int i = blockIdx.x * 256 + threadIdx.x;
    if (i < kB * kCh)
        h[i] = __uint_as_float(g_maxy[i]) / (__uint_as_float(g_maxxe[i]) + 1e-6f);
}

extern "C" void kernel_launch(void* const* d_in, const int* in_sizes, int n_in,
                              void* d_out, int out_size) {
    const float* x     = (const float*)d_in[0];
    const float* A     = (const float*)d_in[1];
    const float* Bp    = (const float*)d_in[2];
    const float* h0    = (const float*)d_in[3];
    const float* W_enc = (const float*)d_in[4];
    const float* b_enc = (const float*)d_in[5];
    const float* W_fc  = (const float*)d_in[6];
    const float* b_fc  = (const float*)d_in[7];
    const float* gamma = (const float*)d_in[8];
    const float* beta  = (const float*)d_in[9];
    const float* W_dec = (const float*)d_in[10];
    const float* b_dec = (const float*)d_in[11];
    float* out = (float*)d_out;

    const int kSmemFFT = 24577 * 8;   // 196616 B dynamic SMEM
    cudaFuncSetAttribute(fftconv_kernel, cudaFuncAttributeMaxDynamicSharedMemorySize, kSmemFFT);

    zero_kernel<<<8, 256>>>();
    twiddle_kernel<<<17, 256>>>();
    wsplit_kernel<<<dim3(kCh * kCh / 256, 3), 256>>>(W_enc, W_fc, W_dec);
    kfgen_kernel<<<dim3(33, kCh), 256>>>(A, Bp);
    gemm_kernel<0><<<dim3(kM / 128, 2), 256>>>(x, b_enc, nullptr);
    transpose_kernel<<<dim3(kSeq / 32, kCh / 32, kB), dim3(32, 8)>>>();
    fftconv_kernel<<<kB * kCh, 1024, kSmemFFT>>>();
    y1merge_kernel<<<dim3(kSeq / 32, kCh / 32, kB), dim3(32, 8)>>>(h0);
    gemm_kernel<1><<<dim3(kM / 128, 2), 256>>>(nullptr, b_fc, nullptr);
    ln_kernel<<<kM / 8, 256>>>(gamma, beta);
    gemm_kernel<2><<<dim3(kM / 128, 2), 256>>>(nullptr, b_dec, out);
    hout_kernel<<<8, 256>>>(out + (size_t)kM * kCh);
}

// round 10
// speedup vs baseline: 1.7068x; 1.0305x over previous
#include <cuda_runtime.h>
#include <cuda_bf16.h>

constexpr int kB = 8, kSeq = 8192, kCh = 256;
constexpr int kM  = kB * kSeq;          // 65536
constexpr int kN2 = 8192;               // complex FFT size (real 16384)
constexpr int kNF = 8193;               // rfft bins of 16384

__device__ __align__(128) float  g_xe [kM * kCh];   // (B,L,C)
__device__ __align__(128) float  g_xeT[kM * kCh];   // (B,C,L); FFT in place -> h1T
__device__ __align__(128) float  g_y1 [kM * kCh];   // (B,L,C)
__device__ __align__(128) float  g_y2 [kM * kCh];   // (B,L,C)
__device__ __align__(128) float2 g_Kf [(size_t)kCh * kNF];
__device__ __align__(128) __nv_bfloat16 g_Wh[3 * kCh * kCh];
__device__ __align__(128) __nv_bfloat16 g_Wl[3 * kCh * kCh];
__device__ float2 g_tw8 [4096];
__device__ float2 g_tw16[4097];
__device__ unsigned g_maxxe[kB * kCh];
__device__ unsigned g_maxy [kB * kCh];

__device__ __forceinline__ float2 cmul(float2 a, float2 b) {
    return make_float2(a.x * b.x - a.y * b.y, a.x * b.y + a.y * b.x);
}
__device__ __forceinline__ float2 cadd(float2 a, float2 b) {
    return make_float2(a.x + b.x, a.y + b.y);
}
__device__ __forceinline__ float2 csub(float2 a, float2 b) {
    return make_float2(a.x - b.x, a.y - b.y);
}
__device__ __forceinline__ float gelu_exact(float v) {
    return 0.5f * v * (1.0f + erff(v * 0.7071067811865476f));
}
__device__ __forceinline__ void ldsm4(unsigned* r, const void* p) {
    unsigned addr = (unsigned)__cvta_generic_to_shared(p);
    asm volatile("ldmatrix.sync.aligned.m8n8.x4.shared.b16 {%0,%1,%2,%3}, [%4];"
                 : "=r"(r[0]), "=r"(r[1]), "=r"(r[2]), "=r"(r[3]) : "r"(addr));
}
__device__ __forceinline__ void mma16816(float* d, const unsigned* a, const unsigned* b) {
    asm volatile("mma.sync.aligned.m16n8k16.row.col.f32.bf16.bf16.f32 "
                 "{%0,%1,%2,%3}, {%4,%5,%6,%7}, {%8,%9}, {%0,%1,%2,%3};"
                 : "+f"(d[0]), "+f"(d[1]), "+f"(d[2]), "+f"(d[3])
                 : "r"(a[0]), "r"(a[1]), "r"(a[2]), "r"(a[3]), "r"(b[0]), "r"(b[1]));
}

__global__ void zero_kernel() {
    int i = blockIdx.x * 256 + threadIdx.x;
    if (i < kB * kCh) { g_maxxe[i] = 0u; g_maxy[i] = 0u; }
}

__global__ void twiddle_kernel() {
    int i = blockIdx.x * 256 + threadIdx.x;
    float s, c;
    if (i < 4096) { sincospif(-2.0f * i / 8192.0f,  &s, &c); g_tw8 [i] = make_float2(c, s); }
    if (i < 4097) { sincospif(-2.0f * i / 16384.0f, &s, &c); g_tw16[i] = make_float2(c, s); }
}

// Split the 3 weight matrices into hi/lo bf16 pairs (x = hi + lo exactly to 2^-18).
__global__ void wsplit_kernel(const float* __restrict__ We, const float* __restrict__ Wf,
                              const float* __restrict__ Wd) {
    int i = blockIdx.x * 256 + threadIdx.x;
    const float* src = (blockIdx.y == 0) ? We : (blockIdx.y == 1 ? Wf : Wd);
    float v = src[i];
    __nv_bfloat16 h = __float2bfloat16(v);
    g_Wh[blockIdx.y * kCh * kCh + i] = h;
    g_Wl[blockIdx.y * kCh * kCh + i] = __float2bfloat16(v - __bfloat162float(h));
}

// Kf[c][k] = B(w)/A(w)/8192, w = e^{-2*pi*i*k/16384}. (IIR tail beyond n=8192
// underflows fp32, so this equals the reference's FFT-generated kernel.)
// Even/odd Horner: P(w) = Pe(w^2) + w*Po(w^2), 4 independent chains for ILP.
__global__ __launch_bounds__(256) void kfgen_kernel(const float* __restrict__ A,
                                                    const float* __restrict__ Bp) {
    __shared__ float sA[64], sB[64];
    int c = blockIdx.y;
    if (threadIdx.x < 64)       sA[threadIdx.x]      = A [c * 64 + threadIdx.x];
    else if (threadIdx.x < 128) sB[threadIdx.x - 64] = Bp[c * 64 + threadIdx.x - 64];
    __syncthreads();
    int k = blockIdx.x * 256 + threadIdx.x;
    if (k >= kNF) return;
    float sv, cv;
    sincospif(-(float)k / 8192.0f, &sv, &cv);
    float2 w  = make_float2(cv, sv);
    float2 w2 = cmul(w, w);
    float2 ae = make_float2(sA[63], 0.f);            // e_32
    float2 ao = make_float2(sA[62], 0.f);            // o_31
    float2 be = make_float2(sB[62], 0.f);            // be_31
    float2 bo = make_float2(sB[63], 0.f);            // bo_31
#pragma unroll 4
    for (int i = 31; i >= 1; --i) {
        ae = cmul(ae, w2); ae.x += sA[2 * i - 1];    // e_i
        ao = cmul(ao, w2); ao.x += sA[2 * i - 2];    // o_{i-1}
        be = cmul(be, w2); be.x += sB[2 * i - 2];    // be_{i-1}
        bo = cmul(bo, w2); bo.x += sB[2 * i - 1];    // bo_{i-1}
    }
    ae = cmul(ae, w2); ae.x += 1.0f;                 // e_0 = 1
    float2 av = cadd(ae, cmul(w, ao));
    float2 bv = cadd(be, cmul(w, bo));
    float scl = (1.0f / 8192.0f) / (av.x * av.x + av.y * av.y);
    g_Kf[(size_t)c * kNF + k] = make_float2((bv.x * av.x + bv.y * av.y) * scl,
                                            (bv.y * av.x - bv.x * av.y) * scl);
}

// ---------------------------------------------------------------------------
// Tensor-core GEMM: C[M,256] = epi(A[M,256] @ W[256,256]^T + bias)
// 3-pass bf16 split: D = Ah*Wh + Ah*Wl + Al*Wh  (error ~2^-17).
// EPI 0: encode (x -> g_xe AND g_xeT via smem restage, colmax -> g_maxxe)
// EPI 1: fc     (g_y1 -> g_y2, v = gelu(v) + xe skip)
// EPI 2: decode (g_y2 -> d_out, colmax -> g_maxy)
constexpr int kGemmSmem0 = 128 * 129 * 4 + 512;          // stage epilogue + red
constexpr int kGemmSmem1 = 4 * 128 * 40 * 2 + 512;       // core tiles + red
constexpr int kGemmSmem2 = kGemmSmem1;

template <int EPI>
__global__ __launch_bounds__(256, 2) void gemm_kernel(const float* __restrict__ Ain,
                                                      const float* __restrict__ bias,
                                                      float* __restrict__ Cout) {
    constexpr int BM = 128, BN = 128, BK = 32, LDS = 40;   // 80B row stride: conflict-free
    constexpr int SMB = (EPI == 0) ? kGemmSmem0 : kGemmSmem1;
    extern __shared__ __align__(16) unsigned char smem_raw[];
    auto Ah = reinterpret_cast<__nv_bfloat16(*)[LDS]>(smem_raw);
    auto Al = reinterpret_cast<__nv_bfloat16(*)[LDS]>(smem_raw + 10240);
    auto Bh = reinterpret_cast<__nv_bfloat16(*)[LDS]>(smem_raw + 20480);
    auto Bl = reinterpret_cast<__nv_bfloat16(*)[LDS]>(smem_raw + 30720);
    unsigned* red = reinterpret_cast<unsigned*>(smem_raw + SMB - 512);
    const float* Ap = (EPI == 1) ? g_y1 : (EPI == 2 ? g_y2 : Ain);
    float*       Cp = (EPI == 0) ? g_xe : (EPI == 1 ? g_y2 : Cout);
    const __nv_bfloat16* Whp = g_Wh + EPI * kCh * kCh;
    const __nv_bfloat16* Wlp = g_Wl + EPI * kCh * kCh;
    const int m0 = blockIdx.x * BM, n0 = blockIdx.y * BN;
    const int tid = threadIdx.x, lane = tid & 31, warp = tid >> 5;
    const int wr = warp >> 1, wc = warp & 1;      // 4x2 warp grid, warp tile 32x64

    if (EPI != 1 && tid < BN) red[tid] = 0u;

    float acc[2][8][4];
#pragma unroll
    for (int mt = 0; mt < 2; ++mt)
#pragma unroll
        for (int nt = 0; nt < 8; ++nt)
#pragma unroll
            for (int r = 0; r < 4; ++r) acc[mt][nt][r] = 0.f;

    for (int kt = 0; kt < kCh; kt += BK) {
        // A: load fp32 128x32, split to hi/lo bf16
#pragma unroll
        for (int u = 0; u < 4; ++u) {
            int idx = u * 256 + tid;               // 0..1023 float4s
            int row = idx >> 3, c4 = (idx & 7) * 4;
            float4 v = *reinterpret_cast<const float4*>(
                Ap + (size_t)(m0 + row) * kCh + kt + c4);
            __nv_bfloat162 h01 = __floats2bfloat162_rn(v.x, v.y);
            __nv_bfloat162 h23 = __floats2bfloat162_rn(v.z, v.w);
            __nv_bfloat162 l01 = __floats2bfloat162_rn(v.x - __low2float(h01),
                                                       v.y - __high2float(h01));
            __nv_bfloat162 l23 = __floats2bfloat162_rn(v.z - __low2float(h23),
                                                       v.w - __high2float(h23));
            *reinterpret_cast<uint2*>(&Ah[row][c4]) =
                make_uint2(*reinterpret_cast<unsigned*>(&h01), *reinterpret_cast<unsigned*>(&h23));
            *reinterpret_cast<uint2*>(&Al[row][c4]) =
                make_uint2(*reinterpret_cast<unsigned*>(&l01), *reinterpret_cast<unsigned*>(&l23));
        }
        // W: copy pre-split bf16 128x32 (hi and lo)
#pragma unroll
        for (int u = 0; u < 2; ++u) {
            int idx = u * 256 + tid;               // 0..511 uint4s
            int row = idx >> 2, c8 = (idx & 3) * 8;
            *reinterpret_cast<uint4*>(&Bh[row][c8]) =
                *reinterpret_cast<const uint4*>(Whp + (size_t)(n0 + row) * kCh + kt + c8);
            *reinterpret_cast<uint4*>(&Bl[row][c8]) =
                *reinterpret_cast<const uint4*>(Wlp + (size_t)(n0 + row) * kCh + kt + c8);
        }
        __syncthreads();
#pragma unroll
        for (int ks = 0; ks < 2; ++ks) {
            const int kb = ks * 16;
            unsigned ah[2][4], al[2][4];
#pragma unroll
            for (int mt = 0; mt < 2; ++mt) {
                int arow = wr * 32 + mt * 16 + (lane & 15);
                int koff = kb + ((lane >> 4) << 3);
                ldsm4(ah[mt], &Ah[arow][koff]);
                ldsm4(al[mt], &Al[arow][koff]);
            }
#pragma unroll
            for (int g = 0; g < 4; ++g) {
                int nrow = wc * 64 + g * 16 + (lane & 7) + ((lane >> 4) << 3);
                int koff = kb + (((lane >> 3) & 1) << 3);
                unsigned bh[4], bl[4];
                ldsm4(bh, &Bh[nrow][koff]);
                ldsm4(bl, &Bl[nrow][koff]);
#pragma unroll
                for (int mt = 0; mt < 2; ++mt) {
                    mma16816(acc[mt][2 * g],     ah[mt], bh);
                    mma16816(acc[mt][2 * g],     ah[mt], bl);
                    mma16816(acc[mt][2 * g],     al[mt], bh);
                    mma16816(acc[mt][2 * g + 1], ah[mt], bh + 2);
                    mma16816(acc[mt][2 * g + 1], ah[mt], bl + 2);
                    mma16816(acc[mt][2 * g + 1], al[mt], bh + 2);
                }
            }
        }
        __syncthreads();
    }

    float* stage = reinterpret_cast<float*>(smem_raw);     // [128][129], EPI==0 only
    // Epilogue: d0,d1 -> (row, col..col+1); d2,d3 -> (row+8, ...)
#pragma unroll
    for (int mt = 0; mt < 2; ++mt) {
        int r0 = m0 + wr * 32 + mt * 16 + (lane >> 2);
#pragma unroll
        for (int nt = 0; nt < 8; ++nt) {
            int col = n0 + wc * 64 + nt * 8 + (lane & 3) * 2;
            float* c = acc[mt][nt];
            float2 bv = *reinterpret_cast<const float2*>(bias + col);
            float v0 = c[0] + bv.x, v1 = c[1] + bv.y;
            float v2 = c[2] + bv.x, v3 = c[3] + bv.y;
            if (EPI == 1) {
                float2 s0 = *reinterpret_cast<const float2*>(g_xe + (size_t)r0 * kCh + col);
                float2 s1 = *reinterpret_cast<const float2*>(g_xe + (size_t)(r0 + 8) * kCh + col);
                v0 = gelu_exact(v0) + s0.x; v1 = gelu_exact(v1) + s0.y;
                v2 = gelu_exact(v2) + s1.x; v3 = gelu_exact(v3) + s1.y;
            } else {
                float me = fmaxf(fabsf(v0), fabsf(v2));
                float mo = fmaxf(fabsf(v1), fabsf(v3));
#pragma unroll
                for (int o = 4; o < 32; o <<= 1) {
                    me = fmaxf(me, __shfl_xor_sync(0xffffffffu, me, o));
                    mo = fmaxf(mo, __shfl_xor_sync(0xffffffffu, mo, o));
                }
                if (lane < 4) {
                    atomicMax(&red[col - n0],     __float_as_uint(me));
                    atomicMax(&red[col - n0 + 1], __float_as_uint(mo));
                }
            }
            if (EPI == 0) {
                int lr = r0 - m0, lc = col - n0;
                stage[lr * 129 + lc]           = v0;
                stage[lr * 129 + lc + 1]       = v1;
                stage[(lr + 8) * 129 + lc]     = v2;
                stage[(lr + 8) * 129 + lc + 1] = v3;
            }
            *reinterpret_cast<float2*>(Cp + (size_t)r0 * kCh + col)       = make_float2(v0, v1);
            *reinterpret_cast<float2*>(Cp + (size_t)(r0 + 8) * kCh + col) = make_float2(v2, v3);
        }
    }
    if (EPI != 1) {
        __syncthreads();
        if (tid < BN) {
            unsigned* buf = (EPI == 0) ? g_maxxe : g_maxy;
            atomicMax(&buf[(m0 >> 13) * kCh + n0 + tid], red[tid]);
        }
    }
    if (EPI == 0) {
        // transposed write: g_xeT[(b*256 + n0 + c)*8192 + l0 + l] = stage[l][c]
        const int b = m0 >> 13, l0m = m0 & (kSeq - 1);
        __syncthreads();
        for (int i = tid; i < 128 * 128; i += 256) {
            int cidx = i >> 7, l = i & 127;
            g_xeT[((size_t)b * kCh + n0 + cidx) * kSeq + l0m + l] = stage[l * 129 + cidx];
        }
    }
}

// Mixed-radix Stockham: 6 radix-4 stages + 1 radix-2, autosorting ping-pong.
template <bool INV>
__device__ __forceinline__ void fft_stages(float2*& src, float2*& dst, const float2* tw) {
    int nn = kN2, s = 1, ls = 0;
    while (nn > 2) {
        int nq = nn >> 2;
        for (int t = threadIdx.x; t < 2048; t += 1024) {
            int q = t & (s - 1), p = t >> ls;
            float2 a0 = src[q + (p << ls)];
            float2 a1 = src[q + ((p + nq) << ls)];
            float2 a2 = src[q + ((p + 2 * nq) << ls)];
            float2 a3 = src[q + ((p + 3 * nq) << ls)];
            float2 t0 = cadd(a0, a2), t1 = csub(a0, a2);
            float2 t2 = cadd(a1, a3), t3 = csub(a1, a3);
            float2 b0 = cadd(t0, t2), b2 = csub(t0, t2);
            float2 b1, b3;
            if (!INV) {
                b1 = make_float2(t1.x + t3.y, t1.y - t3.x);
                b3 = make_float2(t1.x - t3.y, t1.y + t3.x);
            } else {
                b1 = make_float2(t1.x - t3.y, t1.y + t3.x);
                b3 = make_float2(t1.x + t3.y, t1.y - t3.x);
            }
            float2 w1 = tw[p << ls];
            if (INV) w1.y = -w1.y;
            float2 w2 = cmul(w1, w1), w3 = cmul(w2, w1);
            int o = q + (p << (ls + 2));
            dst[o]         = b0;
            dst[o + s]     = cmul(w1, b1);
            dst[o + 2 * s] = cmul(w2, b2);
            dst[o + 3 * s] = cmul(w3, b3);
        }
        __syncthreads();
        float2* tp = src; src = dst; dst = tp;
        nn >>= 2; s <<= 2; ls += 2;
    }
    for (int t = threadIdx.x; t < 4096; t += 1024) {
        float2 a = src[t], b = src[t + 4096];
        dst[t]        = cadd(a, b);
        dst[t + 4096] = csub(a, b);
    }
    __syncthreads();
    float2* tp = src; src = dst; dst = tp;
}

// One CTA per (b,c) row: real-16384 causal conv via packed complex-8192 FFT.
// In place on g_xeT.
__global__ __launch_bounds__(1024, 1) void fftconv_kernel() {
    extern __shared__ float2 sm[];
    float2* tw8  = sm;
    float2* tw16 = sm + 4096;
    float2* b0   = sm + 8193;
    float2* b1   = b0 + kN2;
    for (int i = threadIdx.x; i < 4097; i += 1024) {
        if (i < 4096) tw8[i] = g_tw8[i];
        tw16[i] = g_tw16[i];
    }
    const int r = blockIdx.x, c = r & (kCh - 1);
    float2* row2 = reinterpret_cast<float2*>(g_xeT + (size_t)r * kSeq);
    for (int n = threadIdx.x; n < kN2; n += 1024)
        b0[n] = (n < 4096) ? row2[n] : make_float2(0.f, 0.f);
    __syncthreads();

    float2 *src = b0, *dst = b1;
    fft_stages<false>(src, dst, tw8);

    const float2* Kfc = g_Kf + (size_t)c * kNF;
    for (int k = threadIdx.x; k <= 4096; k += 1024) {
        int j = (kN2 - k) & (kN2 - 1);
        float2 Zk = src[k], Zj = src[j];
        float2 E = make_float2(0.5f * (Zk.x + Zj.x), 0.5f * (Zk.y - Zj.y));
        float2 O = make_float2(0.5f * (Zk.y + Zj.y), -0.5f * (Zk.x - Zj.x));
        float2 w = tw16[k];
        float2 wO = cmul(w, O);
        float2 Xk = make_float2(E.x + wO.x, E.y + wO.y);
        float2 Xj = make_float2(E.x - wO.x, -(E.y - wO.y));
        float2 Yk = cmul(Xk, Kfc[k]);
        float2 Yj = cmul(Xj, Kfc[kN2 - k]);
        float2 Ey = make_float2(0.5f * (Yk.x + Yj.x), 0.5f * (Yk.y - Yj.y));
        float2 Dy = make_float2(0.5f * (Yk.x - Yj.x), 0.5f * (Yk.y + Yj.y));
        float2 Oy = cmul(make_float2(w.x, -w.y), Dy);
        dst[k] = make_float2(Ey.x - Oy.y, Ey.y + Oy.x);
        if (k >= 1 && k < 4096) {
            float2 Em = make_float2(0.5f * (Yj.x + Yk.x), 0.5f * (Yj.y - Yk.y));
            float2 Dm = make_float2(0.5f * (Yj.x - Yk.x), 0.5f * (Yj.y + Yk.y));
            float2 Om = cmul(make_float2(-w.x, -w.y), Dm);
            dst[kN2 - k] = make_float2(Em.x - Om.y, Em.y + Om.x);
        }
    }
    __syncthreads();
    { float2* tp = src; src = dst; dst = tp; }

    fft_stages<true>(src, dst, tw8);

    for (int n = threadIdx.x; n < 4096; n += 1024) row2[n] = src[n];
}

// y1 = gelu(h1 + h0*xe): transpose h1T (in g_xeT) back to (B,L,C), fuse gelu.
__global__ __launch_bounds__(256) void y1merge_kernel(const float* __restrict__ h0) {
    __shared__ float tile[32][33];
    int b = blockIdx.z, l0 = blockIdx.x * 32, c0 = blockIdx.y * 32;
    int tx = threadIdx.x, ty = threadIdx.y;
    const float* h1T = g_xeT + (size_t)b * kCh * kSeq;
    float h0v = h0[0];
#pragma unroll
    for (int i = 0; i < 4; ++i)
        tile[ty + i * 8][tx] = h1T[(size_t)(c0 + ty + i * 8) * kSeq + l0 + tx];
    __syncthreads();
#pragma unroll
    for (int i = 0; i < 4; ++i) {
        int l = l0 + ty + i * 8;
        size_t idx = ((size_t)b * kSeq + l) * kCh + c0 + tx;
        g_y1[idx] = gelu_exact(tile[tx][ty + i * 8] + h0v * g_xe[idx]);
    }
}

// LayerNorm over channels, in place on g_y2. One warp per row.
__global__ __launch_bounds__(256) void ln_kernel(const float* __restrict__ gamma,
                                                 const float* __restrict__ beta) {
    int warp = threadIdx.x >> 5, lane = threadIdx.x & 31;
    size_t row = (size_t)blockIdx.x * 8 + warp;
    float4* p = reinterpret_cast<float4*>(g_y2 + row * kCh);
    float4 v0 = p[lane], v1 = p[lane + 32];
    float s = v0.x + v0.y + v0.z + v0.w + v1.x + v1.y + v1.z + v1.w;
    float q = v0.x * v0.x + v0.y * v0.y + v0.z * v0.z + v0.w * v0.w
            + v1.x * v1.x + v1.y * v1.y + v1.z * v1.z + v1.w * v1.w;
#pragma unroll
    for (int o = 16; o; o >>= 1) {
        s += __shfl_xor_sync(0xffffffffu, s, o);
        q += __shfl_xor_sync(0xffffffffu, q, o);
    }
    float mu = s * (1.f / 256.f);
    float rstd = rsqrtf(q * (1.f / 256.f) - mu * mu + 1e-5f);
    const float4* g4 = reinterpret_cast<const float4*>(gamma);
    const float4* e4 = reinterpret_cast<const float4*>(beta);
    float4 g0 = g4[lane], g1 = g4[lane + 32], e0 = e4[lane], e1 = e4[lane + 32];
    v0.x = (v0.x - mu) * rstd * g0.x + e0.x; v0.y = (v0.y - mu) * rstd * g0.y + e0.y;
    v0.z = (v0.z - mu) * rstd * g0.z + e0.z; v0.w = (v0.w - mu) * rstd * g0.w + e0.w;
    v1.x = (v1.x - mu) * rstd * g1.x + e1.x; v1.y = (v1.y - mu) * rstd * g1.y + e1.y;
    v1.z = (v1.z - mu) * rstd * g1.z + e1.z; v1.w = (v1.w - mu) * rstd * g1.w + e1.w;
    p[lane] = v0; p[lane + 32] = v1;
}

__global__ void hout_kernel(float* __restrict__ h) {
    int i = blockIdx.x * 256 + threadIdx.x;
    if (i < kB * kCh)
        h[i] = __uint_as_float(g_maxy[i]) / (__uint_as_float(g_maxxe[i]) + 1e-6f);
}

extern "C" void kernel_launch(void* const* d_in, const int* in_sizes, int n_in,
                              void* d_out, int out_size) {
    const float* x     = (const float*)d_in[0];
    const float* A     = (const float*)d_in[1];
    const float* Bp    = (const float*)d_in[2];
    const float* h0    = (const float*)d_in[3];
    const float* W_enc = (const float*)d_in[4];
    const float* b_enc = (const float*)d_in[5];
    const float* W_fc  = (const float*)d_in[6];
    const float* b_fc  = (const float*)d_in[7];
    const float* gamma = (const float*)d_in[8];
    const float* beta  = (const float*)d_in[9];
    const float* W_dec = (const float*)d_in[10];
    const float* b_dec = (const float*)d_in[11];
    float* out = (float*)d_out;

    static cudaStream_t side = nullptr;
    static cudaEvent_t evFork = nullptr, evJoin = nullptr;
    static bool attrsSet = false;
    if (!side) {
        cudaStreamCreateWithFlags(&side, cudaStreamNonBlocking);
        cudaEventCreateWithFlags(&evFork, cudaEventDisableTiming);
        cudaEventCreateWithFlags(&evJoin, cudaEventDisableTiming);
    }
    const int kSmemFFT = 24577 * 8;   // 196616 B dynamic SMEM
    if (!attrsSet) {
        cudaFuncSetAttribute(fftconv_kernel, cudaFuncAttributeMaxDynamicSharedMemorySize, kSmemFFT);
        cudaFuncSetAttribute(gemm_kernel<0>, cudaFuncAttributeMaxDynamicSharedMemorySize, kGemmSmem0);
        cudaFuncSetAttribute(gemm_kernel<1>, cudaFuncAttributeMaxDynamicSharedMemorySize, kGemmSmem1);
        cudaFuncSetAttribute(gemm_kernel<2>, cudaFuncAttributeMaxDynamicSharedMemorySize, kGemmSmem2);
        attrsSet = true;
    }

    // Fork: twiddle + kfgen run on the side stream, overlapping gemm<0>.
    cudaEventRecord(evFork, 0);
    cudaStreamWaitEvent(side, evFork, 0);
    twiddle_kernel<<<17, 256, 0, side>>>();
    kfgen_kernel<<<dim3(33, kCh), 256, 0, side>>>(A, Bp);
    cudaEventRecord(evJoin, side);

    zero_kernel<<<8, 256>>>();
    wsplit_kernel<<<dim3(kCh * kCh / 256, 3), 256>>>(W_enc, W_fc, W_dec);
    gemm_kernel<0><<<dim3(kM / 128, 2), 256, kGemmSmem0>>>(x, b_enc, nullptr);
    cudaStreamWaitEvent(0, evJoin, 0);
    fftconv_kernel<<<kB * kCh, 1024, kSmemFFT>>>();
    y1merge_kernel<<<dim3(kSeq / 32, kCh / 32, kB), dim3(32, 8)>>>(h0);
    gemm_kernel<1><<<dim3(kM / 128, 2), 256, kGemmSmem1>>>(nullptr, b_fc, nullptr);
    ln_kernel<<<kM / 8, 256>>>(gamma, beta);
    gemm_kernel<2><<<dim3(kM / 128, 2), 256, kGemmSmem2>>>(nullptr, b_dec, out);
    hout_kernel<<<8, 256>>>(out + (size_t)kM * kCh);
}

// round 11
// speedup vs baseline: 1.7485x; 1.0244x over previous
#include <cuda_runtime.h>
#include <cuda_bf16.h>

constexpr int kB = 8, kSeq = 8192, kCh = 256;
constexpr int kM  = kB * kSeq;          // 65536
constexpr int kN2 = 8192;               // complex FFT size (real 16384)
constexpr int kNF = 8193;               // rfft bins of 16384

__device__ __align__(128) float  g_xe [kM * kCh];   // (B,L,C)
__device__ __align__(128) float  g_xeT[kM * kCh];   // (B,C,L); FFT in place -> h1T
__device__ __align__(128) float  g_y1 [kM * kCh];   // (B,L,C)
__device__ __align__(128) float  g_y2 [kM * kCh];   // (B,L,C)
__device__ __align__(128) float2 g_Kf [(size_t)kCh * kNF];
__device__ __align__(128) __nv_bfloat16 g_Wh[3 * kCh * kCh];
__device__ __align__(128) __nv_bfloat16 g_Wl[3 * kCh * kCh];
__device__ float2 g_tw8 [4096];
__device__ float2 g_tw16[4097];
__device__ unsigned g_maxxe[kB * kCh];
__device__ unsigned g_maxy [kB * kCh];

// Bank-swizzle for the FFT smem data buffers. Injects addr bits 4..5 into
// bits 2..3. All inter-butterfly read strides (2048/4096/6144) and the
// radix-2 stride (4096) live at bit>=11, so strided reads keep their
// conflict-free pattern; stage-stride writes get spread across banks.
#define SWZ(i) ((i) ^ ((((i) >> 4) & 3) << 2))

__device__ __forceinline__ float2 cmul(float2 a, float2 b) {
    return make_float2(a.x * b.x - a.y * b.y, a.x * b.y + a.y * b.x);
}
__device__ __forceinline__ float2 cadd(float2 a, float2 b) {
    return make_float2(a.x + b.x, a.y + b.y);
}
__device__ __forceinline__ float2 csub(float2 a, float2 b) {
    return make_float2(a.x - b.x, a.y - b.y);
}
__device__ __forceinline__ float gelu_exact(float v) {
    return 0.5f * v * (1.0f + erff(v * 0.7071067811865476f));
}
__device__ __forceinline__ void ldsm4(unsigned* r, const void* p) {
    unsigned addr = (unsigned)__cvta_generic_to_shared(p);
    asm volatile("ldmatrix.sync.aligned.m8n8.x4.shared.b16 {%0,%1,%2,%3}, [%4];"
                 : "=r"(r[0]), "=r"(r[1]), "=r"(r[2]), "=r"(r[3]) : "r"(addr));
}
__device__ __forceinline__ void mma16816(float* d, const unsigned* a, const unsigned* b) {
    asm volatile("mma.sync.aligned.m16n8k16.row.col.f32.bf16.bf16.f32 "
                 "{%0,%1,%2,%3}, {%4,%5,%6,%7}, {%8,%9}, {%0,%1,%2,%3};"
                 : "+f"(d[0]), "+f"(d[1]), "+f"(d[2]), "+f"(d[3])
                 : "r"(a[0]), "r"(a[1]), "r"(a[2]), "r"(a[3]), "r"(b[0]), "r"(b[1]));
}

__global__ void zero_kernel() {
    int i = blockIdx.x * 256 + threadIdx.x;
    if (i < kB * kCh) { g_maxxe[i] = 0u; g_maxy[i] = 0u; }
}

__global__ void twiddle_kernel() {
    int i = blockIdx.x * 256 + threadIdx.x;
    float s, c;
    if (i < 4096) { sincospif(-2.0f * i / 8192.0f,  &s, &c); g_tw8 [i] = make_float2(c, s); }
    if (i < 4097) { sincospif(-2.0f * i / 16384.0f, &s, &c); g_tw16[i] = make_float2(c, s); }
}

// Split the 3 weight matrices into hi/lo bf16 pairs (x = hi + lo exactly to 2^-18).
__global__ void wsplit_kernel(const float* __restrict__ We, const float* __restrict__ Wf,
                              const float* __restrict__ Wd) {
    int i = blockIdx.x * 256 + threadIdx.x;
    const float* src = (blockIdx.y == 0) ? We : (blockIdx.y == 1 ? Wf : Wd);
    float v = src[i];
    __nv_bfloat16 h = __float2bfloat16(v);
    g_Wh[blockIdx.y * kCh * kCh + i] = h;
    g_Wl[blockIdx.y * kCh * kCh + i] = __float2bfloat16(v - __bfloat162float(h));
}

// Kf[c][k] = B(w)/A(w)/8192, w = e^{-2*pi*i*k/16384}. (IIR tail beyond n=8192
// underflows fp32, so this equals the reference's FFT-generated kernel.)
// Even/odd Horner: P(w) = Pe(w^2) + w*Po(w^2), 4 independent chains for ILP.
__global__ __launch_bounds__(256) void kfgen_kernel(const float* __restrict__ A,
                                                    const float* __restrict__ Bp) {
    __shared__ float sA[64], sB[64];
    int c = blockIdx.y;
    if (threadIdx.x < 64)       sA[threadIdx.x]      = A [c * 64 + threadIdx.x];
    else if (threadIdx.x < 128) sB[threadIdx.x - 64] = Bp[c * 64 + threadIdx.x - 64];
    __syncthreads();
    int k = blockIdx.x * 256 + threadIdx.x;
    if (k >= kNF) return;
    float sv, cv;
    sincospif(-(float)k / 8192.0f, &sv, &cv);
    float2 w  = make_float2(cv, sv);
    float2 w2 = cmul(w, w);
    float2 ae = make_float2(sA[63], 0.f);            // e_32
    float2 ao = make_float2(sA[62], 0.f);            // o_31
    float2 be = make_float2(sB[62], 0.f);            // be_31
    float2 bo = make_float2(sB[63], 0.f);            // bo_31
#pragma unroll 4
    for (int i = 31; i >= 1; --i) {
        ae = cmul(ae, w2); ae.x += sA[2 * i - 1];    // e_i
        ao = cmul(ao, w2); ao.x += sA[2 * i - 2];    // o_{i-1}
        be = cmul(be, w2); be.x += sB[2 * i - 2];    // be_{i-1}
        bo = cmul(bo, w2); bo.x += sB[2 * i - 1];    // bo_{i-1}
    }
    ae = cmul(ae, w2); ae.x += 1.0f;                 // e_0 = 1
    float2 av = cadd(ae, cmul(w, ao));
    float2 bv = cadd(be, cmul(w, bo));
    float scl = (1.0f / 8192.0f) / (av.x * av.x + av.y * av.y);
    g_Kf[(size_t)c * kNF + k] = make_float2((bv.x * av.x + bv.y * av.y) * scl,
                                            (bv.y * av.x - bv.x * av.y) * scl);
}

// ---------------------------------------------------------------------------
// Tensor-core GEMM (3-pass bf16 split) — unchanged from the 702us baseline.
constexpr int kGemmSmem0 = 128 * 129 * 4 + 512;          // stage epilogue + red
constexpr int kGemmSmem1 = 4 * 128 * 40 * 2 + 512;       // core tiles + red
constexpr int kGemmSmem2 = kGemmSmem1;

template <int EPI>
__global__ __launch_bounds__(256, 2) void gemm_kernel(const float* __restrict__ Ain,
                                                      const float* __restrict__ bias,
                                                      float* __restrict__ Cout) {
    constexpr int BM = 128, BN = 128, BK = 32, LDS = 40;
    constexpr int SMB = (EPI == 0) ? kGemmSmem0 : kGemmSmem1;
    extern __shared__ __align__(16) unsigned char smem_raw[];
    auto Ah = reinterpret_cast<__nv_bfloat16(*)[LDS]>(smem_raw);
    auto Al = reinterpret_cast<__nv_bfloat16(*)[LDS]>(smem_raw + 10240);
    auto Bh = reinterpret_cast<__nv_bfloat16(*)[LDS]>(smem_raw + 20480);
    auto Bl = reinterpret_cast<__nv_bfloat16(*)[LDS]>(smem_raw + 30720);
    unsigned* red = reinterpret_cast<unsigned*>(smem_raw + SMB - 512);
    const float* Ap = (EPI == 1) ? g_y1 : (EPI == 2 ? g_y2 : Ain);
    float*       Cp = (EPI == 0) ? g_xe : (EPI == 1 ? g_y2 : Cout);
    const __nv_bfloat16* Whp = g_Wh + EPI * kCh * kCh;
    const __nv_bfloat16* Wlp = g_Wl + EPI * kCh * kCh;
    const int m0 = blockIdx.x * BM, n0 = blockIdx.y * BN;
    const int tid = threadIdx.x, lane = tid & 31, warp = tid >> 5;
    const int wr = warp >> 1, wc = warp & 1;

    if (EPI != 1 && tid < BN) red[tid] = 0u;

    float acc[2][8][4];
#pragma unroll
    for (int mt = 0; mt < 2; ++mt)
#pragma unroll
        for (int nt = 0; nt < 8; ++nt)
#pragma unroll
            for (int r = 0; r < 4; ++r) acc[mt][nt][r] = 0.f;

    for (int kt = 0; kt < kCh; kt += BK) {
#pragma unroll
        for (int u = 0; u < 4; ++u) {
            int idx = u * 256 + tid;
            int row = idx >> 3, c4 = (idx & 7) * 4;
            float4 v = *reinterpret_cast<const float4*>(
                Ap + (size_t)(m0 + row) * kCh + kt + c4);
            __nv_bfloat162 h01 = __floats2bfloat162_rn(v.x, v.y);
            __nv_bfloat162 h23 = __floats2bfloat162_rn(v.z, v.w);
            __nv_bfloat162 l01 = __floats2bfloat162_rn(v.x - __low2float(h01),
                                                       v.y - __high2float(h01));
            __nv_bfloat162 l23 = __floats2bfloat162_rn(v.z - __low2float(h23),
                                                       v.w - __high2float(h23));
            *reinterpret_cast<uint2*>(&Ah[row][c4]) =
                make_uint2(*reinterpret_cast<unsigned*>(&h01), *reinterpret_cast<unsigned*>(&h23));
            *reinterpret_cast<uint2*>(&Al[row][c4]) =
                make_uint2(*reinterpret_cast<unsigned*>(&l01), *reinterpret_cast<unsigned*>(&l23));
        }
#pragma unroll
        for (int u = 0; u < 2; ++u) {
            int idx = u * 256 + tid;
            int row = idx >> 2, c8 = (idx & 3) * 8;
            *reinterpret_cast<uint4*>(&Bh[row][c8]) =
                *reinterpret_cast<const uint4*>(Whp + (size_t)(n0 + row) * kCh + kt + c8);
            *reinterpret_cast<uint4*>(&Bl[row][c8]) =
                *reinterpret_cast<const uint4*>(Wlp + (size_t)(n0 + row) * kCh + kt + c8);
        }
        __syncthreads();
#pragma unroll
        for (int ks = 0; ks < 2; ++ks) {
            const int kb = ks * 16;
            unsigned ah[2][4], al[2][4];
#pragma unroll
            for (int mt = 0; mt < 2; ++mt) {
                int arow = wr * 32 + mt * 16 + (lane & 15);
                int koff = kb + ((lane >> 4) << 3);
                ldsm4(ah[mt], &Ah[arow][koff]);
                ldsm4(al[mt], &Al[arow][koff]);
            }
#pragma unroll
            for (int g = 0; g < 4; ++g) {
                int nrow = wc * 64 + g * 16 + (lane & 7) + ((lane >> 4) << 3);
                int koff = kb + (((lane >> 3) & 1) << 3);
                unsigned bh[4], bl[4];
                ldsm4(bh, &Bh[nrow][koff]);
                ldsm4(bl, &Bl[nrow][koff]);
#pragma unroll
                for (int mt = 0; mt < 2; ++mt) {
                    mma16816(acc[mt][2 * g],     ah[mt], bh);
                    mma16816(acc[mt][2 * g],     ah[mt], bl);
                    mma16816(acc[mt][2 * g],     al[mt], bh);
                    mma16816(acc[mt][2 * g + 1], ah[mt], bh + 2);
                    mma16816(acc[mt][2 * g + 1], ah[mt], bl + 2);
                    mma16816(acc[mt][2 * g + 1], al[mt], bh + 2);
                }
            }
        }
        __syncthreads();
    }

    float* stage = reinterpret_cast<float*>(smem_raw);     // [128][129], EPI==0 only
#pragma unroll
    for (int mt = 0; mt < 2; ++mt) {
        int r0 = m0 + wr * 32 + mt * 16 + (lane >> 2);
#pragma unroll
        for (int nt = 0; nt < 8; ++nt) {
            int col = n0 + wc * 64 + nt * 8 + (lane & 3) * 2;
            float* c = acc[mt][nt];
            float2 bv = *reinterpret_cast<const float2*>(bias + col);
            float v0 = c[0] + bv.x, v1 = c[1] + bv.y;
            float v2 = c[2] + bv.x, v3 = c[3] + bv.y;
            if (EPI == 1) {
                float2 s0 = *reinterpret_cast<const float2*>(g_xe + (size_t)r0 * kCh + col);
                float2 s1 = *reinterpret_cast<const float2*>(g_xe + (size_t)(r0 + 8) * kCh + col);
                v0 = gelu_exact(v0) + s0.x; v1 = gelu_exact(v1) + s0.y;
                v2 = gelu_exact(v2) + s1.x; v3 = gelu_exact(v3) + s1.y;
            } else {
                float me = fmaxf(fabsf(v0), fabsf(v2));
                float mo = fmaxf(fabsf(v1), fabsf(v3));
#pragma unroll
                for (int o = 4; o < 32; o <<= 1) {
                    me = fmaxf(me, __shfl_xor_sync(0xffffffffu, me, o));
                    mo = fmaxf(mo, __shfl_xor_sync(0xffffffffu, mo, o));
                }
                if (lane < 4) {
                    atomicMax(&red[col - n0],     __float_as_uint(me));
                    atomicMax(&red[col - n0 + 1], __float_as_uint(mo));
                }
            }
            if (EPI == 0) {
                int lr = r0 - m0, lc = col - n0;
                stage[lr * 129 + lc]           = v0;
                stage[lr * 129 + lc + 1]       = v1;
                stage[(lr + 8) * 129 + lc]     = v2;
                stage[(lr + 8) * 129 + lc + 1] = v3;
            }
            *reinterpret_cast<float2*>(Cp + (size_t)r0 * kCh + col)       = make_float2(v0, v1);
            *reinterpret_cast<float2*>(Cp + (size_t)(r0 + 8) * kCh + col) = make_float2(v2, v3);
        }
    }
    if (EPI != 1) {
        __syncthreads();
        if (tid < BN) {
            unsigned* buf = (EPI == 0) ? g_maxxe : g_maxy;
            atomicMax(&buf[(m0 >> 13) * kCh + n0 + tid], red[tid]);
        }
    }
    if (EPI == 0) {
        const int b = m0 >> 13, l0m = m0 & (kSeq - 1);
        __syncthreads();
        for (int i = tid; i < 128 * 128; i += 256) {
            int cidx = i >> 7, l = i & 127;
            g_xeT[((size_t)b * kCh + n0 + cidx) * kSeq + l0m + l] = stage[l * 129 + cidx];
        }
    }
}

// ---------------------------------------------------------------------------
// FFT stages (swizzled smem). Reads are always {t, t+2048, t+4096, t+6144}.
// First stage (s=1) peeled: outputs are 4 consecutive float2 -> two float4
// stores (conflict-free); remaining stages' writes are spread by SWZ.
template <bool INV>
__device__ __forceinline__ void fft_first(const float2* src, float2* dst, const float2* tw) {
    for (int t = threadIdx.x; t < 2048; t += 1024) {
        float2 a0 = src[SWZ(t)];
        float2 a1 = src[SWZ(t + 2048)];
        float2 a2 = src[SWZ(t + 4096)];
        float2 a3 = src[SWZ(t + 6144)];
        float2 t0 = cadd(a0, a2), t1 = csub(a0, a2);
        float2 t2 = cadd(a1, a3), t3 = csub(a1, a3);
        float2 b0 = cadd(t0, t2), b2 = csub(t0, t2);
        float2 b1, b3;
        if (!INV) {
            b1 = make_float2(t1.x + t3.y, t1.y - t3.x);
            b3 = make_float2(t1.x - t3.y, t1.y + t3.x);
        } else {
            b1 = make_float2(t1.x - t3.y, t1.y + t3.x);
            b3 = make_float2(t1.x + t3.y, t1.y - t3.x);
        }
        float2 w1 = tw[t];
        if (INV) w1.y = -w1.y;
        float2 w2 = cmul(w1, w1), w3 = cmul(w2, w1);
        float2 o1 = cmul(w1, b1), o2 = cmul(w2, b2), o3 = cmul(w3, b3);
        float4* d4 = reinterpret_cast<float4*>(dst + SWZ(4 * t));
        d4[0] = make_float4(b0.x, b0.y, o1.x, o1.y);
        d4[1] = make_float4(o2.x, o2.y, o3.x, o3.y);
    }
    __syncthreads();
}

template <bool INV>
__device__ __forceinline__ void fft_stages(float2*& src, float2*& dst, const float2* tw) {
    fft_first<INV>(src, dst, tw);
    { float2* tp = src; src = dst; dst = tp; }
    int nn = 2048, s = 4, ls = 2;
    while (nn > 2) {
        for (int t = threadIdx.x; t < 2048; t += 1024) {
            int q = t & (s - 1), p = t >> ls;
            float2 a0 = src[SWZ(t)];
            float2 a1 = src[SWZ(t + 2048)];
            float2 a2 = src[SWZ(t + 4096)];
            float2 a3 = src[SWZ(t + 6144)];
            float2 t0 = cadd(a0, a2), t1 = csub(a0, a2);
            float2 t2 = cadd(a1, a3), t3 = csub(a1, a3);
            float2 b0 = cadd(t0, t2), b2 = csub(t0, t2);
            float2 b1, b3;
            if (!INV) {
                b1 = make_float2(t1.x + t3.y, t1.y - t3.x);
                b3 = make_float2(t1.x - t3.y, t1.y + t3.x);
            } else {
                b1 = make_float2(t1.x - t3.y, t1.y + t3.x);
                b3 = make_float2(t1.x + t3.y, t1.y - t3.x);
            }
            float2 w1 = tw[p << ls];
            if (INV) w1.y = -w1.y;
            float2 w2 = cmul(w1, w1), w3 = cmul(w2, w1);
            int o = q + (p << (ls + 2));
            dst[SWZ(o)]         = b0;
            dst[SWZ(o + s)]     = cmul(w1, b1);
            dst[SWZ(o + 2 * s)] = cmul(w2, b2);
            dst[SWZ(o + 3 * s)] = cmul(w3, b3);
        }
        __syncthreads();
        float2* tp = src; src = dst; dst = tp;
        nn >>= 2; s <<= 2; ls += 2;
    }
    for (int t = threadIdx.x; t < 4096; t += 1024) {
        float2 a = src[SWZ(t)], b = src[SWZ(t + 4096)];
        dst[SWZ(t)]        = cadd(a, b);
        dst[SWZ(t + 4096)] = csub(a, b);
    }
    __syncthreads();
    float2* tp = src; src = dst; dst = tp;
}

// One CTA per (b,c) row: real-16384 causal conv via packed complex-8192 FFT.
// In place on g_xeT. Data buffers are SWZ-swizzled.
__global__ __launch_bounds__(1024, 1) void fftconv_kernel() {
    extern __shared__ float2 sm[];
    float2* tw8  = sm;                 // [0, 4096)
    float2* tw16 = sm + 4096;          // [4096, 8193)
    float2* b0   = sm + 8194;          // even offset -> 16B-aligned for float4
    float2* b1   = b0 + kN2;           // 16386, even
    for (int i = threadIdx.x; i < 4097; i += 1024) {
        if (i < 4096) tw8[i] = g_tw8[i];
        tw16[i] = g_tw16[i];
    }
    const int r = blockIdx.x, c = r & (kCh - 1);
    float2* row2 = reinterpret_cast<float2*>(g_xeT + (size_t)r * kSeq);
    for (int n = threadIdx.x; n < kN2; n += 1024)
        b0[SWZ(n)] = (n < 4096) ? row2[n] : make_float2(0.f, 0.f);
    __syncthreads();

    float2 *src = b0, *dst = b1;
    fft_stages<false>(src, dst, tw8);

    const float2* Kfc = g_Kf + (size_t)c * kNF;
    for (int k = threadIdx.x; k <= 4096; k += 1024) {
        int j = (kN2 - k) & (kN2 - 1);
        float2 Zk = src[SWZ(k)], Zj = src[SWZ(j)];
        float2 E = make_float2(0.5f * (Zk.x + Zj.x), 0.5f * (Zk.y - Zj.y));
        float2 O = make_float2(0.5f * (Zk.y + Zj.y), -0.5f * (Zk.x - Zj.x));
        float2 w = tw16[k];
        float2 wO = cmul(w, O);
        float2 Xk = make_float2(E.x + wO.x, E.y + wO.y);
        float2 Xj = make_float2(E.x - wO.x, -(E.y - wO.y));
        float2 Yk = cmul(Xk, Kfc[k]);
        float2 Yj = cmul(Xj, Kfc[kN2 - k]);
        float2 Ey = make_float2(0.5f * (Yk.x + Yj.x), 0.5f * (Yk.y - Yj.y));
        float2 Dy = make_float2(0.5f * (Yk.x - Yj.x), 0.5f * (Yk.y + Yj.y));
        float2 Oy = cmul(make_float2(w.x, -w.y), Dy);
        dst[SWZ(k)] = make_float2(Ey.x - Oy.y, Ey.y + Oy.x);
        if (k >= 1 && k < 4096) {
            float2 Em = make_float2(0.5f * (Yj.x + Yk.x), 0.5f * (Yj.y - Yk.y));
            float2 Dm = make_float2(0.5f * (Yj.x - Yk.x), 0.5f * (Yj.y + Yk.y));
            float2 Om = cmul(make_float2(-w.x, -w.y), Dm);
            dst[SWZ(kN2 - k)] = make_float2(Em.x - Om.y, Em.y + Om.x);
        }
    }
    __syncthreads();
    { float2* tp = src; src = dst; dst = tp; }

    fft_stages<true>(src, dst, tw8);

    for (int n = threadIdx.x; n < 4096; n += 1024) row2[n] = src[SWZ(n)];
}

// y1 = gelu(h1 + h0*xe): transpose h1T (in g_xeT) back to (B,L,C), fuse gelu.
__global__ __launch_bounds__(256) void y1merge_kernel(const float* __restrict__ h0) {
    __shared__ float tile[32][33];
    int b = blockIdx.z, l0 = blockIdx.x * 32, c0 = blockIdx.y * 32;
    int tx = threadIdx.x, ty = threadIdx.y;
    const float* h1T = g_xeT + (size_t)b * kCh * kSeq;
    float h0v = h0[0];
#pragma unroll
    for (int i = 0; i < 4; ++i)
        tile[ty + i * 8][tx] = h1T[(size_t)(c0 + ty + i * 8) * kSeq + l0 + tx];
    __syncthreads();
#pragma unroll
    for (int i = 0; i < 4; ++i) {
        int l = l0 + ty + i * 8;
        size_t idx = ((size_t)b * kSeq + l) * kCh + c0 + tx;
        g_y1[idx] = gelu_exact(tile[tx][ty + i * 8] + h0v * g_xe[idx]);
    }
}

// LayerNorm over channels, in place on g_y2. One warp per row.
__global__ __launch_bounds__(256) void ln_kernel(const float* __restrict__ gamma,
                                                 const float* __restrict__ beta) {
    int warp = threadIdx.x >> 5, lane = threadIdx.x & 31;
    size_t row = (size_t)blockIdx.x * 8 + warp;
    float4* p = reinterpret_cast<float4*>(g_y2 + row * kCh);
    float4 v0 = p[lane], v1 = p[lane + 32];
    float s = v0.x + v0.y + v0.z + v0.w + v1.x + v1.y + v1.z + v1.w;
    float q = v0.x * v0.x + v0.y * v0.y + v0.z * v0.z + v0.w * v0.w
            + v1.x * v1.x + v1.y * v1.y + v1.z * v1.z + v1.w * v1.w;
#pragma unroll
    for (int o = 16; o; o >>= 1) {
        s += __shfl_xor_sync(0xffffffffu, s, o);
        q += __shfl_xor_sync(0xffffffffu, q, o);
    }
    float mu = s * (1.f / 256.f);
    float rstd = rsqrtf(q * (1.f / 256.f) - mu * mu + 1e-5f);
    const float4* g4 = reinterpret_cast<const float4*>(gamma);
    const float4* e4 = reinterpret_cast<const float4*>(beta);
    float4 g0 = g4[lane], g1 = g4[lane + 32], e0 = e4[lane], e1 = e4[lane + 32];
    v0.x = (v0.x - mu) * rstd * g0.x + e0.x; v0.y = (v0.y - mu) * rstd * g0.y + e0.y;
    v0.z = (v0.z - mu) * rstd * g0.z + e0.z; v0.w = (v0.w - mu) * rstd * g0.w + e0.w;
    v1.x = (v1.x - mu) * rstd * g1.x + e1.x; v1.y = (v1.y - mu) * rstd * g1.y + e1.y;
    v1.z = (v1.z - mu) * rstd * g1.z + e1.z; v1.w = (v1.w - mu) * rstd * g1.w + e1.w;
    p[lane] = v0; p[lane + 32] = v1;
}

__global__ void hout_kernel(float* __restrict__ h) {
    int i = blockIdx.x * 256 + threadIdx.x;
    if (i < kB * kCh)
        h[i] = __uint_as_float(g_maxy[i]) / (__uint_as_float(g_maxxe[i]) + 1e-6f);
}

extern "C" void kernel_launch(void* const* d_in, const int* in_sizes, int n_in,
                              void* d_out, int out_size) {
    const float* x     = (const float*)d_in[0];
    const float* A     = (const float*)d_in[1];
    const float* Bp    = (const float*)d_in[2];
    const float* h0    = (const float*)d_in[3];
    const float* W_enc = (const float*)d_in[4];
    const float* b_enc = (const float*)d_in[5];
    const float* W_fc  = (const float*)d_in[6];
    const float* b_fc  = (const float*)d_in[7];
    const float* gamma = (const float*)d_in[8];
    const float* beta  = (const float*)d_in[9];
    const float* W_dec = (const float*)d_in[10];
    const float* b_dec = (const float*)d_in[11];
    float* out = (float*)d_out;

    static cudaStream_t side = nullptr;
    static cudaEvent_t evFork = nullptr, evJoin = nullptr;
    static bool attrsSet = false;
    if (!side) {
        cudaStreamCreateWithFlags(&side, cudaStreamNonBlocking);
        cudaEventCreateWithFlags(&evFork, cudaEventDisableTiming);
        cudaEventCreateWithFlags(&evJoin, cudaEventDisableTiming);
    }
    const int kSmemFFT = 24578 * 8;   // 196624 B dynamic SMEM (b0 16B-aligned)
    if (!attrsSet) {
        cudaFuncSetAttribute(fftconv_kernel, cudaFuncAttributeMaxDynamicSharedMemorySize, kSmemFFT);
        cudaFuncSetAttribute(gemm_kernel<0>, cudaFuncAttributeMaxDynamicSharedMemorySize, kGemmSmem0);
        cudaFuncSetAttribute(gemm_kernel<1>, cudaFuncAttributeMaxDynamicSharedMemorySize, kGemmSmem1);
        cudaFuncSetAttribute(gemm_kernel<2>, cudaFuncAttributeMaxDynamicSharedMemorySize, kGemmSmem2);
        attrsSet = true;
    }

    // Fork: twiddle + kfgen run on the side stream, overlapping gemm<0>.
    cudaEventRecord(evFork, 0);
    cudaStreamWaitEvent(side, evFork, 0);
    twiddle_kernel<<<17, 256, 0, side>>>();
    kfgen_kernel<<<dim3(33, kCh), 256, 0, side>>>(A, Bp);
    cudaEventRecord(evJoin, side);

    zero_kernel<<<8, 256>>>();
    wsplit_kernel<<<dim3(kCh * kCh / 256, 3), 256>>>(W_enc, W_fc, W_dec);
    gemm_kernel<0><<<dim3(kM / 128, 2), 256, kGemmSmem0>>>(x, b_enc, nullptr);
    cudaStreamWaitEvent(0, evJoin, 0);
    fftconv_kernel<<<kB * kCh, 1024, kSmemFFT>>>();
    y1merge_kernel<<<dim3(kSeq / 32, kCh / 32, kB), dim3(32, 8)>>>(h0);
    gemm_kernel<1><<<dim3(kM / 128, 2), 256, kGemmSmem1>>>(nullptr, b_fc, nullptr);
    ln_kernel<<<kM / 8, 256>>>(gamma, beta);
    gemm_kernel<2><<<dim3(kM / 128, 2), 256, kGemmSmem2>>>(nullptr, b_dec, out);
    hout_kernel<<<8, 256>>>(out + (size_t)kM * kCh);
}

// round 12
// speedup vs baseline: 1.8495x; 1.0577x over previous
#include <cuda_runtime.h>
#include <cuda_bf16.h>

constexpr int kB = 8, kSeq = 8192, kCh = 256;
constexpr int kM  = kB * kSeq;          // 65536
constexpr int kN2 = 8192;               // complex FFT size (real 16384)
constexpr int kNF = 8193;               // rfft bins of 16384

__device__ __align__(128) float  g_xe [kM * kCh];   // (B,L,C)
__device__ __align__(128) float  g_xeT[kM * kCh];   // (B,C,L), preserved
__device__ __align__(128) float  g_y1 [kM * kCh];   // (B,C,L)  y1T = gelu(h1T+h0*xeT)
__device__ __align__(128) float  g_y2 [kM * kCh];   // (B,L,C)
__device__ __align__(128) float2 g_Kf [(size_t)kCh * kNF];
__device__ __align__(128) __nv_bfloat16 g_Wh[3 * kCh * kCh];
__device__ __align__(128) __nv_bfloat16 g_Wl[3 * kCh * kCh];
__device__ float2 g_tw8 [4096];
__device__ float2 g_tw16[4097];
__device__ unsigned g_maxxe[kB * kCh];
__device__ unsigned g_maxy [kB * kCh];

// Bank-swizzle for FFT smem data buffers (see R11): spreads stage-stride writes.
#define SWZ(i) ((i) ^ ((((i) >> 4) & 3) << 2))

__device__ __forceinline__ float2 cmul(float2 a, float2 b) {
    return make_float2(a.x * b.x - a.y * b.y, a.x * b.y + a.y * b.x);
}
__device__ __forceinline__ float2 cadd(float2 a, float2 b) {
    return make_float2(a.x + b.x, a.y + b.y);
}
__device__ __forceinline__ float2 csub(float2 a, float2 b) {
    return make_float2(a.x - b.x, a.y - b.y);
}
__device__ __forceinline__ float gelu_exact(float v) {
    return 0.5f * v * (1.0f + erff(v * 0.7071067811865476f));
}
__device__ __forceinline__ void ldsm4(unsigned* r, const void* p) {
    unsigned addr = (unsigned)__cvta_generic_to_shared(p);
    asm volatile("ldmatrix.sync.aligned.m8n8.x4.shared.b16 {%0,%1,%2,%3}, [%4];"
                 : "=r"(r[0]), "=r"(r[1]), "=r"(r[2]), "=r"(r[3]) : "r"(addr));
}
__device__ __forceinline__ void ldsm4t(unsigned* r, const void* p) {
    unsigned addr = (unsigned)__cvta_generic_to_shared(p);
    asm volatile("ldmatrix.sync.aligned.m8n8.x4.trans.shared.b16 {%0,%1,%2,%3}, [%4];"
                 : "=r"(r[0]), "=r"(r[1]), "=r"(r[2]), "=r"(r[3]) : "r"(addr));
}
__device__ __forceinline__ void mma16816(float* d, const unsigned* a, const unsigned* b) {
    asm volatile("mma.sync.aligned.m16n8k16.row.col.f32.bf16.bf16.f32 "
                 "{%0,%1,%2,%3}, {%4,%5,%6,%7}, {%8,%9}, {%0,%1,%2,%3};"
                 : "+f"(d[0]), "+f"(d[1]), "+f"(d[2]), "+f"(d[3])
                 : "r"(a[0]), "r"(a[1]), "r"(a[2]), "r"(a[3]), "r"(b[0]), "r"(b[1]));
}

__global__ void zero_kernel() {
    int i = blockIdx.x * 256 + threadIdx.x;
    if (i < kB * kCh) { g_maxxe[i] = 0u; g_maxy[i] = 0u; }
}

__global__ void twiddle_kernel() {
    int i = blockIdx.x * 256 + threadIdx.x;
    float s, c;
    if (i < 4096) { sincospif(-2.0f * i / 8192.0f,  &s, &c); g_tw8 [i] = make_float2(c, s); }
    if (i < 4097) { sincospif(-2.0f * i / 16384.0f, &s, &c); g_tw16[i] = make_float2(c, s); }
}

// Split the 3 weight matrices into hi/lo bf16 pairs (x = hi + lo exactly to 2^-18).
__global__ void wsplit_kernel(const float* __restrict__ We, const float* __restrict__ Wf,
                              const float* __restrict__ Wd) {
    int i = blockIdx.x * 256 + threadIdx.x;
    const float* src = (blockIdx.y == 0) ? We : (blockIdx.y == 1 ? Wf : Wd);
    float v = src[i];
    __nv_bfloat16 h = __float2bfloat16(v);
    g_Wh[blockIdx.y * kCh * kCh + i] = h;
    g_Wl[blockIdx.y * kCh * kCh + i] = __float2bfloat16(v - __bfloat162float(h));
}

// Kf[c][k] = B(w)/A(w)/8192 (IIR tail underflows fp32 beyond n=8192).
// Even/odd Horner, 4 independent chains for ILP.
__global__ __launch_bounds__(256) void kfgen_kernel(const float* __restrict__ A,
                                                    const float* __restrict__ Bp) {
    __shared__ float sA[64], sB[64];
    int c = blockIdx.y;
    if (threadIdx.x < 64)       sA[threadIdx.x]      = A [c * 64 + threadIdx.x];
    else if (threadIdx.x < 128) sB[threadIdx.x - 64] = Bp[c * 64 + threadIdx.x - 64];
    __syncthreads();
    int k = blockIdx.x * 256 + threadIdx.x;
    if (k >= kNF) return;
    float sv, cv;
    sincospif(-(float)k / 8192.0f, &sv, &cv);
    float2 w  = make_float2(cv, sv);
    float2 w2 = cmul(w, w);
    float2 ae = make_float2(sA[63], 0.f);
    float2 ao = make_float2(sA[62], 0.f);
    float2 be = make_float2(sB[62], 0.f);
    float2 bo = make_float2(sB[63], 0.f);
#pragma unroll 4
    for (int i = 31; i >= 1; --i) {
        ae = cmul(ae, w2); ae.x += sA[2 * i - 1];
        ao = cmul(ao, w2); ao.x += sA[2 * i - 2];
        be = cmul(be, w2); be.x += sB[2 * i - 2];
        bo = cmul(bo, w2); bo.x += sB[2 * i - 1];
    }
    ae = cmul(ae, w2); ae.x += 1.0f;
    float2 av = cadd(ae, cmul(w, ao));
    float2 bv = cadd(be, cmul(w, bo));
    float scl = (1.0f / 8192.0f) / (av.x * av.x + av.y * av.y);
    g_Kf[(size_t)c * kNF + k] = make_float2((bv.x * av.x + bv.y * av.y) * scl,
                                            (bv.y * av.x - bv.x * av.y) * scl);
}

// ---------------------------------------------------------------------------
// Tensor-core GEMM (3-pass bf16 split).
// EPI 0: encode (x (B,L,C) -> g_xe + g_xeT via smem restage, colmax)
// EPI 1: fc     (A from y1T (B,C,L) via ldmatrix.trans; out gelu+skip -> g_y2)
// EPI 2: decode (g_y2 -> d_out, colmax)
constexpr int kGemmSmem0 = 128 * 129 * 4 + 512;
constexpr int kGemmSmem1 = 4 * 128 * 40 * 2 + 512;
constexpr int kGemmSmem2 = kGemmSmem1;

template <int EPI>
__global__ __launch_bounds__(256, 2) void gemm_kernel(const float* __restrict__ Ain,
                                                      const float* __restrict__ bias,
                                                      float* __restrict__ Cout) {
    constexpr int BM = 128, BN = 128, BK = 32, LDS = 40, LDT = 136;
    constexpr int SMB = (EPI == 0) ? kGemmSmem0 : kGemmSmem1;
    extern __shared__ __align__(16) unsigned char smem_raw[];
    // EPI 0/2: A row-major tiles [128][40]; EPI 1: A K-major tiles [32][136]
    auto Ah  = reinterpret_cast<__nv_bfloat16(*)[LDS]>(smem_raw);
    auto Al  = reinterpret_cast<__nv_bfloat16(*)[LDS]>(smem_raw + 10240);
    auto Ath = reinterpret_cast<__nv_bfloat16(*)[LDT]>(smem_raw);
    auto Atl = reinterpret_cast<__nv_bfloat16(*)[LDT]>(smem_raw + 8704);
    auto Bh  = reinterpret_cast<__nv_bfloat16(*)[LDS]>(smem_raw + 20480);
    auto Bl  = reinterpret_cast<__nv_bfloat16(*)[LDS]>(smem_raw + 30720);
    unsigned* red = reinterpret_cast<unsigned*>(smem_raw + SMB - 512);
    const float* Ap = (EPI == 1) ? g_y1 : (EPI == 2 ? g_y2 : Ain);
    float*       Cp = (EPI == 0) ? g_xe : (EPI == 1 ? g_y2 : Cout);
    const __nv_bfloat16* Whp = g_Wh + EPI * kCh * kCh;
    const __nv_bfloat16* Wlp = g_Wl + EPI * kCh * kCh;
    const int m0 = blockIdx.x * BM, n0 = blockIdx.y * BN;
    const int tid = threadIdx.x, lane = tid & 31, warp = tid >> 5;
    const int wr = warp >> 1, wc = warp & 1;

    if (EPI != 1 && tid < BN) red[tid] = 0u;

    float acc[2][8][4];
#pragma unroll
    for (int mt = 0; mt < 2; ++mt)
#pragma unroll
        for (int nt = 0; nt < 8; ++nt)
#pragma unroll
            for (int r = 0; r < 4; ++r) acc[mt][nt][r] = 0.f;

    for (int kt = 0; kt < kCh; kt += BK) {
        if (EPI == 1) {
            // A from y1T: [ch][m] tile, float4 along m (coalesced)
            const int b = m0 >> 13, l0m = m0 & (kSeq - 1);
#pragma unroll
            for (int u = 0; u < 4; ++u) {
                int idx = u * 256 + tid;
                int ch = idx >> 5, mg = (idx & 31) * 4;
                float4 v = *reinterpret_cast<const float4*>(
                    Ap + ((size_t)b * kCh + kt + ch) * kSeq + l0m + mg);
                __nv_bfloat162 h01 = __floats2bfloat162_rn(v.x, v.y);
                __nv_bfloat162 h23 = __floats2bfloat162_rn(v.z, v.w);
                __nv_bfloat162 l01 = __floats2bfloat162_rn(v.x - __low2float(h01),
                                                           v.y - __high2float(h01));
                __nv_bfloat162 l23 = __floats2bfloat162_rn(v.z - __low2float(h23),
                                                           v.w - __high2float(h23));
                *reinterpret_cast<uint2*>(&Ath[ch][mg]) =
                    make_uint2(*reinterpret_cast<unsigned*>(&h01), *reinterpret_cast<unsigned*>(&h23));
                *reinterpret_cast<uint2*>(&Atl[ch][mg]) =
                    make_uint2(*reinterpret_cast<unsigned*>(&l01), *reinterpret_cast<unsigned*>(&l23));
            }
        } else {
#pragma unroll
            for (int u = 0; u < 4; ++u) {
                int idx = u * 256 + tid;
                int row = idx >> 3, c4 = (idx & 7) * 4;
                float4 v = *reinterpret_cast<const float4*>(
                    Ap + (size_t)(m0 + row) * kCh + kt + c4);
                __nv_bfloat162 h01 = __floats2bfloat162_rn(v.x, v.y);
                __nv_bfloat162 h23 = __floats2bfloat162_rn(v.z, v.w);
                __nv_bfloat162 l01 = __floats2bfloat162_rn(v.x - __low2float(h01),
                                                           v.y - __high2float(h01));
                __nv_bfloat162 l23 = __floats2bfloat162_rn(v.z - __low2float(h23),
                                                           v.w - __high2float(h23));
                *reinterpret_cast<uint2*>(&Ah[row][c4]) =
                    make_uint2(*reinterpret_cast<unsigned*>(&h01), *reinterpret_cast<unsigned*>(&h23));
                *reinterpret_cast<uint2*>(&Al[row][c4]) =
                    make_uint2(*reinterpret_cast<unsigned*>(&l01), *reinterpret_cast<unsigned*>(&l23));
            }
        }
#pragma unroll
        for (int u = 0; u < 2; ++u) {
            int idx = u * 256 + tid;
            int row = idx >> 2, c8 = (idx & 3) * 8;
            *reinterpret_cast<uint4*>(&Bh[row][c8]) =
                *reinterpret_cast<const uint4*>(Whp + (size_t)(n0 + row) * kCh + kt + c8);
            *reinterpret_cast<uint4*>(&Bl[row][c8]) =
                *reinterpret_cast<const uint4*>(Wlp + (size_t)(n0 + row) * kCh + kt + c8);
        }
        __syncthreads();
#pragma unroll
        for (int ks = 0; ks < 2; ++ks) {
            const int kb = ks * 16;
            unsigned ah[2][4], al[2][4];
#pragma unroll
            for (int mt = 0; mt < 2; ++mt) {
                if (EPI == 1) {
                    int krow = kb + ((lane >> 4) << 3) + (lane & 7);
                    int mcol = wr * 32 + mt * 16 + (((lane >> 3) & 1) << 3);
                    ldsm4t(ah[mt], &Ath[krow][mcol]);
                    ldsm4t(al[mt], &Atl[krow][mcol]);
                } else {
                    int arow = wr * 32 + mt * 16 + (lane & 15);
                    int koff = kb + ((lane >> 4) << 3);
                    ldsm4(ah[mt], &Ah[arow][koff]);
                    ldsm4(al[mt], &Al[arow][koff]);
                }
            }
#pragma unroll
            for (int g = 0; g < 4; ++g) {
                int nrow = wc * 64 + g * 16 + (lane & 7) + ((lane >> 4) << 3);
                int koff = kb + (((lane >> 3) & 1) << 3);
                unsigned bh[4], bl[4];
                ldsm4(bh, &Bh[nrow][koff]);
                ldsm4(bl, &Bl[nrow][koff]);
#pragma unroll
                for (int mt = 0; mt < 2; ++mt) {
                    mma16816(acc[mt][2 * g],     ah[mt], bh);
                    mma16816(acc[mt][2 * g],     ah[mt], bl);
                    mma16816(acc[mt][2 * g],     al[mt], bh);
                    mma16816(acc[mt][2 * g + 1], ah[mt], bh + 2);
                    mma16816(acc[mt][2 * g + 1], ah[mt], bl + 2);
                    mma16816(acc[mt][2 * g + 1], al[mt], bh + 2);
                }
            }
        }
        __syncthreads();
    }

    float* stage = reinterpret_cast<float*>(smem_raw);     // [128][129], EPI==0 only
#pragma unroll
    for (int mt = 0; mt < 2; ++mt) {
        int r0 = m0 + wr * 32 + mt * 16 + (lane >> 2);
#pragma unroll
        for (int nt = 0; nt < 8; ++nt) {
            int col = n0 + wc * 64 + nt * 8 + (lane & 3) * 2;
            float* c = acc[mt][nt];
            float2 bv = *reinterpret_cast<const float2*>(bias + col);
            float v0 = c[0] + bv.x, v1 = c[1] + bv.y;
            float v2 = c[2] + bv.x, v3 = c[3] + bv.y;
            if (EPI == 1) {
                float2 s0 = *reinterpret_cast<const float2*>(g_xe + (size_t)r0 * kCh + col);
                float2 s1 = *reinterpret_cast<const float2*>(g_xe + (size_t)(r0 + 8) * kCh + col);
                v0 = gelu_exact(v0) + s0.x; v1 = gelu_exact(v1) + s0.y;
                v2 = gelu_exact(v2) + s1.x; v3 = gelu_exact(v3) + s1.y;
            } else {
                float me = fmaxf(fabsf(v0), fabsf(v2));
                float mo = fmaxf(fabsf(v1), fabsf(v3));
#pragma unroll
                for (int o = 4; o < 32; o <<= 1) {
                    me = fmaxf(me, __shfl_xor_sync(0xffffffffu, me, o));
                    mo = fmaxf(mo, __shfl_xor_sync(0xffffffffu, mo, o));
                }
                if (lane < 4) {
                    atomicMax(&red[col - n0],     __float_as_uint(me));
                    atomicMax(&red[col - n0 + 1], __float_as_uint(mo));
                }
            }
            if (EPI == 0) {
                int lr = r0 - m0, lc = col - n0;
                stage[lr * 129 + lc]           = v0;
                stage[lr * 129 + lc + 1]       = v1;
                stage[(lr + 8) * 129 + lc]     = v2;
                stage[(lr + 8) * 129 + lc + 1] = v3;
            }
            *reinterpret_cast<float2*>(Cp + (size_t)r0 * kCh + col)       = make_float2(v0, v1);
            *reinterpret_cast<float2*>(Cp + (size_t)(r0 + 8) * kCh + col) = make_float2(v2, v3);
        }
    }
    if (EPI != 1) {
        __syncthreads();
        if (tid < BN) {
            unsigned* buf = (EPI == 0) ? g_maxxe : g_maxy;
            atomicMax(&buf[(m0 >> 13) * kCh + n0 + tid], red[tid]);
        }
    }
    if (EPI == 0) {
        const int b = m0 >> 13, l0m = m0 & (kSeq - 1);
        __syncthreads();
        for (int i = tid; i < 128 * 128; i += 256) {
            int cidx = i >> 7, l = i & 127;
            g_xeT[((size_t)b * kCh + n0 + cidx) * kSeq + l0m + l] = stage[l * 129 + cidx];
        }
    }
}

// ---------------------------------------------------------------------------
// FFT stages (swizzled smem; first stage peeled with float4 stores).
template <bool INV>
__device__ __forceinline__ void fft_first(const float2* src, float2* dst, const float2* tw) {
    for (int t = threadIdx.x; t < 2048; t += 1024) {
        float2 a0 = src[SWZ(t)];
        float2 a1 = src[SWZ(t + 2048)];
        float2 a2 = src[SWZ(t + 4096)];
        float2 a3 = src[SWZ(t + 6144)];
        float2 t0 = cadd(a0, a2), t1 = csub(a0, a2);
        float2 t2 = cadd(a1, a3), t3 = csub(a1, a3);
        float2 b0 = cadd(t0, t2), b2 = csub(t0, t2);
        float2 b1, b3;
        if (!INV) {
            b1 = make_float2(t1.x + t3.y, t1.y - t3.x);
            b3 = make_float2(t1.x - t3.y, t1.y + t3.x);
        } else {
            b1 = make_float2(t1.x - t3.y, t1.y + t3.x);
            b3 = make_float2(t1.x + t3.y, t1.y - t3.x);
        }
        float2 w1 = tw[t];
        if (INV) w1.y = -w1.y;
        float2 w2 = cmul(w1, w1), w3 = cmul(w2, w1);
        float2 o1 = cmul(w1, b1), o2 = cmul(w2, b2), o3 = cmul(w3, b3);
        float4* d4 = reinterpret_cast<float4*>(dst + SWZ(4 * t));
        d4[0] = make_float4(b0.x, b0.y, o1.x, o1.y);
        d4[1] = make_float4(o2.x, o2.y, o3.x, o3.y);
    }
    __syncthreads();
}

template <bool INV>
__device__ __forceinline__ void fft_stages(float2*& src, float2*& dst, const float2* tw) {
    fft_first<INV>(src, dst, tw);
    { float2* tp = src; src = dst; dst = tp; }
    int nn = 2048, s = 4, ls = 2;
    while (nn > 2) {
        for (int t = threadIdx.x; t < 2048; t += 1024) {
            int q = t & (s - 1), p = t >> ls;
            float2 a0 = src[SWZ(t)];
            float2 a1 = src[SWZ(t + 2048)];
            float2 a2 = src[SWZ(t + 4096)];
            float2 a3 = src[SWZ(t + 6144)];
            float2 t0 = cadd(a0, a2), t1 = csub(a0, a2);
            float2 t2 = cadd(a1, a3), t3 = csub(a1, a3);
            float2 b0 = cadd(t0, t2), b2 = csub(t0, t2);
            float2 b1, b3;
            if (!INV) {
                b1 = make_float2(t1.x + t3.y, t1.y - t3.x);
                b3 = make_float2(t1.x - t3.y, t1.y + t3.x);
            } else {
                b1 = make_float2(t1.x - t3.y, t1.y + t3.x);
                b3 = make_float2(t1.x + t3.y, t1.y - t3.x);
            }
            float2 w1 = tw[p << ls];
            if (INV) w1.y = -w1.y;
            float2 w2 = cmul(w1, w1), w3 = cmul(w2, w1);
            int o = q + (p << (ls + 2));
            dst[SWZ(o)]         = b0;
            dst[SWZ(o + s)]     = cmul(w1, b1);
            dst[SWZ(o + 2 * s)] = cmul(w2, b2);
            dst[SWZ(o + 3 * s)] = cmul(w3, b3);
        }
        __syncthreads();
        float2* tp = src; src = dst; dst = tp;
        nn >>= 2; s <<= 2; ls += 2;
    }
    for (int t = threadIdx.x; t < 4096; t += 1024) {
        float2 a = src[SWZ(t)], b = src[SWZ(t + 4096)];
        dst[SWZ(t)]        = cadd(a, b);
        dst[SWZ(t + 4096)] = csub(a, b);
    }
    __syncthreads();
    float2* tp = src; src = dst; dst = tp;
}

// One CTA per (b,c) row: real-16384 causal conv via packed complex-8192 FFT.
// Reads g_xeT (preserved); writes y1T = gelu(h1T + h0*xeT) to g_y1.
__global__ __launch_bounds__(1024, 1) void fftconv_kernel(const float* __restrict__ h0p) {
    extern __shared__ float2 sm[];
    float2* tw8  = sm;
    float2* tw16 = sm + 4096;
    float2* b0   = sm + 8194;          // 16B-aligned
    float2* b1   = b0 + kN2;
    for (int i = threadIdx.x; i < 4097; i += 1024) {
        if (i < 4096) tw8[i] = g_tw8[i];
        tw16[i] = g_tw16[i];
    }
    const int r = blockIdx.x, c = r & (kCh - 1);
    const float2* row2 = reinterpret_cast<const float2*>(g_xeT + (size_t)r * kSeq);
    for (int n = threadIdx.x; n < kN2; n += 1024)
        b0[SWZ(n)] = (n < 4096) ? row2[n] : make_float2(0.f, 0.f);
    __syncthreads();

    float2 *src = b0, *dst = b1;
    fft_stages<false>(src, dst, tw8);

    const float2* Kfc = g_Kf + (size_t)c * kNF;
    for (int k = threadIdx.x; k <= 4096; k += 1024) {
        int j = (kN2 - k) & (kN2 - 1);
        float2 Zk = src[SWZ(k)], Zj = src[SWZ(j)];
        float2 E = make_float2(0.5f * (Zk.x + Zj.x), 0.5f * (Zk.y - Zj.y));
        float2 O = make_float2(0.5f * (Zk.y + Zj.y), -0.5f * (Zk.x - Zj.x));
        float2 w = tw16[k];
        float2 wO = cmul(w, O);
        float2 Xk = make_float2(E.x + wO.x, E.y + wO.y);
        float2 Xj = make_float2(E.x - wO.x, -(E.y - wO.y));
        float2 Yk = cmul(Xk, Kfc[k]);
        float2 Yj = cmul(Xj, Kfc[kN2 - k]);
        float2 Ey = make_float2(0.5f * (Yk.x + Yj.x), 0.5f * (Yk.y - Yj.y));
        float2 Dy = make_float2(0.5f * (Yk.x - Yj.x), 0.5f * (Yk.y + Yj.y));
        float2 Oy = cmul(make_float2(w.x, -w.y), Dy);
        dst[SWZ(k)] = make_float2(Ey.x - Oy.y, Ey.y + Oy.x);
        if (k >= 1 && k < 4096) {
            float2 Em = make_float2(0.5f * (Yj.x + Yk.x), 0.5f * (Yj.y - Yk.y));
            float2 Dm = make_float2(0.5f * (Yj.x - Yk.x), 0.5f * (Yj.y + Yk.y));
            float2 Om = cmul(make_float2(-w.x, -w.y), Dm);
            dst[SWZ(kN2 - k)] = make_float2(Em.x - Om.y, Em.y + Om.x);
        }
    }
    __syncthreads();
    { float2* tp = src; src = dst; dst = tp; }

    fft_stages<true>(src, dst, tw8);

    const float h0v = h0p[0];
    float2* y1row = reinterpret_cast<float2*>(g_y1 + (size_t)r * kSeq);
    for (int n = threadIdx.x; n < 4096; n += 1024) {
        float2 v = src[SWZ(n)];
        float2 e = row2[n];
        y1row[n] = make_float2(gelu_exact(v.x + h0v * e.x),
                               gelu_exact(v.y + h0v * e.y));
    }
}

// LayerNorm over channels, in place on g_y2. One warp per row.
__global__ __launch_bounds__(256) void ln_kernel(const float* __restrict__ gamma,
                                                 const float* __restrict__ beta) {
    int warp = threadIdx.x >> 5, lane = threadIdx.x & 31;
    size_t row = (size_t)blockIdx.x * 8 + warp;
    float4* p = reinterpret_cast<float4*>(g_y2 + row * kCh);
    float4 v0 = p[lane], v1 = p[lane + 32];
    float s = v0.x + v0.y + v0.z + v0.w + v1.x + v1.y + v1.z + v1.w;
    float q = v0.x * v0.x + v0.y * v0.y + v0.z * v0.z + v0.w * v0.w
            + v1.x * v1.x + v1.y * v1.y + v1.z * v1.z + v1.w * v1.w;
#pragma unroll
    for (int o = 16; o; o >>= 1) {
        s += __shfl_xor_sync(0xffffffffu, s, o);
        q += __shfl_xor_sync(0xffffffffu, q, o);
    }
    float mu = s * (1.f / 256.f);
    float rstd = rsqrtf(q * (1.f / 256.f) - mu * mu + 1e-5f);
    const float4* g4 = reinterpret_cast<const float4*>(gamma);
    const float4* e4 = reinterpret_cast<const float4*>(beta);
    float4 g0 = g4[lane], g1 = g4[lane + 32], e0 = e4[lane], e1 = e4[lane + 32];
    v0.x = (v0.x - mu) * rstd * g0.x + e0.x; v0.y = (v0.y - mu) * rstd * g0.y + e0.y;
    v0.z = (v0.z - mu) * rstd * g0.z + e0.z; v0.w = (v0.w - mu) * rstd * g0.w + e0.w;
    v1.x = (v1.x - mu) * rstd * g1.x + e1.x; v1.y = (v1.y - mu) * rstd * g1.y + e1.y;
    v1.z = (v1.z - mu) * rstd * g1.z + e1.z; v1.w = (v1.w - mu) * rstd * g1.w + e1.w;
    p[lane] = v0; p[lane + 32] = v1;
}

__global__ void hout_kernel(float* __restrict__ h) {
    int i = blockIdx.x * 256 + threadIdx.x;
    if (i < kB * kCh)
        h[i] = __uint_as_float(g_maxy[i]) / (__uint_as_float(g_maxxe[i]) + 1e-6f);
}

extern "C" void kernel_launch(void* const* d_in, const int* in_sizes, int n_in,
                              void* d_out, int out_size) {
    const float* x     = (const float*)d_in[0];
    const float* A     = (const float*)d_in[1];
    const float* Bp    = (const float*)d_in[2];
    const float* h0    = (const float*)d_in[3];
    const float* W_enc = (const float*)d_in[4];
    const float* b_enc = (const float*)d_in[5];
    const float* W_fc  = (const float*)d_in[6];
    const float* b_fc  = (const float*)d_in[7];
    const float* gamma = (const float*)d_in[8];
    const float* beta  = (const float*)d_in[9];
    const float* W_dec = (const float*)d_in[10];
    const float* b_dec = (const float*)d_in[11];
    float* out = (float*)d_out;

    static cudaStream_t side = nullptr;
    static cudaEvent_t evFork = nullptr, evJoin = nullptr;
    static bool attrsSet = false;
    if (!side) {
        cudaStreamCreateWithFlags(&side, cudaStreamNonBlocking);
        cudaEventCreateWithFlags(&evFork, cudaEventDisableTiming);
        cudaEventCreateWithFlags(&evJoin, cudaEventDisableTiming);
    }
    const int kSmemFFT = 24578 * 8;   // 196624 B dynamic SMEM
    if (!attrsSet) {
        cudaFuncSetAttribute(fftconv_kernel, cudaFuncAttributeMaxDynamicSharedMemorySize, kSmemFFT);
        cudaFuncSetAttribute(gemm_kernel<0>, cudaFuncAttributeMaxDynamicSharedMemorySize, kGemmSmem0);
        cudaFuncSetAttribute(gemm_kernel<1>, cudaFuncAttributeMaxDynamicSharedMemorySize, kGemmSmem1);
        cudaFuncSetAttribute(gemm_kernel<2>, cudaFuncAttributeMaxDynamicSharedMemorySize, kGemmSmem2);
        attrsSet = true;
    }

    // Fork: twiddle + kfgen run on the side stream, overlapping gemm<0>.
    cudaEventRecord(evFork, 0);
    cudaStreamWaitEvent(side, evFork, 0);
    twiddle_kernel<<<17, 256, 0, side>>>();
    kfgen_kernel<<<dim3(33, kCh), 256, 0, side>>>(A, Bp);
    cudaEventRecord(evJoin, side);

    zero_kernel<<<8, 256>>>();
    wsplit_kernel<<<dim3(kCh * kCh / 256, 3), 256>>>(W_enc, W_fc, W_dec);
    gemm_kernel<0><<<dim3(kM / 128, 2), 256, kGemmSmem0>>>(x, b_enc, nullptr);
    cudaStreamWaitEvent(0, evJoin, 0);
    fftconv_kernel<<<kB * kCh, 1024, kSmemFFT>>>(h0);
    gemm_kernel<1><<<dim3(kM / 128, 2), 256, kGemmSmem1>>>(nullptr, b_fc, nullptr);
    ln_kernel<<<kM / 8, 256>>>(gamma, beta);
    gemm_kernel<2><<<dim3(kM / 128, 2), 256, kGemmSmem2>>>(nullptr, b_dec, out);
    hout_kernel<<<8, 256>>>(out + (size_t)kM * kCh);
}

// round 13
// speedup vs baseline: 1.9891x; 1.0755x over previous
#include <cuda_runtime.h>
#include <cuda_bf16.h>

constexpr int kB = 8, kSeq = 8192, kCh = 256;
constexpr int kM  = kB * kSeq;          // 65536
constexpr int kN2 = 8192;               // complex FFT size (real 16384)
constexpr int kNF = 8193;               // rfft bins of 16384

__device__ __align__(128) float  g_xe [kM * kCh];   // (B,L,C)
__device__ __align__(128) float  g_xeT[kM * kCh];   // (B,C,L), preserved
__device__ __align__(128) float  g_y1 [kM * kCh];   // (B,C,L)  y1T
__device__ __align__(128) float  g_y2 [kM * kCh];   // (B,L,C)
__device__ __align__(128) float2 g_Kf [(size_t)kCh * kNF];
__device__ __align__(128) __nv_bfloat16 g_Wh[3 * kCh * kCh];
__device__ __align__(128) __nv_bfloat16 g_Wl[3 * kCh * kCh];
__device__ float2 g_tw8 [4096];
__device__ float2 g_tw16[4097];
__device__ unsigned g_maxxe[kB * kCh];
__device__ unsigned g_maxy [kB * kCh];

#define SWZ(i) ((i) ^ ((((i) >> 4) & 3) << 2))

__device__ __forceinline__ float2 cmul(float2 a, float2 b) {
    return make_float2(a.x * b.x - a.y * b.y, a.x * b.y + a.y * b.x);
}
__device__ __forceinline__ float2 cadd(float2 a, float2 b) {
    return make_float2(a.x + b.x, a.y + b.y);
}
__device__ __forceinline__ float2 csub(float2 a, float2 b) {
    return make_float2(a.x - b.x, a.y - b.y);
}
__device__ __forceinline__ float gelu_exact(float v) {
    return 0.5f * v * (1.0f + erff(v * 0.7071067811865476f));
}
__device__ __forceinline__ void ldsm4(unsigned* r, const void* p) {
    unsigned addr = (unsigned)__cvta_generic_to_shared(p);
    asm volatile("ldmatrix.sync.aligned.m8n8.x4.shared.b16 {%0,%1,%2,%3}, [%4];"
                 : "=r"(r[0]), "=r"(r[1]), "=r"(r[2]), "=r"(r[3]) : "r"(addr));
}
__device__ __forceinline__ void ldsm4t(unsigned* r, const void* p) {
    unsigned addr = (unsigned)__cvta_generic_to_shared(p);
    asm volatile("ldmatrix.sync.aligned.m8n8.x4.trans.shared.b16 {%0,%1,%2,%3}, [%4];"
                 : "=r"(r[0]), "=r"(r[1]), "=r"(r[2]), "=r"(r[3]) : "r"(addr));
}
__device__ __forceinline__ void mma16816(float* d, const unsigned* a, const unsigned* b) {
    asm volatile("mma.sync.aligned.m16n8k16.row.col.f32.bf16.bf16.f32 "
                 "{%0,%1,%2,%3}, {%4,%5,%6,%7}, {%8,%9}, {%0,%1,%2,%3};"
                 : "+f"(d[0]), "+f"(d[1]), "+f"(d[2]), "+f"(d[3])
                 : "r"(a[0]), "r"(a[1]), "r"(a[2]), "r"(a[3]), "r"(b[0]), "r"(b[1]));
}
__device__ __forceinline__ void cpasync16(void* smem_dst, const void* gsrc) {
    unsigned a = (unsigned)__cvta_generic_to_shared(smem_dst);
    asm volatile("cp.async.cg.shared.global [%0], [%1], 16;" :: "r"(a), "l"(gsrc));
}
#define CP_COMMIT() asm volatile("cp.async.commit_group;")
#define CP_WAIT0()  asm volatile("cp.async.wait_group 0;")

__global__ void zero_kernel() {
    int i = blockIdx.x * 256 + threadIdx.x;
    if (i < kB * kCh) { g_maxxe[i] = 0u; g_maxy[i] = 0u; }
}

__global__ void twiddle_kernel() {
    int i = blockIdx.x * 256 + threadIdx.x;
    float s, c;
    if (i < 4096) { sincospif(-2.0f * i / 8192.0f,  &s, &c); g_tw8 [i] = make_float2(c, s); }
    if (i < 4097) { sincospif(-2.0f * i / 16384.0f, &s, &c); g_tw16[i] = make_float2(c, s); }
}

__global__ void wsplit_kernel(const float* __restrict__ We, const float* __restrict__ Wf,
                              const float* __restrict__ Wd) {
    int i = blockIdx.x * 256 + threadIdx.x;
    const float* src = (blockIdx.y == 0) ? We : (blockIdx.y == 1 ? Wf : Wd);
    float v = src[i];
    __nv_bfloat16 h = __float2bfloat16(v);
    g_Wh[blockIdx.y * kCh * kCh + i] = h;
    g_Wl[blockIdx.y * kCh * kCh + i] = __float2bfloat16(v - __bfloat162float(h));
}

// Kf[c][k] = B(w)/A(w)/8192 (IIR tail underflows fp32 beyond n=8192).
__global__ __launch_bounds__(256) void kfgen_kernel(const float* __restrict__ A,
                                                    const float* __restrict__ Bp) {
    __shared__ float sA[64], sB[64];
    int c = blockIdx.y;
    if (threadIdx.x < 64)       sA[threadIdx.x]      = A [c * 64 + threadIdx.x];
    else if (threadIdx.x < 128) sB[threadIdx.x - 64] = Bp[c * 64 + threadIdx.x - 64];
    __syncthreads();
    int k = blockIdx.x * 256 + threadIdx.x;
    if (k >= kNF) return;
    float sv, cv;
    sincospif(-(float)k / 8192.0f, &sv, &cv);
    float2 w  = make_float2(cv, sv);
    float2 w2 = cmul(w, w);
    float2 ae = make_float2(sA[63], 0.f);
    float2 ao = make_float2(sA[62], 0.f);
    float2 be = make_float2(sB[62], 0.f);
    float2 bo = make_float2(sB[63], 0.f);
#pragma unroll 4
    for (int i = 31; i >= 1; --i) {
        ae = cmul(ae, w2); ae.x += sA[2 * i - 1];
        ao = cmul(ao, w2); ao.x += sA[2 * i - 2];
        be = cmul(be, w2); be.x += sB[2 * i - 2];
        bo = cmul(bo, w2); bo.x += sB[2 * i - 1];
    }
    ae = cmul(ae, w2); ae.x += 1.0f;
    float2 av = cadd(ae, cmul(w, ao));
    float2 bv = cadd(be, cmul(w, bo));
    float scl = (1.0f / 8192.0f) / (av.x * av.x + av.y * av.y);
    g_Kf[(size_t)c * kNF + k] = make_float2((bv.x * av.x + bv.y * av.y) * scl,
                                            (bv.y * av.x - bv.x * av.y) * scl);
}

// ---------------------------------------------------------------------------
// Tensor-core GEMM (3-pass bf16 split), software-pipelined:
// double-buffered smem, A via register prefetch, W via cp.async, 1 sync/iter.
constexpr int kGemmSmem = 81920 + 512;    // 2x(Ah,Al,Bh,Bl) + red

template <int EPI>
__global__ __launch_bounds__(256, 2) void gemm_kernel(const float* __restrict__ Ain,
                                                      const float* __restrict__ bias,
                                                      float* __restrict__ Cout) {
    constexpr int BM = 128, BN = 128, BK = 32, LDS = 40, LDT = 136;
    extern __shared__ __align__(16) unsigned char smem_raw[];
    unsigned* red = reinterpret_cast<unsigned*>(smem_raw + 81920);
    const float* Ap = (EPI == 1) ? g_y1 : (EPI == 2 ? g_y2 : Ain);
    float*       Cp = (EPI == 0) ? g_xe : (EPI == 1 ? g_y2 : Cout);
    const __nv_bfloat16* Whp = g_Wh + EPI * kCh * kCh;
    const __nv_bfloat16* Wlp = g_Wl + EPI * kCh * kCh;
    const int m0 = blockIdx.x * BM, n0 = blockIdx.y * BN;
    const int tid = threadIdx.x, lane = tid & 31, warp = tid >> 5;
    const int wr = warp >> 1, wc = warp & 1;
    const int bB = m0 >> 13, l0m = m0 & (kSeq - 1);

    if (EPI != 1 && tid < BN) red[tid] = 0u;

    float acc[2][8][4];
#pragma unroll
    for (int mt = 0; mt < 2; ++mt)
#pragma unroll
        for (int nt = 0; nt < 8; ++nt)
#pragma unroll
            for (int r = 0; r < 4; ++r) acc[mt][nt][r] = 0.f;

    auto ldgA = [&](int kt, float4* ra) {
#pragma unroll
        for (int u = 0; u < 4; ++u) {
            int idx = u * 256 + tid;
            if (EPI == 1) {
                int ch = idx >> 5, mg = (idx & 31) * 4;
                ra[u] = *reinterpret_cast<const float4*>(
                    Ap + ((size_t)bB * kCh + kt + ch) * kSeq + l0m + mg);
            } else {
                int row = idx >> 3, c4 = (idx & 7) * 4;
                ra[u] = *reinterpret_cast<const float4*>(
                    Ap + (size_t)(m0 + row) * kCh + kt + c4);
            }
        }
    };
    auto stA = [&](int buf, const float4* ra) {
#pragma unroll
        for (int u = 0; u < 4; ++u) {
            int idx = u * 256 + tid;
            float4 v = ra[u];
            __nv_bfloat162 h01 = __floats2bfloat162_rn(v.x, v.y);
            __nv_bfloat162 h23 = __floats2bfloat162_rn(v.z, v.w);
            __nv_bfloat162 l01 = __floats2bfloat162_rn(v.x - __low2float(h01),
                                                       v.y - __high2float(h01));
            __nv_bfloat162 l23 = __floats2bfloat162_rn(v.z - __low2float(h23),
                                                       v.w - __high2float(h23));
            uint2 hv = make_uint2(*reinterpret_cast<unsigned*>(&h01),
                                  *reinterpret_cast<unsigned*>(&h23));
            uint2 lv = make_uint2(*reinterpret_cast<unsigned*>(&l01),
                                  *reinterpret_cast<unsigned*>(&l23));
            if (EPI == 1) {
                int ch = idx >> 5, mg = (idx & 31) * 4;
                auto Ath = reinterpret_cast<__nv_bfloat16(*)[LDT]>(smem_raw + buf * 8704);
                auto Atl = reinterpret_cast<__nv_bfloat16(*)[LDT]>(smem_raw + 20480 + buf * 8704);
                *reinterpret_cast<uint2*>(&Ath[ch][mg]) = hv;
                *reinterpret_cast<uint2*>(&Atl[ch][mg]) = lv;
            } else {
                int row = idx >> 3, c4 = (idx & 7) * 4;
                auto Ah = reinterpret_cast<__nv_bfloat16(*)[LDS]>(smem_raw + buf * 10240);
                auto Al = reinterpret_cast<__nv_bfloat16(*)[LDS]>(smem_raw + 20480 + buf * 10240);
                *reinterpret_cast<uint2*>(&Ah[row][c4]) = hv;
                *reinterpret_cast<uint2*>(&Al[row][c4]) = lv;
            }
        }
    };
    auto cpW = [&](int kt, int buf) {
        auto Bh = reinterpret_cast<__nv_bfloat16(*)[LDS]>(smem_raw + 40960 + buf * 10240);
        auto Bl = reinterpret_cast<__nv_bfloat16(*)[LDS]>(smem_raw + 61440 + buf * 10240);
#pragma unroll
        for (int u = 0; u < 2; ++u) {
            int idx = u * 256 + tid;
            int row = idx >> 2, c8 = (idx & 3) * 8;
            cpasync16(&Bh[row][c8], Whp + (size_t)(n0 + row) * kCh + kt + c8);
            cpasync16(&Bl[row][c8], Wlp + (size_t)(n0 + row) * kCh + kt + c8);
        }
    };

    float4 ra[4];
    ldgA(0, ra);
    cpW(0, 0);
    CP_COMMIT();

    for (int it = 0; it < 8; ++it) {
        const int cur = it & 1;
        stA(cur, ra);
        if (it < 7) ldgA((it + 1) * BK, ra);
        CP_WAIT0();
        __syncthreads();
        if (it < 7) { cpW((it + 1) * BK, cur ^ 1); CP_COMMIT(); }

        auto Ah  = reinterpret_cast<__nv_bfloat16(*)[LDS]>(smem_raw + cur * 10240);
        auto Al  = reinterpret_cast<__nv_bfloat16(*)[LDS]>(smem_raw + 20480 + cur * 10240);
        auto Ath = reinterpret_cast<__nv_bfloat16(*)[LDT]>(smem_raw + cur * 8704);
        auto Atl = reinterpret_cast<__nv_bfloat16(*)[LDT]>(smem_raw + 20480 + cur * 8704);
        auto Bh  = reinterpret_cast<__nv_bfloat16(*)[LDS]>(smem_raw + 40960 + cur * 10240);
        auto Bl  = reinterpret_cast<__nv_bfloat16(*)[LDS]>(smem_raw + 61440 + cur * 10240);
#pragma unroll
        for (int ks = 0; ks < 2; ++ks) {
            const int kb = ks * 16;
            unsigned ah[2][4], al[2][4];
#pragma unroll
            for (int mt = 0; mt < 2; ++mt) {
                if (EPI == 1) {
                    int krow = kb + ((lane >> 4) << 3) + (lane & 7);
                    int mcol = wr * 32 + mt * 16 + (((lane >> 3) & 1) << 3);
                    ldsm4t(ah[mt], &Ath[krow][mcol]);
                    ldsm4t(al[mt], &Atl[krow][mcol]);
                } else {
                    int arow = wr * 32 + mt * 16 + (lane & 15);
                    int koff = kb + ((lane >> 4) << 3);
                    ldsm4(ah[mt], &Ah[arow][koff]);
                    ldsm4(al[mt], &Al[arow][koff]);
                }
            }
#pragma unroll
            for (int g = 0; g < 4; ++g) {
                int nrow = wc * 64 + g * 16 + (lane & 7) + ((lane >> 4) << 3);
                int koff = kb + (((lane >> 3) & 1) << 3);
                unsigned bh[4], bl[4];
                ldsm4(bh, &Bh[nrow][koff]);
                ldsm4(bl, &Bl[nrow][koff]);
#pragma unroll
                for (int mt = 0; mt < 2; ++mt) {
                    mma16816(acc[mt][2 * g],     ah[mt], bh);
                    mma16816(acc[mt][2 * g],     ah[mt], bl);
                    mma16816(acc[mt][2 * g],     al[mt], bh);
                    mma16816(acc[mt][2 * g + 1], ah[mt], bh + 2);
                    mma16816(acc[mt][2 * g + 1], ah[mt], bl + 2);
                    mma16816(acc[mt][2 * g + 1], al[mt], bh + 2);
                }
            }
        }
    }
    __syncthreads();   // all mma done before smem reuse (EPI0 stage)

    float* stage = reinterpret_cast<float*>(smem_raw);     // [128][129], EPI==0 only
#pragma unroll
    for (int mt = 0; mt < 2; ++mt) {
        int r0 = m0 + wr * 32 + mt * 16 + (lane >> 2);
#pragma unroll
        for (int nt = 0; nt < 8; ++nt) {
            int col = n0 + wc * 64 + nt * 8 + (lane & 3) * 2;
            float* c = acc[mt][nt];
            float2 bv = *reinterpret_cast<const float2*>(bias + col);
            float v0 = c[0] + bv.x, v1 = c[1] + bv.y;
            float v2 = c[2] + bv.x, v3 = c[3] + bv.y;
            if (EPI == 1) {
                float2 s0 = *reinterpret_cast<const float2*>(g_xe + (size_t)r0 * kCh + col);
                float2 s1 = *reinterpret_cast<const float2*>(g_xe + (size_t)(r0 + 8) * kCh + col);
                v0 = gelu_exact(v0) + s0.x; v1 = gelu_exact(v1) + s0.y;
                v2 = gelu_exact(v2) + s1.x; v3 = gelu_exact(v3) + s1.y;
            } else {
                float me = fmaxf(fabsf(v0), fabsf(v2));
                float mo = fmaxf(fabsf(v1), fabsf(v3));
#pragma unroll
                for (int o = 4; o < 32; o <<= 1) {
                    me = fmaxf(me, __shfl_xor_sync(0xffffffffu, me, o));
                    mo = fmaxf(mo, __shfl_xor_sync(0xffffffffu, mo, o));
                }
                if (lane < 4) {
                    atomicMax(&red[col - n0],     __float_as_uint(me));
                    atomicMax(&red[col - n0 + 1], __float_as_uint(mo));
                }
            }
            if (EPI == 0) {
                int lr = r0 - m0, lc = col - n0;
                stage[lr * 129 + lc]           = v0;
                stage[lr * 129 + lc + 1]       = v1;
                stage[(lr + 8) * 129 + lc]     = v2;
                stage[(lr + 8) * 129 + lc + 1] = v3;
            }
            *reinterpret_cast<float2*>(Cp + (size_t)r0 * kCh + col)       = make_float2(v0, v1);
            *reinterpret_cast<float2*>(Cp + (size_t)(r0 + 8) * kCh + col) = make_float2(v2, v3);
        }
    }
    if (EPI != 1) {
        __syncthreads();
        if (tid < BN) {
            unsigned* buf = (EPI == 0) ? g_maxxe : g_maxy;
            atomicMax(&buf[(m0 >> 13) * kCh + n0 + tid], red[tid]);
        }
    }
    if (EPI == 0) {
        __syncthreads();
        for (int i = tid; i < 128 * 128; i += 256) {
            int cidx = i >> 7, l = i & 127;
            g_xeT[((size_t)bB * kCh + n0 + cidx) * kSeq + l0m + l] = stage[l * 129 + cidx];
        }
    }
}

// ---------------------------------------------------------------------------
// FFT stages (swizzled smem; first stage peeled with float4 stores).
template <bool INV>
__device__ __forceinline__ void fft_first(const float2* src, float2* dst, const float2* tw) {
    for (int t = threadIdx.x; t < 2048; t += 1024) {
        float2 a0 = src[SWZ(t)];
        float2 a1 = src[SWZ(t + 2048)];
        float2 a2 = src[SWZ(t + 4096)];
        float2 a3 = src[SWZ(t + 6144)];
        float2 t0 = cadd(a0, a2), t1 = csub(a0, a2);
        float2 t2 = cadd(a1, a3), t3 = csub(a1, a3);
        float2 b0 = cadd(t0, t2), b2 = csub(t0, t2);
        float2 b1, b3;
        if (!INV) {
            b1 = make_float2(t1.x + t3.y, t1.y - t3.x);
            b3 = make_float2(t1.x - t3.y, t1.y + t3.x);
        } else {
            b1 = make_float2(t1.x - t3.y, t1.y + t3.x);
            b3 = make_float2(t1.x + t3.y, t1.y - t3.x);
        }
        float2 w1 = tw[t];
        if (INV) w1.y = -w1.y;
        float2 w2 = cmul(w1, w1), w3 = cmul(w2, w1);
        float2 o1 = cmul(w1, b1), o2 = cmul(w2, b2), o3 = cmul(w3, b3);
        float4* d4 = reinterpret_cast<float4*>(dst + SWZ(4 * t));
        d4[0] = make_float4(b0.x, b0.y, o1.x, o1.y);
        d4[1] = make_float4(o2.x, o2.y, o3.x, o3.y);
    }
    __syncthreads();
}

template <bool INV>
__device__ __forceinline__ void fft_stages(float2*& src, float2*& dst, const float2* tw) {
    fft_first<INV>(src, dst, tw);
    { float2* tp = src; src = dst; dst = tp; }
    int nn = 2048, s = 4, ls = 2;
    while (nn > 2) {
        for (int t = threadIdx.x; t < 2048; t += 1024) {
            int q = t & (s - 1), p = t >> ls;
            float2 a0 = src[SWZ(t)];
            float2 a1 = src[SWZ(t + 2048)];
            float2 a2 = src[SWZ(t + 4096)];
            float2 a3 = src[SWZ(t + 6144)];
            float2 t0 = cadd(a0, a2), t1 = csub(a0, a2);
            float2 t2 = cadd(a1, a3), t3 = csub(a1, a3);
            float2 b0 = cadd(t0, t2), b2 = csub(t0, t2);
            float2 b1, b3;
            if (!INV) {
                b1 = make_float2(t1.x + t3.y, t1.y - t3.x);
                b3 = make_float2(t1.x - t3.y, t1.y + t3.x);
            } else {
                b1 = make_float2(t1.x - t3.y, t1.y + t3.x);
                b3 = make_float2(t1.x + t3.y, t1.y - t3.x);
            }
            float2 w1 = tw[p << ls];
            if (INV) w1.y = -w1.y;
            float2 w2 = cmul(w1, w1), w3 = cmul(w2, w1);
            int o = q + (p << (ls + 2));
            dst[SWZ(o)]         = b0;
            dst[SWZ(o + s)]     = cmul(w1, b1);
            dst[SWZ(o + 2 * s)] = cmul(w2, b2);
            dst[SWZ(o + 3 * s)] = cmul(w3, b3);
        }
        __syncthreads();
        float2* tp = src; src = dst; dst = tp;
        nn >>= 2; s <<= 2; ls += 2;
    }
    for (int t = threadIdx.x; t < 4096; t += 1024) {
        float2 a = src[SWZ(t)], b = src[SWZ(t + 4096)];
        dst[SWZ(t)]        = cadd(a, b);
        dst[SWZ(t + 4096)] = csub(a, b);
    }
    __syncthreads();
    float2* tp = src; src = dst; dst = tp;
}

// One CTA per (b,c) row; writes y1T = gelu(h1T + h0*xeT) to g_y1.
__global__ __launch_bounds__(1024, 1) void fftconv_kernel(const float* __restrict__ h0p) {
    extern __shared__ float2 sm[];
    float2* tw8  = sm;
    float2* tw16 = sm + 4096;
    float2* b0   = sm + 8194;
    float2* b1   = b0 + kN2;
    for (int i = threadIdx.x; i < 4097; i += 1024) {
        if (i < 4096) tw8[i] = g_tw8[i];
        tw16[i] = g_tw16[i];
    }
    const int r = blockIdx.x, c = r & (kCh - 1);
    const float2* row2 = reinterpret_cast<const float2*>(g_xeT + (size_t)r * kSeq);
    for (int n = threadIdx.x; n < kN2; n += 1024)
        b0[SWZ(n)] = (n < 4096) ? row2[n] : make_float2(0.f, 0.f);
    __syncthreads();

    float2 *src = b0, *dst = b1;
    fft_stages<false>(src, dst, tw8);

    const float2* Kfc = g_Kf + (size_t)c * kNF;
    for (int k = threadIdx.x; k <= 4096; k += 1024) {
        int j = (kN2 - k) & (kN2 - 1);
        float2 Zk = src[SWZ(k)], Zj = src[SWZ(j)];
        float2 E = make_float2(0.5f * (Zk.x + Zj.x), 0.5f * (Zk.y - Zj.y));
        float2 O = make_float2(0.5f * (Zk.y + Zj.y), -0.5f * (Zk.x - Zj.x));
        float2 w = tw16[k];
        float2 wO = cmul(w, O);
        float2 Xk = make_float2(E.x + wO.x, E.y + wO.y);
        float2 Xj = make_float2(E.x - wO.x, -(E.y - wO.y));
        float2 Yk = cmul(Xk, Kfc[k]);
        float2 Yj = cmul(Xj, Kfc[kN2 - k]);
        float2 Ey = make_float2(0.5f * (Yk.x + Yj.x), 0.5f * (Yk.y - Yj.y));
        float2 Dy = make_float2(0.5f * (Yk.x - Yj.x), 0.5f * (Yk.y + Yj.y));
        float2 Oy = cmul(make_float2(w.x, -w.y), Dy);
        dst[SWZ(k)] = make_float2(Ey.x - Oy.y, Ey.y + Oy.x);
        if (k >= 1 && k < 4096) {
            float2 Em = make_float2(0.5f * (Yj.x + Yk.x), 0.5f * (Yj.y - Yk.y));
            float2 Dm = make_float2(0.5f * (Yj.x - Yk.x), 0.5f * (Yj.y + Yk.y));
            float2 Om = cmul(make_float2(-w.x, -w.y), Dm);
            dst[SWZ(kN2 - k)] = make_float2(Em.x - Om.y, Em.y + Om.x);
        }
    }
    __syncthreads();
    { float2* tp = src; src = dst; dst = tp; }

    fft_stages<true>(src, dst, tw8);

    const float h0v = h0p[0];
    float2* y1row = reinterpret_cast<float2*>(g_y1 + (size_t)r * kSeq);
    for (int n = threadIdx.x; n < 4096; n += 1024) {
        float2 v = src[SWZ(n)];
        float2 e = row2[n];
        y1row[n] = make_float2(gelu_exact(v.x + h0v * e.x),
                               gelu_exact(v.y + h0v * e.y));
    }
}

// LayerNorm over channels, in place on g_y2. One warp per row.
__global__ __launch_bounds__(256) void ln_kernel(const float* __restrict__ gamma,
                                                 const float* __restrict__ beta) {
    int warp = threadIdx.x >> 5, lane = threadIdx.x & 31;
    size_t row = (size_t)blockIdx.x * 8 + warp;
    float4* p = reinterpret_cast<float4*>(g_y2 + row * kCh);
    float4 v0 = p[lane], v1 = p[lane + 32];
    float s = v0.x + v0.y + v0.z + v0.w + v1.x + v1.y + v1.z + v1.w;
    float q = v0.x * v0.x + v0.y * v0.y + v0.z * v0.z + v0.w * v0.w
            + v1.x * v1.x + v1.y * v1.y + v1.z * v1.z + v1.w * v1.w;
#pragma unroll
    for (int o = 16; o; o >>= 1) {
        s += __shfl_xor_sync(0xffffffffu, s, o);
        q += __shfl_xor_sync(0xffffffffu, q, o);
    }
    float mu = s * (1.f / 256.f);
    float rstd = rsqrtf(q * (1.f / 256.f) - mu * mu + 1e-5f);
    const float4* g4 = reinterpret_cast<const float4*>(gamma);
    const float4* e4 = reinterpret_cast<const float4*>(beta);
    float4 g0 = g4[lane], g1 = g4[lane + 32], e0 = e4[lane], e1 = e4[lane + 32];
    v0.x = (v0.x - mu) * rstd * g0.x + e0.x; v0.y = (v0.y - mu) * rstd * g0.y + e0.y;
    v0.z = (v0.z - mu) * rstd * g0.z + e0.z; v0.w = (v0.w - mu) * rstd * g0.w + e0.w;
    v1.x = (v1.x - mu) * rstd * g1.x + e1.x; v1.y = (v1.y - mu) * rstd * g1.y + e1.y;
    v1.z = (v1.z - mu) * rstd * g1.z + e1.z; v1.w = (v1.w - mu) * rstd * g1.w + e1.w;
    p[lane] = v0; p[lane + 32] = v1;
}

__global__ void hout_kernel(float* __restrict__ h) {
    int i = blockIdx.x * 256 + threadIdx.x;
    if (i < kB * kCh)
        h[i] = __uint_as_float(g_maxy[i]) / (__uint_as_float(g_maxxe[i]) + 1e-6f);
}

extern "C" void kernel_launch(void* const* d_in, const int* in_sizes, int n_in,
                              void* d_out, int out_size) {
    const float* x     = (const float*)d_in[0];
    const float* A     = (const float*)d_in[1];
    const float* Bp    = (const float*)d_in[2];
    const float* h0    = (const float*)d_in[3];
    const float* W_enc = (const float*)d_in[4];
    const float* b_enc = (const float*)d_in[5];
    const float* W_fc  = (const float*)d_in[6];
    const float* b_fc  = (const float*)d_in[7];
    const float* gamma = (const float*)d_in[8];
    const float* beta  = (const float*)d_in[9];
    const float* W_dec = (const float*)d_in[10];
    const float* b_dec = (const float*)d_in[11];
    float* out = (float*)d_out;

    static cudaStream_t side = nullptr;
    static cudaEvent_t evFork = nullptr, evJoin = nullptr;
    static bool attrsSet = false;
    if (!side) {
        cudaStreamCreateWithFlags(&side, cudaStreamNonBlocking);
        cudaEventCreateWithFlags(&evFork, cudaEventDisableTiming);
        cudaEventCreateWithFlags(&evJoin, cudaEventDisableTiming);
    }
    const int kSmemFFT = 24578 * 8;   // 196624 B dynamic SMEM
    if (!attrsSet) {
        cudaFuncSetAttribute(fftconv_kernel, cudaFuncAttributeMaxDynamicSharedMemorySize, kSmemFFT);
        cudaFuncSetAttribute(gemm_kernel<0>, cudaFuncAttributeMaxDynamicSharedMemorySize, kGemmSmem);
        cudaFuncSetAttribute(gemm_kernel<1>, cudaFuncAttributeMaxDynamicSharedMemorySize, kGemmSmem);
        cudaFuncSetAttribute(gemm_kernel<2>, cudaFuncAttributeMaxDynamicSharedMemorySize, kGemmSmem);
        attrsSet = true;
    }

    cudaEventRecord(evFork, 0);
    cudaStreamWaitEvent(side, evFork, 0);
    twiddle_kernel<<<17, 256, 0, side>>>();
    kfgen_kernel<<<dim3(33, kCh), 256, 0, side>>>(A, Bp);
    cudaEventRecord(evJoin, side);

    zero_kernel<<<8, 256>>>();
    wsplit_kernel<<<dim3(kCh * kCh / 256, 3), 256>>>(W_enc, W_fc, W_dec);
    gemm_kernel<0><<<dim3(kM / 128, 2), 256, kGemmSmem>>>(x, b_enc, nullptr);
    cudaStreamWaitEvent(0, evJoin, 0);
    fftconv_kernel<<<kB * kCh, 1024, kSmemFFT>>>(h0);
    gemm_kernel<1><<<dim3(kM / 128, 2), 256, kGemmSmem>>>(nullptr, b_fc, nullptr);
    ln_kernel<<<kM / 8, 256>>>(gamma, beta);
    gemm_kernel<2><<<dim3(kM / 128, 2), 256, kGemmSmem>>>(nullptr, b_dec, out);
    hout_kernel<<<8, 256>>>(out + (size_t)kM * kCh);
}

// round 14
// speedup vs baseline: 2.1861x; 1.0991x over previous
#include <cuda_runtime.h>
#include <cuda_bf16.h>

constexpr int kB = 8, kSeq = 8192, kCh = 256;
constexpr int kM  = kB * kSeq;          // 65536
constexpr int kN2 = 8192;               // complex FFT size (real 16384)
constexpr int kNF = 8193;               // rfft bins of 16384

__device__ __align__(128) float  g_xe [kM * kCh];   // (B,L,C)
__device__ __align__(128) float  g_xeT[kM * kCh];   // (B,C,L), preserved
__device__ __align__(128) float  g_y1 [kM * kCh];   // (B,C,L)  y1T
__device__ __align__(128) float  g_y2 [kM * kCh];   // (B,L,C)
__device__ __align__(128) float2 g_Kf [(size_t)kCh * kNF];
__device__ __align__(128) __nv_bfloat16 g_Wh[3 * kCh * kCh];
__device__ __align__(128) __nv_bfloat16 g_Wl[3 * kCh * kCh];
__device__ float2 g_tw8 [4096];
__device__ float2 g_tw16[4097];
__device__ unsigned g_maxxe[kB * kCh];
__device__ unsigned g_maxy [kB * kCh];

#define SWZ(i) ((i) ^ ((((i) >> 4) & 3) << 2))

__device__ __forceinline__ float2 cmul(float2 a, float2 b) {
    return make_float2(a.x * b.x - a.y * b.y, a.x * b.y + a.y * b.x);
}
__device__ __forceinline__ float2 cadd(float2 a, float2 b) {
    return make_float2(a.x + b.x, a.y + b.y);
}
__device__ __forceinline__ float2 csub(float2 a, float2 b) {
    return make_float2(a.x - b.x, a.y - b.y);
}
__device__ __forceinline__ float gelu_exact(float v) {
    return 0.5f * v * (1.0f + erff(v * 0.7071067811865476f));
}
__device__ __forceinline__ void ldsm4(unsigned* r, const void* p) {
    unsigned addr = (unsigned)__cvta_generic_to_shared(p);
    asm volatile("ldmatrix.sync.aligned.m8n8.x4.shared.b16 {%0,%1,%2,%3}, [%4];"
                 : "=r"(r[0]), "=r"(r[1]), "=r"(r[2]), "=r"(r[3]) : "r"(addr));
}
__device__ __forceinline__ void ldsm4t(unsigned* r, const void* p) {
    unsigned addr = (unsigned)__cvta_generic_to_shared(p);
    asm volatile("ldmatrix.sync.aligned.m8n8.x4.trans.shared.b16 {%0,%1,%2,%3}, [%4];"
                 : "=r"(r[0]), "=r"(r[1]), "=r"(r[2]), "=r"(r[3]) : "r"(addr));
}
__device__ __forceinline__ void mma16816(float* d, const unsigned* a, const unsigned* b) {
    asm volatile("mma.sync.aligned.m16n8k16.row.col.f32.bf16.bf16.f32 "
                 "{%0,%1,%2,%3}, {%4,%5,%6,%7}, {%8,%9}, {%0,%1,%2,%3};"
                 : "+f"(d[0]), "+f"(d[1]), "+f"(d[2]), "+f"(d[3])
                 : "r"(a[0]), "r"(a[1]), "r"(a[2]), "r"(a[3]), "r"(b[0]), "r"(b[1]));
}
__device__ __forceinline__ void cpasync16(void* smem_dst, const void* gsrc) {
    unsigned a = (unsigned)__cvta_generic_to_shared(smem_dst);
    asm volatile("cp.async.cg.shared.global [%0], [%1], 16;" :: "r"(a), "l"(gsrc));
}
#define CP_COMMIT() asm volatile("cp.async.commit_group;")
#define CP_WAIT0()  asm volatile("cp.async.wait_group 0;")

__global__ void zero_kernel() {
    int i = blockIdx.x * 256 + threadIdx.x;
    if (i < kB * kCh) { g_maxxe[i] = 0u; g_maxy[i] = 0u; }
}

__global__ void twiddle_kernel() {
    int i = blockIdx.x * 256 + threadIdx.x;
    float s, c;
    if (i < 4096) { sincospif(-2.0f * i / 8192.0f,  &s, &c); g_tw8 [i] = make_float2(c, s); }
    if (i < 4097) { sincospif(-2.0f * i / 16384.0f, &s, &c); g_tw16[i] = make_float2(c, s); }
}

__global__ void wsplit_kernel(const float* __restrict__ We, const float* __restrict__ Wf,
                              const float* __restrict__ Wd) {
    int i = blockIdx.x * 256 + threadIdx.x;
    const float* src = (blockIdx.y == 0) ? We : (blockIdx.y == 1 ? Wf : Wd);
    float v = src[i];
    __nv_bfloat16 h = __float2bfloat16(v);
    g_Wh[blockIdx.y * kCh * kCh + i] = h;
    g_Wl[blockIdx.y * kCh * kCh + i] = __float2bfloat16(v - __bfloat162float(h));
}

// Kf[c][k] = B(w)/A(w)/8192 (IIR tail underflows fp32 beyond n=8192).
__global__ __launch_bounds__(256) void kfgen_kernel(const float* __restrict__ A,
                                                    const float* __restrict__ Bp) {
    __shared__ float sA[64], sB[64];
    int c = blockIdx.y;
    if (threadIdx.x < 64)       sA[threadIdx.x]      = A [c * 64 + threadIdx.x];
    else if (threadIdx.x < 128) sB[threadIdx.x - 64] = Bp[c * 64 + threadIdx.x - 64];
    __syncthreads();
    int k = blockIdx.x * 256 + threadIdx.x;
    if (k >= kNF) return;
    float sv, cv;
    sincospif(-(float)k / 8192.0f, &sv, &cv);
    float2 w  = make_float2(cv, sv);
    float2 w2 = cmul(w, w);
    float2 ae = make_float2(sA[63], 0.f);
    float2 ao = make_float2(sA[62], 0.f);
    float2 be = make_float2(sB[62], 0.f);
    float2 bo = make_float2(sB[63], 0.f);
#pragma unroll 4
    for (int i = 31; i >= 1; --i) {
        ae = cmul(ae, w2); ae.x += sA[2 * i - 1];
        ao = cmul(ao, w2); ao.x += sA[2 * i - 2];
        be = cmul(be, w2); be.x += sB[2 * i - 2];
        bo = cmul(bo, w2); bo.x += sB[2 * i - 1];
    }
    ae = cmul(ae, w2); ae.x += 1.0f;
    float2 av = cadd(ae, cmul(w, ao));
    float2 bv = cadd(be, cmul(w, bo));
    float scl = (1.0f / 8192.0f) / (av.x * av.x + av.y * av.y);
    g_Kf[(size_t)c * kNF + k] = make_float2((bv.x * av.x + bv.y * av.y) * scl,
                                            (bv.y * av.x - bv.x * av.y) * scl);
}

// ---------------------------------------------------------------------------
// Tensor-core GEMM (3-pass bf16 split), software-pipelined (unchanged).
constexpr int kGemmSmem = 81920 + 512;

template <int EPI>
__global__ __launch_bounds__(256, 2) void gemm_kernel(const float* __restrict__ Ain,
                                                      const float* __restrict__ bias,
                                                      float* __restrict__ Cout) {
    constexpr int BM = 128, BN = 128, BK = 32, LDS = 40, LDT = 136;
    extern __shared__ __align__(16) unsigned char smem_raw[];
    unsigned* red = reinterpret_cast<unsigned*>(smem_raw + 81920);
    const float* Ap = (EPI == 1) ? g_y1 : (EPI == 2 ? g_y2 : Ain);
    float*       Cp = (EPI == 0) ? g_xe : (EPI == 1 ? g_y2 : Cout);
    const __nv_bfloat16* Whp = g_Wh + EPI * kCh * kCh;
    const __nv_bfloat16* Wlp = g_Wl + EPI * kCh * kCh;
    const int m0 = blockIdx.x * BM, n0 = blockIdx.y * BN;
    const int tid = threadIdx.x, lane = tid & 31, warp = tid >> 5;
    const int wr = warp >> 1, wc = warp & 1;
    const int bB = m0 >> 13, l0m = m0 & (kSeq - 1);

    if (EPI != 1 && tid < BN) red[tid] = 0u;

    float acc[2][8][4];
#pragma unroll
    for (int mt = 0; mt < 2; ++mt)
#pragma unroll
        for (int nt = 0; nt < 8; ++nt)
#pragma unroll
            for (int r = 0; r < 4; ++r) acc[mt][nt][r] = 0.f;

    auto ldgA = [&](int kt, float4* ra) {
#pragma unroll
        for (int u = 0; u < 4; ++u) {
            int idx = u * 256 + tid;
            if (EPI == 1) {
                int ch = idx >> 5, mg = (idx & 31) * 4;
                ra[u] = *reinterpret_cast<const float4*>(
                    Ap + ((size_t)bB * kCh + kt + ch) * kSeq + l0m + mg);
            } else {
                int row = idx >> 3, c4 = (idx & 7) * 4;
                ra[u] = *reinterpret_cast<const float4*>(
                    Ap + (size_t)(m0 + row) * kCh + kt + c4);
            }
        }
    };
    auto stA = [&](int buf, const float4* ra) {
#pragma unroll
        for (int u = 0; u < 4; ++u) {
            int idx = u * 256 + tid;
            float4 v = ra[u];
            __nv_bfloat162 h01 = __floats2bfloat162_rn(v.x, v.y);
            __nv_bfloat162 h23 = __floats2bfloat162_rn(v.z, v.w);
            __nv_bfloat162 l01 = __floats2bfloat162_rn(v.x - __low2float(h01),
                                                       v.y - __high2float(h01));
            __nv_bfloat162 l23 = __floats2bfloat162_rn(v.z - __low2float(h23),
                                                       v.w - __high2float(h23));
            uint2 hv = make_uint2(*reinterpret_cast<unsigned*>(&h01),
                                  *reinterpret_cast<unsigned*>(&h23));
            uint2 lv = make_uint2(*reinterpret_cast<unsigned*>(&l01),
                                  *reinterpret_cast<unsigned*>(&l23));
            if (EPI == 1) {
                int ch = idx >> 5, mg = (idx & 31) * 4;
                auto Ath = reinterpret_cast<__nv_bfloat16(*)[LDT]>(smem_raw + buf * 8704);
                auto Atl = reinterpret_cast<__nv_bfloat16(*)[LDT]>(smem_raw + 20480 + buf * 8704);
                *reinterpret_cast<uint2*>(&Ath[ch][mg]) = hv;
                *reinterpret_cast<uint2*>(&Atl[ch][mg]) = lv;
            } else {
                int row = idx >> 3, c4 = (idx & 7) * 4;
                auto Ah = reinterpret_cast<__nv_bfloat16(*)[LDS]>(smem_raw + buf * 10240);
                auto Al = reinterpret_cast<__nv_bfloat16(*)[LDS]>(smem_raw + 20480 + buf * 10240);
                *reinterpret_cast<uint2*>(&Ah[row][c4]) = hv;
                *reinterpret_cast<uint2*>(&Al[row][c4]) = lv;
            }
        }
    };
    auto cpW = [&](int kt, int buf) {
        auto Bh = reinterpret_cast<__nv_bfloat16(*)[LDS]>(smem_raw + 40960 + buf * 10240);
        auto Bl = reinterpret_cast<__nv_bfloat16(*)[LDS]>(smem_raw + 61440 + buf * 10240);
#pragma unroll
        for (int u = 0; u < 2; ++u) {
            int idx = u * 256 + tid;
            int row = idx >> 2, c8 = (idx & 3) * 8;
            cpasync16(&Bh[row][c8], Whp + (size_t)(n0 + row) * kCh + kt + c8);
            cpasync16(&Bl[row][c8], Wlp + (size_t)(n0 + row) * kCh + kt + c8);
        }
    };

    float4 ra[4];
    ldgA(0, ra);
    cpW(0, 0);
    CP_COMMIT();

    for (int it = 0; it < 8; ++it) {
        const int cur = it & 1;
        stA(cur, ra);
        if (it < 7) ldgA((it + 1) * BK, ra);
        CP_WAIT0();
        __syncthreads();
        if (it < 7) { cpW((it + 1) * BK, cur ^ 1); CP_COMMIT(); }

        auto Ah  = reinterpret_cast<__nv_bfloat16(*)[LDS]>(smem_raw + cur * 10240);
        auto Al  = reinterpret_cast<__nv_bfloat16(*)[LDS]>(smem_raw + 20480 + cur * 10240);
        auto Ath = reinterpret_cast<__nv_bfloat16(*)[LDT]>(smem_raw + cur * 8704);
        auto Atl = reinterpret_cast<__nv_bfloat16(*)[LDT]>(smem_raw + 20480 + cur * 8704);
        auto Bh  = reinterpret_cast<__nv_bfloat16(*)[LDS]>(smem_raw + 40960 + cur * 10240);
        auto Bl  = reinterpret_cast<__nv_bfloat16(*)[LDS]>(smem_raw + 61440 + cur * 10240);
#pragma unroll
        for (int ks = 0; ks < 2; ++ks) {
            const int kb = ks * 16;
            unsigned ah[2][4], al[2][4];
#pragma unroll
            for (int mt = 0; mt < 2; ++mt) {
                if (EPI == 1) {
                    int krow = kb + ((lane >> 4) << 3) + (lane & 7);
                    int mcol = wr * 32 + mt * 16 + (((lane >> 3) & 1) << 3);
                    ldsm4t(ah[mt], &Ath[krow][mcol]);
                    ldsm4t(al[mt], &Atl[krow][mcol]);
                } else {
                    int arow = wr * 32 + mt * 16 + (lane & 15);
                    int koff = kb + ((lane >> 4) << 3);
                    ldsm4(ah[mt], &Ah[arow][koff]);
                    ldsm4(al[mt], &Al[arow][koff]);
                }
            }
#pragma unroll
            for (int g = 0; g < 4; ++g) {
                int nrow = wc * 64 + g * 16 + (lane & 7) + ((lane >> 4) << 3);
                int koff = kb + (((lane >> 3) & 1) << 3);
                unsigned bh[4], bl[4];
                ldsm4(bh, &Bh[nrow][koff]);
                ldsm4(bl, &Bl[nrow][koff]);
#pragma unroll
                for (int mt = 0; mt < 2; ++mt) {
                    mma16816(acc[mt][2 * g],     ah[mt], bh);
                    mma16816(acc[mt][2 * g],     ah[mt], bl);
                    mma16816(acc[mt][2 * g],     al[mt], bh);
                    mma16816(acc[mt][2 * g + 1], ah[mt], bh + 2);
                    mma16816(acc[mt][2 * g + 1], ah[mt], bl + 2);
                    mma16816(acc[mt][2 * g + 1], al[mt], bh + 2);
                }
            }
        }
    }
    __syncthreads();

    float* stage = reinterpret_cast<float*>(smem_raw);     // [128][129], EPI==0 only
#pragma unroll
    for (int mt = 0; mt < 2; ++mt) {
        int r0 = m0 + wr * 32 + mt * 16 + (lane >> 2);
#pragma unroll
        for (int nt = 0; nt < 8; ++nt) {
            int col = n0 + wc * 64 + nt * 8 + (lane & 3) * 2;
            float* c = acc[mt][nt];
            float2 bv = *reinterpret_cast<const float2*>(bias + col);
            float v0 = c[0] + bv.x, v1 = c[1] + bv.y;
            float v2 = c[2] + bv.x, v3 = c[3] + bv.y;
            if (EPI == 1) {
                float2 s0 = *reinterpret_cast<const float2*>(g_xe + (size_t)r0 * kCh + col);
                float2 s1 = *reinterpret_cast<const float2*>(g_xe + (size_t)(r0 + 8) * kCh + col);
                v0 = gelu_exact(v0) + s0.x; v1 = gelu_exact(v1) + s0.y;
                v2 = gelu_exact(v2) + s1.x; v3 = gelu_exact(v3) + s1.y;
            } else {
                float me = fmaxf(fabsf(v0), fabsf(v2));
                float mo = fmaxf(fabsf(v1), fabsf(v3));
#pragma unroll
                for (int o = 4; o < 32; o <<= 1) {
                    me = fmaxf(me, __shfl_xor_sync(0xffffffffu, me, o));
                    mo = fmaxf(mo, __shfl_xor_sync(0xffffffffu, mo, o));
                }
                if (lane < 4) {
                    atomicMax(&red[col - n0],     __float_as_uint(me));
                    atomicMax(&red[col - n0 + 1], __float_as_uint(mo));
                }
            }
            if (EPI == 0) {
                int lr = r0 - m0, lc = col - n0;
                stage[lr * 129 + lc]           = v0;
                stage[lr * 129 + lc + 1]       = v1;
                stage[(lr + 8) * 129 + lc]     = v2;
                stage[(lr + 8) * 129 + lc + 1] = v3;
            }
            *reinterpret_cast<float2*>(Cp + (size_t)r0 * kCh + col)       = make_float2(v0, v1);
            *reinterpret_cast<float2*>(Cp + (size_t)(r0 + 8) * kCh + col) = make_float2(v2, v3);
        }
    }
    if (EPI != 1) {
        __syncthreads();
        if (tid < BN) {
            unsigned* buf = (EPI == 0) ? g_maxxe : g_maxy;
            atomicMax(&buf[(m0 >> 13) * kCh + n0 + tid], red[tid]);
        }
    }
    if (EPI == 0) {
        __syncthreads();
        for (int i = tid; i < 128 * 128; i += 256) {
            int cidx = i >> 7, l = i & 127;
            g_xeT[((size_t)bB * kCh + n0 + cidx) * kSeq + l0m + l] = stage[l * 129 + cidx];
        }
    }
}

// ---------------------------------------------------------------------------
// Radix-8 Stockham FFT: 4 radix-8 stages + 1 radix-2 per direction.
template <bool INV>
__device__ __forceinline__ void dft4v(float2 a0, float2 a1, float2 a2, float2 a3,
                                      float2& y0, float2& y1, float2& y2, float2& y3) {
    float2 t0 = cadd(a0, a2), t1 = csub(a0, a2);
    float2 t2 = cadd(a1, a3), t3 = csub(a1, a3);
    y0 = cadd(t0, t2); y2 = csub(t0, t2);
    if (!INV) {
        y1 = make_float2(t1.x + t3.y, t1.y - t3.x);
        y3 = make_float2(t1.x - t3.y, t1.y + t3.x);
    } else {
        y1 = make_float2(t1.x - t3.y, t1.y + t3.x);
        y3 = make_float2(t1.x + t3.y, t1.y - t3.x);
    }
}

template <bool INV>
__device__ __forceinline__ void dft8v(const float2* a, float2* b) {
    const float C = 0.7071067811865476f;
    float2 E0, E1, E2, E3, O0, O1, O2, O3;
    dft4v<INV>(a[0], a[2], a[4], a[6], E0, E1, E2, E3);
    dft4v<INV>(a[1], a[3], a[5], a[7], O0, O1, O2, O3);
    float2 u1, u2, u3;
    if (!INV) {
        u1 = make_float2(C * (O1.x + O1.y), C * (O1.y - O1.x));
        u2 = make_float2(O2.y, -O2.x);
        u3 = make_float2(C * (O3.y - O3.x), -C * (O3.x + O3.y));
    } else {
        u1 = make_float2(C * (O1.x - O1.y), C * (O1.x + O1.y));
        u2 = make_float2(-O2.y, O2.x);
        u3 = make_float2(-C * (O3.x + O3.y), C * (O3.x - O3.y));
    }
    b[0] = cadd(E0, O0); b[4] = csub(E0, O0);
    b[1] = cadd(E1, u1); b[5] = csub(E1, u1);
    b[2] = cadd(E2, u2); b[6] = csub(E2, u2);
    b[3] = cadd(E3, u3); b[7] = csub(E3, u3);
}

template <bool INV>
__device__ __forceinline__ void fft_stages(float2*& src, float2*& dst, const float2* tw) {
    const int t = threadIdx.x;              // 1024 threads, one butterfly each
    // stage 1: s=1 (consecutive writes -> float4; SWZ keeps pairs adjacent)
    {
        float2 a[8], b[8];
#pragma unroll
        for (int j = 0; j < 8; ++j) a[j] = src[SWZ(t + j * 1024)];
        dft8v<INV>(a, b);
        float2 w1 = tw[t]; if (INV) w1.y = -w1.y;
        float2 w2 = cmul(w1, w1), w3 = cmul(w2, w1), w4 = cmul(w2, w2),
               w5 = cmul(w2, w3), w6 = cmul(w3, w3), w7 = cmul(w3, w4);
        float2 o1 = cmul(w1, b[1]), o2 = cmul(w2, b[2]), o3 = cmul(w3, b[3]),
               o4 = cmul(w4, b[4]), o5 = cmul(w5, b[5]), o6 = cmul(w6, b[6]),
               o7 = cmul(w7, b[7]);
        int base = 8 * t;
        *reinterpret_cast<float4*>(dst + SWZ(base))     = make_float4(b[0].x, b[0].y, o1.x, o1.y);
        *reinterpret_cast<float4*>(dst + SWZ(base + 2)) = make_float4(o2.x, o2.y, o3.x, o3.y);
        *reinterpret_cast<float4*>(dst + SWZ(base + 4)) = make_float4(o4.x, o4.y, o5.x, o5.y);
        *reinterpret_cast<float4*>(dst + SWZ(base + 6)) = make_float4(o6.x, o6.y, o7.x, o7.y);
        __syncthreads();
        float2* tp = src; src = dst; dst = tp;
    }
    // stages s = 8, 64, 512
#pragma unroll
    for (int ls = 3; ls <= 9; ls += 3) {
        const int s = 1 << ls;
        int q = t & (s - 1), p = t >> ls;
        float2 a[8], b[8];
#pragma unroll
        for (int j = 0; j < 8; ++j) a[j] = src[SWZ(t + j * 1024)];
        dft8v<INV>(a, b);
        float2 w1 = tw[p << ls]; if (INV) w1.y = -w1.y;
        float2 w2 = cmul(w1, w1), w3 = cmul(w2, w1), w4 = cmul(w2, w2),
               w5 = cmul(w2, w3), w6 = cmul(w3, w3), w7 = cmul(w3, w4);
        int o = q + (p << (ls + 3));
        dst[SWZ(o)]         = b[0];
        dst[SWZ(o + s)]     = cmul(w1, b[1]);
        dst[SWZ(o + 2 * s)] = cmul(w2, b[2]);
        dst[SWZ(o + 3 * s)] = cmul(w3, b[3]);
        dst[SWZ(o + 4 * s)] = cmul(w4, b[4]);
        dst[SWZ(o + 5 * s)] = cmul(w5, b[5]);
        dst[SWZ(o + 6 * s)] = cmul(w6, b[6]);
        dst[SWZ(o + 7 * s)] = cmul(w7, b[7]);
        __syncthreads();
        float2* tp = src; src = dst; dst = tp;
    }
    // final radix-2, s=4096
    for (int u = t; u < 4096; u += 1024) {
        float2 a = src[SWZ(u)], b = src[SWZ(u + 4096)];
        dst[SWZ(u)]        = cadd(a, b);
        dst[SWZ(u + 4096)] = csub(a, b);
    }
    __syncthreads();
    float2* tp = src; src = dst; dst = tp;
}

// One CTA per (b,c) row; writes y1T = gelu(h1T + h0*xeT) to g_y1.
__global__ __launch_bounds__(1024, 1) void fftconv_kernel(const float* __restrict__ h0p) {
    extern __shared__ float2 sm[];
    float2* tw8  = sm;
    float2* tw16 = sm + 4096;
    float2* b0   = sm + 8194;
    float2* b1   = b0 + kN2;
    for (int i = threadIdx.x; i < 4097; i += 1024) {
        if (i < 4096) tw8[i] = g_tw8[i];
        tw16[i] = g_tw16[i];
    }
    const int r = blockIdx.x, c = r & (kCh - 1);
    const float2* row2 = reinterpret_cast<const float2*>(g_xeT + (size_t)r * kSeq);
    for (int n = threadIdx.x; n < kN2; n += 1024)
        b0[SWZ(n)] = (n < 4096) ? row2[n] : make_float2(0.f, 0.f);
    __syncthreads();

    float2 *src = b0, *dst = b1;
    fft_stages<false>(src, dst, tw8);

    const float2* Kfc = g_Kf + (size_t)c * kNF;
    for (int k = threadIdx.x; k <= 4096; k += 1024) {
        int j = (kN2 - k) & (kN2 - 1);
        float2 Zk = src[SWZ(k)], Zj = src[SWZ(j)];
        float2 E = make_float2(0.5f * (Zk.x + Zj.x), 0.5f * (Zk.y - Zj.y));
        float2 O = make_float2(0.5f * (Zk.y + Zj.y), -0.5f * (Zk.x - Zj.x));
        float2 w = tw16[k];
        float2 wO = cmul(w, O);
        float2 Xk = make_float2(E.x + wO.x, E.y + wO.y);
        float2 Xj = make_float2(E.x - wO.x, -(E.y - wO.y));
        float2 Yk = cmul(Xk, Kfc[k]);
        float2 Yj = cmul(Xj, Kfc[kN2 - k]);
        float2 Ey = make_float2(0.5f * (Yk.x + Yj.x), 0.5f * (Yk.y - Yj.y));
        float2 Dy = make_float2(0.5f * (Yk.x - Yj.x), 0.5f * (Yk.y + Yj.y));
        float2 Oy = cmul(make_float2(w.x, -w.y), Dy);
        dst[SWZ(k)] = make_float2(Ey.x - Oy.y, Ey.y + Oy.x);
        if (k >= 1 && k < 4096) {
            float2 Em = make_float2(0.5f * (Yj.x + Yk.x), 0.5f * (Yj.y - Yk.y));
            float2 Dm = make_float2(0.5f * (Yj.x - Yk.x), 0.5f * (Yj.y + Yk.y));
            float2 Om = cmul(make_float2(-w.x, -w.y), Dm);
            dst[SWZ(kN2 - k)] = make_float2(Em.x - Om.y, Em.y + Om.x);
        }
    }
    __syncthreads();
    { float2* tp = src; src = dst; dst = tp; }

    fft_stages<true>(src, dst, tw8);

    const float h0v = h0p[0];
    float2* y1row = reinterpret_cast<float2*>(g_y1 + (size_t)r * kSeq);
    for (int n = threadIdx.x; n < 4096; n += 1024) {
        float2 v = src[SWZ(n)];
        float2 e = row2[n];
        y1row[n] = make_float2(gelu_exact(v.x + h0v * e.x),
                               gelu_exact(v.y + h0v * e.y));
    }
}

// LayerNorm over channels, in place on g_y2. One warp per row.
__global__ __launch_bounds__(256) void ln_kernel(const float* __restrict__ gamma,
                                                 const float* __restrict__ beta) {
    int warp = threadIdx.x >> 5, lane = threadIdx.x & 31;
    size_t row = (size_t)blockIdx.x * 8 + warp;
    float4* p = reinterpret_cast<float4*>(g_y2 + row * kCh);
    float4 v0 = p[lane], v1 = p[lane + 32];
    float s = v0.x + v0.y + v0.z + v0.w + v1.x + v1.y + v1.z + v1.w;
    float q = v0.x * v0.x + v0.y * v0.y + v0.z * v0.z + v0.w * v0.w
            + v1.x * v1.x + v1.y * v1.y + v1.z * v1.z + v1.w * v1.w;
#pragma unroll
    for (int o = 16; o; o >>= 1) {
        s += __shfl_xor_sync(0xffffffffu, s, o);
        q += __shfl_xor_sync(0xffffffffu, q, o);
    }
    float mu = s * (1.f / 256.f);
    float rstd = rsqrtf(q * (1.f / 256.f) - mu * mu + 1e-5f);
    const float4* g4 = reinterpret_cast<const float4*>(gamma);
    const float4* e4 = reinterpret_cast<const float4*>(beta);
    float4 g0 = g4[lane], g1 = g4[lane + 32], e0 = e4[lane], e1 = e4[lane + 32];
    v0.x = (v0.x - mu) * rstd * g0.x + e0.x; v0.y = (v0.y - mu) * rstd * g0.y + e0.y;
    v0.z = (v0.z - mu) * rstd * g0.z + e0.z; v0.w = (v0.w - mu) * rstd * g0.w + e0.w;
    v1.x = (v1.x - mu) * rstd * g1.x + e1.x; v1.y = (v1.y - mu) * rstd * g1.y + e1.y;
    v1.z = (v1.z - mu) * rstd * g1.z + e1.z; v1.w = (v1.w - mu) * rstd * g1.w + e1.w;
    p[lane] = v0; p[lane + 32] = v1;
}

__global__ void hout_kernel(float* __restrict__ h) {
    int i = blockIdx.x * 256 + threadIdx.x;
    if (i < kB * kCh)
        h[i] = __uint_as_float(g_maxy[i]) / (__uint_as_float(g_maxxe[i]) + 1e-6f);
}

extern "C" void kernel_launch(void* const* d_in, const int* in_sizes, int n_in,
                              void* d_out, int out_size) {
    const float* x     = (const float*)d_in[0];
    const float* A     = (const float*)d_in[1];
    const float* Bp    = (const float*)d_in[2];
    const float* h0    = (const float*)d_in[3];
    const float* W_enc = (const float*)d_in[4];
    const float* b_enc = (const float*)d_in[5];
    const float* W_fc  = (const float*)d_in[6];
    const float* b_fc  = (const float*)d_in[7];
    const float* gamma = (const float*)d_in[8];
    const float* beta  = (const float*)d_in[9];
    const float* W_dec = (const float*)d_in[10];
    const float* b_dec = (const float*)d_in[11];
    float* out = (float*)d_out;

    static cudaStream_t side = nullptr;
    static cudaEvent_t evFork = nullptr, evJoin = nullptr;
    static bool attrsSet = false;
    if (!side) {
        cudaStreamCreateWithFlags(&side, cudaStreamNonBlocking);
        cudaEventCreateWithFlags(&evFork, cudaEventDisableTiming);
        cudaEventCreateWithFlags(&evJoin, cudaEventDisableTiming);
    }
    const int kSmemFFT = 24578 * 8;   // 196624 B dynamic SMEM
    if (!attrsSet) {
        cudaFuncSetAttribute(fftconv_kernel, cudaFuncAttributeMaxDynamicSharedMemorySize, kSmemFFT);
        cudaFuncSetAttribute(gemm_kernel<0>, cudaFuncAttributeMaxDynamicSharedMemorySize, kGemmSmem);
        cudaFuncSetAttribute(gemm_kernel<1>, cudaFuncAttributeMaxDynamicSharedMemorySize, kGemmSmem);
        cudaFuncSetAttribute(gemm_kernel<2>, cudaFuncAttributeMaxDynamicSharedMemorySize, kGemmSmem);
        attrsSet = true;
    }

    cudaEventRecord(evFork, 0);
    cudaStreamWaitEvent(side, evFork, 0);
    twiddle_kernel<<<17, 256, 0, side>>>();
    kfgen_kernel<<<dim3(33, kCh), 256, 0, side>>>(A, Bp);
    cudaEventRecord(evJoin, side);

    zero_kernel<<<8, 256>>>();
    wsplit_kernel<<<dim3(kCh * kCh / 256, 3), 256>>>(W_enc, W_fc, W_dec);
    gemm_kernel<0><<<dim3(kM / 128, 2), 256, kGemmSmem>>>(x, b_enc, nullptr);
    cudaStreamWaitEvent(0, evJoin, 0);
    fftconv_kernel<<<kB * kCh, 1024, kSmemFFT>>>(h0);
    gemm_kernel<1><<<dim3(kM / 128, 2), 256, kGemmSmem>>>(nullptr, b_fc, nullptr);
    ln_kernel<<<kM / 8, 256>>>(gamma, beta);
    gemm_kernel<2><<<dim3(kM / 128, 2), 256, kGemmSmem>>>(nullptr, b_dec, out);
    hout_kernel<<<8, 256>>>(out + (size_t)kM * kCh);
}